// round 9
// baseline (speedup 1.0000x reference)
#include <cuda_runtime.h>
#include <cuda_bf16.h>
#include <cstdint>

constexpr int BATCH = 2, NSEQ = 2048, DM = 1024, NH = 16, DH = 64;
constexpr int MROWS = BATCH * NSEQ;

__device__ __align__(16) __nv_bfloat16 g_x_hi[MROWS*DM],     g_x_lo[MROWS*DM];
__device__ __align__(16) __nv_bfloat16 g_wqkv_hi[3*DM*DM],   g_wqkv_lo[3*DM*DM];   // [3072][1024] (transposed)
__device__ __align__(16) __nv_bfloat16 g_wp_hi[DM*DM],       g_wp_lo[DM*DM];       // [1024][1024] (transposed)
__device__ __align__(16) __nv_bfloat16 g_q_hi[MROWS*NH*DH],  g_q_lo[MROWS*NH*DH];  // [bh][n][d] (q pre-scaled)
__device__ __align__(16) __nv_bfloat16 g_k_hi[MROWS*NH*DH],  g_k_lo[MROWS*NH*DH];  // [bh][n][d]
__device__ __align__(16) __nv_bfloat16 g_v_hi[MROWS*NH*DH],  g_v_lo[MROWS*NH*DH];  // [bh][d][n] (transposed)
__device__ __align__(16) __nv_bfloat16 g_att_hi[MROWS*DM],   g_att_lo[MROWS*DM];   // [4096][1024]

// ---------------- helpers ----------------
__device__ __forceinline__ void ldsm4(uint32_t a, uint32_t& r0, uint32_t& r1, uint32_t& r2, uint32_t& r3) {
    asm volatile("ldmatrix.sync.aligned.m8n8.x4.shared.b16 {%0,%1,%2,%3}, [%4];\n"
                 : "=r"(r0), "=r"(r1), "=r"(r2), "=r"(r3) : "r"(a));
}
__device__ __forceinline__ void mma16816(float* c, const uint32_t* a, uint32_t b0, uint32_t b1) {
    asm volatile("mma.sync.aligned.m16n8k16.row.col.f32.bf16.bf16.f32 "
                 "{%0,%1,%2,%3}, {%4,%5,%6,%7}, {%8,%9}, {%0,%1,%2,%3};\n"
                 : "+f"(c[0]), "+f"(c[1]), "+f"(c[2]), "+f"(c[3])
                 : "r"(a[0]), "r"(a[1]), "r"(a[2]), "r"(a[3]), "r"(b0), "r"(b1));
}
__device__ __forceinline__ void split2(float a, float b, uint32_t& hi, uint32_t& lo) {
    __nv_bfloat16 ha = __float2bfloat16_rn(a), hb = __float2bfloat16_rn(b);
    __nv_bfloat162 h2 = __halves2bfloat162(ha, hb);
    __nv_bfloat162 l2 = __halves2bfloat162(__float2bfloat16_rn(a - __bfloat162float(ha)),
                                           __float2bfloat16_rn(b - __bfloat162float(hb)));
    hi = *(uint32_t*)&h2; lo = *(uint32_t*)&l2;
}
__device__ __forceinline__ void cp_async16(uint32_t dst, const void* src) {
    asm volatile("cp.async.cg.shared.global [%0], [%1], 16;\n" :: "r"(dst), "l"(src) : "memory");
}
__device__ __forceinline__ void cp_commit() { asm volatile("cp.async.commit_group;\n" ::: "memory"); }
template<int N> __device__ __forceinline__ void cp_wait() {
    asm volatile("cp.async.wait_group %0;\n" :: "n"(N) : "memory");
}

// ---------------- split prep kernels ----------------
__global__ void split_x_kernel(const float* __restrict__ src) {
    int i = blockIdx.x * 256 + threadIdx.x;
    float v = src[i];
    __nv_bfloat16 h = __float2bfloat16_rn(v);
    g_x_hi[i] = h; g_x_lo[i] = __float2bfloat16_rn(v - __bfloat162float(h));
}
__global__ void split_wt_kernel(const float* __restrict__ src, int N, int mode) {
    __shared__ float t[32][33];
    int n0 = blockIdx.x * 32, k0 = blockIdx.y * 32;
    int tx = threadIdx.x & 31, ty0 = threadIdx.x >> 5;
    for (int ty = ty0; ty < 32; ty += 8) t[ty][tx] = src[(size_t)(k0+ty)*N + n0 + tx];
    __syncthreads();
    __nv_bfloat16* dh = mode ? g_wp_hi : g_wqkv_hi;
    __nv_bfloat16* dl = mode ? g_wp_lo : g_wqkv_lo;
    for (int ty = ty0; ty < 32; ty += 8) {
        float v = t[tx][ty];
        __nv_bfloat16 h = __float2bfloat16_rn(v);
        size_t o = (size_t)(n0+ty)*1024 + k0 + tx;
        dh[o] = h; dl[o] = __float2bfloat16_rn(v - __bfloat162float(h));
    }
}

// =====================================================================
// Legacy-HMMA split GEMM v4: BK=32 stages, 3-stage ring, TERM-MAJOR
// MMA ordering (RAW distance 4). 8 warps (2m x 4n), 2 CTA/SM.
// mode 0: qkv (scatter split q/k/v).  mode 1: proj (fp32 out).
// =====================================================================
constexpr uint32_t G_STAGE = 4u * 128u * 64u;    // 32768 bytes
constexpr int GEMM_SMEM = 3 * (int)G_STAGE;      // 98304

__global__ __launch_bounds__(256, 2) void mma_gemm(float* __restrict__ Cout, int mode)
{
    extern __shared__ __align__(16) char dynsm[];
    const uint32_t sbase = (uint32_t)__cvta_generic_to_shared(dynsm);

    const __nv_bfloat16* Ahi = mode ? g_att_hi : g_x_hi;
    const __nv_bfloat16* Alo = mode ? g_att_lo : g_x_lo;
    const __nv_bfloat16* Bhi = mode ? g_wp_hi  : g_wqkv_hi;
    const __nv_bfloat16* Blo = mode ? g_wp_lo  : g_wqkv_lo;

    const int m0 = blockIdx.y * 128, n0 = blockIdx.x * 128;
    const int tid = threadIdx.x, w = tid >> 5, lane = tid & 31;
    const int gid = lane >> 2, tig = lane & 3;
    const int wm = (w & 1) * 64, wn = (w >> 1) * 32;

    const __nv_bfloat16* planes[4] = { Ahi + (size_t)m0 * 1024, Alo + (size_t)m0 * 1024,
                                       Bhi + (size_t)n0 * 1024, Blo + (size_t)n0 * 1024 };

    // per stage: 4 planes x 128 rows x 4 cells(16B) = 2048 chunks, 8/thread
    auto issue_stage = [&](int s) {
        const uint32_t sbuf = sbase + (uint32_t)(s % 3) * G_STAGE;
        #pragma unroll
        for (int i = 0; i < 8; i++) {
            const int u = tid + 256 * i;
            const int plane = u >> 9, rem = u & 511;
            const int row = rem >> 2, cell = rem & 3;
            const uint32_t csw = (uint32_t)(cell ^ ((row >> 1) & 3));
            cp_async16(sbuf + (uint32_t)plane * 8192u + (uint32_t)row * 64u + csw * 16u,
                       planes[plane] + (size_t)row * 1024 + s * 32 + cell * 8);
        }
        cp_commit();
    };

    const int a_r = lane & 15, a_k8 = lane >> 4;
    const int b_r = (lane & 7) + ((lane >> 4) & 1) * 8, b_k8 = (lane >> 3) & 1;

    issue_stage(0);
    issue_stage(1);

    float acc[4][4][4] = {};

    for (int s = 0; s < 32; s++) {
        cp_wait<1>();
        __syncthreads();
        if (s + 2 < 32) issue_stage(s + 2);
        else cp_commit();

        const uint32_t bo = sbase + (uint32_t)(s % 3) * G_STAGE;

        #pragma unroll
        for (int hk = 0; hk < 2; hk++) {
            // B fragments (2 n-groups x 2 planes)
            uint32_t bf[2][2][4];
            #pragma unroll
            for (int g = 0; g < 2; g++) {
                const int row = wn + g * 16 + b_r;
                const uint32_t csw = (uint32_t)((hk * 2 + b_k8) ^ ((row >> 1) & 3));
                const uint32_t ad = bo + (uint32_t)row * 64u + csw * 16u;
                ldsm4(ad + 2u * 8192u, bf[0][g][0], bf[0][g][1], bf[0][g][2], bf[0][g][3]);
                ldsm4(ad + 3u * 8192u, bf[1][g][0], bf[1][g][1], bf[1][g][2], bf[1][g][3]);
            }
            // A fragments: double-buffered across i
            uint32_t ah[2][4], al[2][4];
            auto lda = [&](int i, int b) {
                const int row = wm + i * 16 + a_r;
                const uint32_t csw = (uint32_t)((hk * 2 + a_k8) ^ ((row >> 1) & 3));
                const uint32_t ad = bo + (uint32_t)row * 64u + csw * 16u;
                ldsm4(ad,         ah[b][0], ah[b][1], ah[b][2], ah[b][3]);
                ldsm4(ad + 8192u, al[b][0], al[b][1], al[b][2], al[b][3]);
            };
            lda(0, 0);
            #pragma unroll
            for (int i = 0; i < 4; i++) {
                if (i < 3) lda(i + 1, (i + 1) & 1);
                const int cb = i & 1;
                // TERM-MAJOR: all 4 accumulators get term0, then term1, then term2
                #pragma unroll
                for (int jn = 0; jn < 4; jn++) {
                    const int g = jn >> 1, h2 = (jn & 1) * 2;
                    mma16816(acc[i][jn], ah[cb], bf[0][g][h2], bf[0][g][h2+1]);
                }
                #pragma unroll
                for (int jn = 0; jn < 4; jn++) {
                    const int g = jn >> 1, h2 = (jn & 1) * 2;
                    mma16816(acc[i][jn], ah[cb], bf[1][g][h2], bf[1][g][h2+1]);
                }
                #pragma unroll
                for (int jn = 0; jn < 4; jn++) {
                    const int g = jn >> 1, h2 = (jn & 1) * 2;
                    mma16816(acc[i][jn], al[cb], bf[0][g][h2], bf[0][g][h2+1]);
                }
            }
        }
    }

    // ---------------- epilogue ----------------
    #pragma unroll
    for (int i = 0; i < 4; i++) {
        const int row0 = m0 + wm + i*16 + gid;
        #pragma unroll
        for (int jn = 0; jn < 4; jn++) {
            const int col = n0 + wn + jn*8 + tig*2;
            if (mode == 1) {
                *(float2*)&Cout[(size_t)row0*1024 + col]     = make_float2(acc[i][jn][0], acc[i][jn][1]);
                *(float2*)&Cout[(size_t)(row0+8)*1024 + col] = make_float2(acc[i][jn][2], acc[i][jn][3]);
            } else {
                #pragma unroll
                for (int r = 0; r < 4; r++) {
                    const int rr = row0 + ((r >= 2) ? 8 : 0), cc = col + (r & 1);
                    float v = acc[i][jn][r];
                    const int which = cc % 3, hd = cc / 3, h = hd >> 6, d = hd & 63;
                    const int bb = rr >> 11, nn = rr & 2047;
                    __nv_bfloat16 h16; size_t o;
                    if (which == 0) {
                        v *= 0.125f;
                        o = ((size_t)(bb*16 + h)*2048 + nn)*64 + d;
                        h16 = __float2bfloat16_rn(v);
                        g_q_hi[o] = h16; g_q_lo[o] = __float2bfloat16_rn(v - __bfloat162float(h16));
                    } else if (which == 1) {
                        o = ((size_t)(bb*16 + h)*2048 + nn)*64 + d;
                        h16 = __float2bfloat16_rn(v);
                        g_k_hi[o] = h16; g_k_lo[o] = __float2bfloat16_rn(v - __bfloat162float(h16));
                    } else {
                        o = ((size_t)(bb*16 + h)*64 + d)*2048 + nn;
                        h16 = __float2bfloat16_rn(v);
                        g_v_hi[o] = h16; g_v_lo[o] = __float2bfloat16_rn(v - __bfloat162float(h16));
                    }
                }
            }
        }
    }
}

// =====================================================================
// Causal flash attention v3: cp.async 2-stage K/V prefetch, one barrier
// per k-tile, TERM-MAJOR MMA ordering in S and PV phases.
// =====================================================================
constexpr int ATTN_SMEM = (16384 + 2 * 16384) * 2;   // 98304 bytes

__global__ __launch_bounds__(256, 2) void attn_mma()
{
    extern __shared__ __align__(16) __nv_bfloat16 dsm[];
    constexpr int QHI = 0, QLO = 8192;

    const int qt = (int)gridDim.x - 1 - (int)blockIdx.x;
    const int bh = blockIdx.y, bb = bh >> 4, hh = bh & 15;
    const size_t base = (size_t)bh * (2048*64);
    const int tid = threadIdx.x, w = tid >> 5, lane = tid & 31;
    const int gid = lane >> 2, tig = lane & 3;
    const uint32_t sbase = (uint32_t)__cvta_generic_to_shared(dsm);
    const int a_r = lane & 15, a_k8 = lane >> 4;
    const int b_r = (lane & 7) + ((lane >> 4) & 1) * 8, b_k8 = (lane >> 3) & 1;

    // K/V stage loader: 4 planes x 64 rows x 8 cells(16B) = 2048 chunks, 8/thread
    auto issue_kv = [&](int kt) {
        const uint32_t sbuf = sbase + (uint32_t)(16384 + (kt & 1) * 16384) * 2;
        const __nv_bfloat16* bases[4] = { g_k_hi + base, g_k_lo + base, g_v_hi + base, g_v_lo + base };
        #pragma unroll
        for (int i = 0; i < 8; i++) {
            const int u = tid + 256 * i;
            const int plane = u >> 9, rem = u & 511;
            const int row = rem >> 3, c16 = rem & 7;
            const uint32_t so = (uint32_t)(row * 128 + ((c16 ^ (row & 7)) * 16));
            const size_t goff = (plane < 2)
                ? ((size_t)(kt * 64 + row) * 64 + c16 * 8)
                : ((size_t)row * 2048 + (size_t)kt * 64 + c16 * 8);
            cp_async16(sbuf + (uint32_t)plane * 8192u + so, bases[plane] + goff);
        }
        cp_commit();
    };

    // load Q tile (128 x 64), both planes (plain loads; published by first barrier)
    #pragma unroll
    for (int it = 0; it < 4; it++) {
        const int u = tid + 256*it, r = u >> 3, c16 = u & 7;
        const int so = r*64 + ((c16 ^ (r & 7))*8);
        const size_t go = base + (size_t)(qt*128 + r)*64 + c16*8;
        *(uint4*)&dsm[QHI + so] = *(const uint4*)(g_q_hi + go);
        *(uint4*)&dsm[QLO + so] = *(const uint4*)(g_q_lo + go);
    }

    float s[8][4], o[8][4] = {};
    float mr0 = -1e30f, mr1 = -1e30f, lr0 = 0.f, lr1 = 0.f;
    const int row0g = qt*128 + w*16 + gid, row1g = row0g + 8;
    const int ntiles = 2*qt + 2;

    issue_kv(0);

    for (int kt = 0; kt < ntiles; kt++) {
        cp_wait<0>();
        __syncthreads();              // kt data visible to all; all warps done with kt-1
        if (kt + 1 < ntiles) issue_kv(kt + 1);

        const int khi = 16384 + (kt & 1) * 16384;
        const int klo = khi + 4096, vhi = khi + 8192, vlo = khi + 12288;

        #pragma unroll
        for (int j = 0; j < 8; j++)
            #pragma unroll
            for (int r = 0; r < 4; r++) s[j][r] = 0.f;
        #pragma unroll
        for (int kk = 0; kk < 4; kk++) {
            uint32_t aqh[4], aql[4];
            {
                const int r = w*16 + a_r, c16 = kk*2 + a_k8;
                const int so = r*64 + ((c16 ^ (r & 7))*8);
                ldsm4(sbase + (uint32_t)(QHI + so)*2, aqh[0], aqh[1], aqh[2], aqh[3]);
                ldsm4(sbase + (uint32_t)(QLO + so)*2, aql[0], aql[1], aql[2], aql[3]);
            }
            uint32_t bk[2][4][4];
            #pragma unroll
            for (int g = 0; g < 4; g++) {
                const int r = g*16 + b_r, c16 = kk*2 + b_k8;
                const int so = r*64 + ((c16 ^ (r & 7))*8);
                ldsm4(sbase + (uint32_t)(khi + so)*2, bk[0][g][0], bk[0][g][1], bk[0][g][2], bk[0][g][3]);
                ldsm4(sbase + (uint32_t)(klo + so)*2, bk[1][g][0], bk[1][g][1], bk[1][g][2], bk[1][g][3]);
            }
            // TERM-MAJOR across 8 independent accumulators
            #pragma unroll
            for (int j8 = 0; j8 < 8; j8++) {
                const int g = j8 >> 1, h = (j8 & 1)*2;
                mma16816(s[j8], aqh, bk[0][g][h], bk[0][g][h+1]);
            }
            #pragma unroll
            for (int j8 = 0; j8 < 8; j8++) {
                const int g = j8 >> 1, h = (j8 & 1)*2;
                mma16816(s[j8], aqh, bk[1][g][h], bk[1][g][h+1]);
            }
            #pragma unroll
            for (int j8 = 0; j8 < 8; j8++) {
                const int g = j8 >> 1, h = (j8 & 1)*2;
                mma16816(s[j8], aql, bk[0][g][h], bk[0][g][h+1]);
            }
        }

        if (kt >= 2*qt) {
            #pragma unroll
            for (int j8 = 0; j8 < 8; j8++) {
                const int c = kt*64 + j8*8 + tig*2;
                if (c > row0g)   s[j8][0] = -1e30f;
                if (c+1 > row0g) s[j8][1] = -1e30f;
                if (c > row1g)   s[j8][2] = -1e30f;
                if (c+1 > row1g) s[j8][3] = -1e30f;
            }
        }

        float mx0 = -1e30f, mx1 = -1e30f;
        #pragma unroll
        for (int j8 = 0; j8 < 8; j8++) {
            mx0 = fmaxf(mx0, fmaxf(s[j8][0], s[j8][1]));
            mx1 = fmaxf(mx1, fmaxf(s[j8][2], s[j8][3]));
        }
        mx0 = fmaxf(mx0, __shfl_xor_sync(~0u, mx0, 1)); mx0 = fmaxf(mx0, __shfl_xor_sync(~0u, mx0, 2));
        mx1 = fmaxf(mx1, __shfl_xor_sync(~0u, mx1, 1)); mx1 = fmaxf(mx1, __shfl_xor_sync(~0u, mx1, 2));
        const float mn0 = fmaxf(mr0, mx0), mn1 = fmaxf(mr1, mx1);
        const float f0 = __expf(mr0 - mn0), f1 = __expf(mr1 - mn1);
        mr0 = mn0; mr1 = mn1;
        float s0 = 0.f, s1 = 0.f;
        #pragma unroll
        for (int j8 = 0; j8 < 8; j8++) {
            s[j8][0] = __expf(s[j8][0] - mn0); s[j8][1] = __expf(s[j8][1] - mn0);
            s[j8][2] = __expf(s[j8][2] - mn1); s[j8][3] = __expf(s[j8][3] - mn1);
            s0 += s[j8][0] + s[j8][1]; s1 += s[j8][2] + s[j8][3];
        }
        s0 += __shfl_xor_sync(~0u, s0, 1); s0 += __shfl_xor_sync(~0u, s0, 2);
        s1 += __shfl_xor_sync(~0u, s1, 1); s1 += __shfl_xor_sync(~0u, s1, 2);
        lr0 = lr0*f0 + s0; lr1 = lr1*f1 + s1;
        #pragma unroll
        for (int j8 = 0; j8 < 8; j8++) {
            o[j8][0] *= f0; o[j8][1] *= f0; o[j8][2] *= f1; o[j8][3] *= f1;
        }

        #pragma unroll
        for (int kk = 0; kk < 4; kk++) {
            uint32_t aph[4], apl[4];
            split2(s[2*kk][0],   s[2*kk][1],   aph[0], apl[0]);
            split2(s[2*kk][2],   s[2*kk][3],   aph[1], apl[1]);
            split2(s[2*kk+1][0], s[2*kk+1][1], aph[2], apl[2]);
            split2(s[2*kk+1][2], s[2*kk+1][3], aph[3], apl[3]);
            uint32_t bv[2][4][4];
            #pragma unroll
            for (int g = 0; g < 4; g++) {
                const int r = g*16 + b_r, c16 = kk*2 + b_k8;
                const int so = r*64 + ((c16 ^ (r & 7))*8);
                ldsm4(sbase + (uint32_t)(vhi + so)*2, bv[0][g][0], bv[0][g][1], bv[0][g][2], bv[0][g][3]);
                ldsm4(sbase + (uint32_t)(vlo + so)*2, bv[1][g][0], bv[1][g][1], bv[1][g][2], bv[1][g][3]);
            }
            // TERM-MAJOR across 8 independent accumulators
            #pragma unroll
            for (int j8 = 0; j8 < 8; j8++) {
                const int g = j8 >> 1, h = (j8 & 1)*2;
                mma16816(o[j8], aph, bv[0][g][h], bv[0][g][h+1]);
            }
            #pragma unroll
            for (int j8 = 0; j8 < 8; j8++) {
                const int g = j8 >> 1, h = (j8 & 1)*2;
                mma16816(o[j8], aph, bv[1][g][h], bv[1][g][h+1]);
            }
            #pragma unroll
            for (int j8 = 0; j8 < 8; j8++) {
                const int g = j8 >> 1, h = (j8 & 1)*2;
                mma16816(o[j8], apl, bv[0][g][h], bv[0][g][h+1]);
            }
        }
    }

    const float i0 = 1.f / lr0, i1 = 1.f / lr1;
    #pragma unroll
    for (int j8 = 0; j8 < 8; j8++) {
        const int col = hh*64 + j8*8 + tig*2;
        uint32_t hi, lo;
        size_t ob = ((size_t)bb*2048 + row0g) * DM + col;
        split2(o[j8][0]*i0, o[j8][1]*i0, hi, lo);
        *(uint32_t*)&g_att_hi[ob] = hi; *(uint32_t*)&g_att_lo[ob] = lo;
        ob = ((size_t)bb*2048 + row1g) * DM + col;
        split2(o[j8][2]*i1, o[j8][3]*i1, hi, lo);
        *(uint32_t*)&g_att_hi[ob] = hi; *(uint32_t*)&g_att_lo[ob] = lo;
    }
}

extern "C" void kernel_launch(void* const* d_in, const int* in_sizes, int n_in,
                              void* d_out, int out_size)
{
    (void)in_sizes; (void)n_in; (void)out_size;
    const float* x      = (const float*)d_in[0];
    const float* w_qkv  = (const float*)d_in[1];
    const float* w_proj = (const float*)d_in[2];
    float* out = (float*)d_out;

    static bool attr_done = false;
    if (!attr_done) {
        cudaFuncSetAttribute(attn_mma, cudaFuncAttributeMaxDynamicSharedMemorySize, ATTN_SMEM);
        cudaFuncSetAttribute(mma_gemm, cudaFuncAttributeMaxDynamicSharedMemorySize, GEMM_SMEM);
        attr_done = true;
    }

    split_x_kernel<<<MROWS*DM/256, 256>>>(x);
    split_wt_kernel<<<dim3(96, 32), 256>>>(w_qkv, 3*DM, 0);
    split_wt_kernel<<<dim3(32, 32), 256>>>(w_proj, DM, 1);
    mma_gemm<<<dim3(24, 32), 256, GEMM_SMEM>>>(nullptr, 0);
    attn_mma<<<dim3(16, 32), 256, ATTN_SMEM>>>();
    mma_gemm<<<dim3(8, 32), 256, GEMM_SMEM>>>(out, 1);
}

// round 10
// speedup vs baseline: 1.3788x; 1.3788x over previous
#include <cuda_runtime.h>
#include <cuda_fp16.h>
#include <cstdint>

constexpr int BATCH = 2, NSEQ = 2048, DM = 1024, NH = 16, DH = 64;
constexpr int MROWS = BATCH * NSEQ;

// A-operands: fp16 hi/lo split (exact to ~2^-22). B-operands: single fp16.
__device__ __align__(16) __half g_x_hi[MROWS*DM],    g_x_lo[MROWS*DM];
__device__ __align__(16) __half g_wqkv[3*DM*DM];                        // [3072][1024] (transposed)
__device__ __align__(16) __half g_wp[DM*DM];                            // [1024][1024] (transposed)
__device__ __align__(16) __half g_q_hi[MROWS*NH*DH], g_q_lo[MROWS*NH*DH]; // [bh][n][d] (pre-scaled)
__device__ __align__(16) __half g_k[MROWS*NH*DH];                       // [bh][n][d]
__device__ __align__(16) __half g_v[MROWS*NH*DH];                       // [bh][d][n] (transposed)
__device__ __align__(16) __half g_att_hi[MROWS*DM],  g_att_lo[MROWS*DM]; // [4096][1024]

// ---------------- helpers ----------------
__device__ __forceinline__ void ldsm4(uint32_t a, uint32_t& r0, uint32_t& r1, uint32_t& r2, uint32_t& r3) {
    asm volatile("ldmatrix.sync.aligned.m8n8.x4.shared.b16 {%0,%1,%2,%3}, [%4];\n"
                 : "=r"(r0), "=r"(r1), "=r"(r2), "=r"(r3) : "r"(a));
}
__device__ __forceinline__ void mma16816(float* c, const uint32_t* a, uint32_t b0, uint32_t b1) {
    asm volatile("mma.sync.aligned.m16n8k16.row.col.f32.f16.f16.f32 "
                 "{%0,%1,%2,%3}, {%4,%5,%6,%7}, {%8,%9}, {%0,%1,%2,%3};\n"
                 : "+f"(c[0]), "+f"(c[1]), "+f"(c[2]), "+f"(c[3])
                 : "r"(a[0]), "r"(a[1]), "r"(a[2]), "r"(a[3]), "r"(b0), "r"(b1));
}
__device__ __forceinline__ void split2h(float a, float b, uint32_t& hi, uint32_t& lo) {
    __half ha = __float2half_rn(a), hb = __float2half_rn(b);
    __half2 h2 = __halves2half2(ha, hb);
    __half2 l2 = __halves2half2(__float2half_rn(a - __half2float(ha)),
                                __float2half_rn(b - __half2float(hb)));
    hi = *(uint32_t*)&h2; lo = *(uint32_t*)&l2;
}
__device__ __forceinline__ void cp_async16(uint32_t dst, const void* src) {
    asm volatile("cp.async.cg.shared.global [%0], [%1], 16;\n" :: "r"(dst), "l"(src) : "memory");
}
__device__ __forceinline__ void cp_commit() { asm volatile("cp.async.commit_group;\n" ::: "memory"); }
template<int N> __device__ __forceinline__ void cp_wait() {
    asm volatile("cp.async.wait_group %0;\n" :: "n"(N) : "memory");
}

// ---------------- split prep kernels ----------------
__global__ void split_x_kernel(const float* __restrict__ src) {
    int i = blockIdx.x * 256 + threadIdx.x;
    float v = src[i];
    __half h = __float2half_rn(v);
    g_x_hi[i] = h; g_x_lo[i] = __float2half_rn(v - __half2float(h));
}
// transpose [1024][N] -> [N][1024], round to fp16. mode 0 = w_qkv, 1 = w_proj
__global__ void split_wt_kernel(const float* __restrict__ src, int N, int mode) {
    __shared__ float t[32][33];
    int n0 = blockIdx.x * 32, k0 = blockIdx.y * 32;
    int tx = threadIdx.x & 31, ty0 = threadIdx.x >> 5;
    for (int ty = ty0; ty < 32; ty += 8) t[ty][tx] = src[(size_t)(k0+ty)*N + n0 + tx];
    __syncthreads();
    __half* dh = mode ? g_wp : g_wqkv;
    for (int ty = ty0; ty < 32; ty += 8)
        dh[(size_t)(n0+ty)*1024 + k0 + tx] = __float2half_rn(t[tx][ty]);
}

// =====================================================================
// fp16 2-term GEMM: C = (Ahi+Alo) @ B^T, BK=32 stages, 3-stage ring.
// smem/stage: 3 planes (Ahi, Alo, B) x 128 rows x 64B = 24KB.
// 8 warps (2m x 4n), 2 CTA/SM.
// mode 0: qkv (scatter q split / k / v).  mode 1: proj (fp32 out).
// =====================================================================
constexpr uint32_t G_STAGE = 3u * 128u * 64u;    // 24576 bytes
constexpr int GEMM_SMEM = 3 * (int)G_STAGE;      // 73728

__global__ __launch_bounds__(256, 2) void mma_gemm(float* __restrict__ Cout, int mode)
{
    extern __shared__ __align__(16) char dynsm[];
    const uint32_t sbase = (uint32_t)__cvta_generic_to_shared(dynsm);

    const __half* Ahi = mode ? g_att_hi : g_x_hi;
    const __half* Alo = mode ? g_att_lo : g_x_lo;
    const __half* Bw  = mode ? g_wp     : g_wqkv;

    const int m0 = blockIdx.y * 128, n0 = blockIdx.x * 128;
    const int tid = threadIdx.x, w = tid >> 5, lane = tid & 31;
    const int gid = lane >> 2, tig = lane & 3;
    const int wm = (w & 1) * 64, wn = (w >> 1) * 32;

    const __half* planes[3] = { Ahi + (size_t)m0 * 1024, Alo + (size_t)m0 * 1024,
                                Bw  + (size_t)n0 * 1024 };

    // per stage: 3 planes x 128 rows x 4 cells(16B) = 1536 chunks, 6/thread
    auto issue_stage = [&](int s) {
        const uint32_t sbuf = sbase + (uint32_t)(s % 3) * G_STAGE;
        #pragma unroll
        for (int i = 0; i < 6; i++) {
            const int u = tid + 256 * i;
            const int plane = u >> 9, rem = u & 511;
            const int row = rem >> 2, cell = rem & 3;
            const uint32_t csw = (uint32_t)(cell ^ ((row >> 1) & 3));
            cp_async16(sbuf + (uint32_t)plane * 8192u + (uint32_t)row * 64u + csw * 16u,
                       planes[plane] + (size_t)row * 1024 + s * 32 + cell * 8);
        }
        cp_commit();
    };

    const int a_r = lane & 15, a_k8 = lane >> 4;
    const int b_r = (lane & 7) + ((lane >> 4) & 1) * 8, b_k8 = (lane >> 3) & 1;

    issue_stage(0);
    issue_stage(1);

    float acc[4][4][4] = {};

    for (int s = 0; s < 32; s++) {
        cp_wait<1>();
        __syncthreads();
        if (s + 2 < 32) issue_stage(s + 2);
        else cp_commit();

        const uint32_t bo = sbase + (uint32_t)(s % 3) * G_STAGE;

        #pragma unroll
        for (int hk = 0; hk < 2; hk++) {
            // B fragments (2 n-groups, single plane)
            uint32_t bf[2][4];
            #pragma unroll
            for (int g = 0; g < 2; g++) {
                const int row = wn + g * 16 + b_r;
                const uint32_t csw = (uint32_t)((hk * 2 + b_k8) ^ ((row >> 1) & 3));
                ldsm4(bo + 2u * 8192u + (uint32_t)row * 64u + csw * 16u,
                      bf[g][0], bf[g][1], bf[g][2], bf[g][3]);
            }
            // A fragments: double-buffered across i
            uint32_t ah[2][4], al[2][4];
            auto lda = [&](int i, int b) {
                const int row = wm + i * 16 + a_r;
                const uint32_t csw = (uint32_t)((hk * 2 + a_k8) ^ ((row >> 1) & 3));
                const uint32_t ad = bo + (uint32_t)row * 64u + csw * 16u;
                ldsm4(ad,         ah[b][0], ah[b][1], ah[b][2], ah[b][3]);
                ldsm4(ad + 8192u, al[b][0], al[b][1], al[b][2], al[b][3]);
            };
            lda(0, 0);
            #pragma unroll
            for (int i = 0; i < 4; i++) {
                if (i < 3) lda(i + 1, (i + 1) & 1);
                const int cb = i & 1;
                #pragma unroll
                for (int jn = 0; jn < 4; jn++) {
                    const int g = jn >> 1, h2 = (jn & 1) * 2;
                    mma16816(acc[i][jn], ah[cb], bf[g][h2], bf[g][h2+1]);
                }
                #pragma unroll
                for (int jn = 0; jn < 4; jn++) {
                    const int g = jn >> 1, h2 = (jn & 1) * 2;
                    mma16816(acc[i][jn], al[cb], bf[g][h2], bf[g][h2+1]);
                }
            }
        }
    }

    // ---------------- epilogue ----------------
    #pragma unroll
    for (int i = 0; i < 4; i++) {
        const int row0 = m0 + wm + i*16 + gid;
        #pragma unroll
        for (int jn = 0; jn < 4; jn++) {
            const int col = n0 + wn + jn*8 + tig*2;
            if (mode == 1) {
                *(float2*)&Cout[(size_t)row0*1024 + col]     = make_float2(acc[i][jn][0], acc[i][jn][1]);
                *(float2*)&Cout[(size_t)(row0+8)*1024 + col] = make_float2(acc[i][jn][2], acc[i][jn][3]);
            } else {
                #pragma unroll
                for (int r = 0; r < 4; r++) {
                    const int rr = row0 + ((r >= 2) ? 8 : 0), cc = col + (r & 1);
                    float v = acc[i][jn][r];
                    const int which = cc % 3, hd = cc / 3, h = hd >> 6, d = hd & 63;
                    const int bb = rr >> 11, nn = rr & 2047;
                    if (which == 0) {
                        v *= 0.125f;
                        const size_t o = ((size_t)(bb*16 + h)*2048 + nn)*64 + d;
                        __half h16 = __float2half_rn(v);
                        g_q_hi[o] = h16; g_q_lo[o] = __float2half_rn(v - __half2float(h16));
                    } else if (which == 1) {
                        g_k[((size_t)(bb*16 + h)*2048 + nn)*64 + d] = __float2half_rn(v);
                    } else {
                        g_v[((size_t)(bb*16 + h)*64 + d)*2048 + nn] = __float2half_rn(v);
                    }
                }
            }
        }
    }
}

// =====================================================================
// fp16 causal flash attention: Q split (A), K/V single fp16 (B).
// cp.async 2-stage K/V prefetch, one barrier per k-tile.
// smem: Qhi(16KB) Qlo(16KB) + 2 stages x (K 8KB + V 8KB) = 64KB.
// =====================================================================
constexpr int ATTN_SMEM = 65536;

__global__ __launch_bounds__(256, 2) void attn_mma()
{
    extern __shared__ __align__(16) __half dsm[];
    constexpr int QHI = 0, QLO = 8192;          // element (half) offsets

    const int qt = (int)gridDim.x - 1 - (int)blockIdx.x;
    const int bh = blockIdx.y, bb = bh >> 4, hh = bh & 15;
    const size_t base = (size_t)bh * (2048*64);
    const int tid = threadIdx.x, w = tid >> 5, lane = tid & 31;
    const int gid = lane >> 2, tig = lane & 3;
    const uint32_t sbase = (uint32_t)__cvta_generic_to_shared(dsm);
    const int a_r = lane & 15, a_k8 = lane >> 4;
    const int b_r = (lane & 7) + ((lane >> 4) & 1) * 8, b_k8 = (lane >> 3) & 1;

    // K/V stage loader: 2 planes x 64 rows x 8 cells(16B) = 1024 chunks, 4/thread
    auto issue_kv = [&](int kt) {
        const uint32_t sbuf = sbase + (uint32_t)(16384 + (kt & 1) * 8192) * 2;
        const __half* bases[2] = { g_k + base, g_v + base };
        #pragma unroll
        for (int i = 0; i < 4; i++) {
            const int u = tid + 256 * i;
            const int plane = u >> 9, rem = u & 511;
            const int row = rem >> 3, c16 = rem & 7;
            const uint32_t so = (uint32_t)(row * 128 + ((c16 ^ (row & 7)) * 16));
            const size_t goff = (plane == 0)
                ? ((size_t)(kt * 64 + row) * 64 + c16 * 8)
                : ((size_t)row * 2048 + (size_t)kt * 64 + c16 * 8);
            cp_async16(sbuf + (uint32_t)plane * 8192u + so, bases[plane] + goff);
        }
        cp_commit();
    };

    // load Q tile (128 x 64), both planes
    #pragma unroll
    for (int it = 0; it < 4; it++) {
        const int u = tid + 256*it, r = u >> 3, c16 = u & 7;
        const int so = r*64 + ((c16 ^ (r & 7))*8);
        const size_t go = base + (size_t)(qt*128 + r)*64 + c16*8;
        *(uint4*)&dsm[QHI + so] = *(const uint4*)(g_q_hi + go);
        *(uint4*)&dsm[QLO + so] = *(const uint4*)(g_q_lo + go);
    }

    float s[8][4], o[8][4] = {};
    float mr0 = -1e30f, mr1 = -1e30f, lr0 = 0.f, lr1 = 0.f;
    const int row0g = qt*128 + w*16 + gid, row1g = row0g + 8;
    const int ntiles = 2*qt + 2;

    issue_kv(0);

    for (int kt = 0; kt < ntiles; kt++) {
        cp_wait<0>();
        __syncthreads();
        if (kt + 1 < ntiles) issue_kv(kt + 1);

        const int koff = 16384 + (kt & 1) * 8192;     // K plane (elements)
        const int voff = koff + 4096;                 // V plane

        #pragma unroll
        for (int j = 0; j < 8; j++)
            #pragma unroll
            for (int r = 0; r < 4; r++) s[j][r] = 0.f;
        #pragma unroll
        for (int kk = 0; kk < 4; kk++) {
            uint32_t aqh[4], aql[4];
            {
                const int r = w*16 + a_r, c16 = kk*2 + a_k8;
                const int so = r*64 + ((c16 ^ (r & 7))*8);
                ldsm4(sbase + (uint32_t)(QHI + so)*2, aqh[0], aqh[1], aqh[2], aqh[3]);
                ldsm4(sbase + (uint32_t)(QLO + so)*2, aql[0], aql[1], aql[2], aql[3]);
            }
            uint32_t bk[4][4];
            #pragma unroll
            for (int g = 0; g < 4; g++) {
                const int r = g*16 + b_r, c16 = kk*2 + b_k8;
                const int so = r*64 + ((c16 ^ (r & 7))*8);
                ldsm4(sbase + (uint32_t)(koff + so)*2, bk[g][0], bk[g][1], bk[g][2], bk[g][3]);
            }
            #pragma unroll
            for (int j8 = 0; j8 < 8; j8++) {
                const int g = j8 >> 1, h = (j8 & 1)*2;
                mma16816(s[j8], aqh, bk[g][h], bk[g][h+1]);
            }
            #pragma unroll
            for (int j8 = 0; j8 < 8; j8++) {
                const int g = j8 >> 1, h = (j8 & 1)*2;
                mma16816(s[j8], aql, bk[g][h], bk[g][h+1]);
            }
        }

        if (kt >= 2*qt) {
            #pragma unroll
            for (int j8 = 0; j8 < 8; j8++) {
                const int c = kt*64 + j8*8 + tig*2;
                if (c > row0g)   s[j8][0] = -1e30f;
                if (c+1 > row0g) s[j8][1] = -1e30f;
                if (c > row1g)   s[j8][2] = -1e30f;
                if (c+1 > row1g) s[j8][3] = -1e30f;
            }
        }

        float mx0 = -1e30f, mx1 = -1e30f;
        #pragma unroll
        for (int j8 = 0; j8 < 8; j8++) {
            mx0 = fmaxf(mx0, fmaxf(s[j8][0], s[j8][1]));
            mx1 = fmaxf(mx1, fmaxf(s[j8][2], s[j8][3]));
        }
        mx0 = fmaxf(mx0, __shfl_xor_sync(~0u, mx0, 1)); mx0 = fmaxf(mx0, __shfl_xor_sync(~0u, mx0, 2));
        mx1 = fmaxf(mx1, __shfl_xor_sync(~0u, mx1, 1)); mx1 = fmaxf(mx1, __shfl_xor_sync(~0u, mx1, 2));
        const float mn0 = fmaxf(mr0, mx0), mn1 = fmaxf(mr1, mx1);
        const float f0 = __expf(mr0 - mn0), f1 = __expf(mr1 - mn1);
        mr0 = mn0; mr1 = mn1;
        float s0 = 0.f, s1 = 0.f;
        #pragma unroll
        for (int j8 = 0; j8 < 8; j8++) {
            s[j8][0] = __expf(s[j8][0] - mn0); s[j8][1] = __expf(s[j8][1] - mn0);
            s[j8][2] = __expf(s[j8][2] - mn1); s[j8][3] = __expf(s[j8][3] - mn1);
            s0 += s[j8][0] + s[j8][1]; s1 += s[j8][2] + s[j8][3];
        }
        s0 += __shfl_xor_sync(~0u, s0, 1); s0 += __shfl_xor_sync(~0u, s0, 2);
        s1 += __shfl_xor_sync(~0u, s1, 1); s1 += __shfl_xor_sync(~0u, s1, 2);
        lr0 = lr0*f0 + s0; lr1 = lr1*f1 + s1;
        #pragma unroll
        for (int j8 = 0; j8 < 8; j8++) {
            o[j8][0] *= f0; o[j8][1] *= f0; o[j8][2] *= f1; o[j8][3] *= f1;
        }

        #pragma unroll
        for (int kk = 0; kk < 4; kk++) {
            uint32_t aph[4], apl[4];
            split2h(s[2*kk][0],   s[2*kk][1],   aph[0], apl[0]);
            split2h(s[2*kk][2],   s[2*kk][3],   aph[1], apl[1]);
            split2h(s[2*kk+1][0], s[2*kk+1][1], aph[2], apl[2]);
            split2h(s[2*kk+1][2], s[2*kk+1][3], aph[3], apl[3]);
            uint32_t bv[4][4];
            #pragma unroll
            for (int g = 0; g < 4; g++) {
                const int r = g*16 + b_r, c16 = kk*2 + b_k8;
                const int so = r*64 + ((c16 ^ (r & 7))*8);
                ldsm4(sbase + (uint32_t)(voff + so)*2, bv[g][0], bv[g][1], bv[g][2], bv[g][3]);
            }
            #pragma unroll
            for (int j8 = 0; j8 < 8; j8++) {
                const int g = j8 >> 1, h = (j8 & 1)*2;
                mma16816(o[j8], aph, bv[g][h], bv[g][h+1]);
            }
            #pragma unroll
            for (int j8 = 0; j8 < 8; j8++) {
                const int g = j8 >> 1, h = (j8 & 1)*2;
                mma16816(o[j8], apl, bv[g][h], bv[g][h+1]);
            }
        }
    }

    const float i0 = 1.f / lr0, i1 = 1.f / lr1;
    #pragma unroll
    for (int j8 = 0; j8 < 8; j8++) {
        const int col = hh*64 + j8*8 + tig*2;
        uint32_t hi, lo;
        size_t ob = ((size_t)bb*2048 + row0g) * DM + col;
        split2h(o[j8][0]*i0, o[j8][1]*i0, hi, lo);
        *(uint32_t*)&g_att_hi[ob] = hi; *(uint32_t*)&g_att_lo[ob] = lo;
        ob = ((size_t)bb*2048 + row1g) * DM + col;
        split2h(o[j8][2]*i1, o[j8][3]*i1, hi, lo);
        *(uint32_t*)&g_att_hi[ob] = hi; *(uint32_t*)&g_att_lo[ob] = lo;
    }
}

extern "C" void kernel_launch(void* const* d_in, const int* in_sizes, int n_in,
                              void* d_out, int out_size)
{
    (void)in_sizes; (void)n_in; (void)out_size;
    const float* x      = (const float*)d_in[0];
    const float* w_qkv  = (const float*)d_in[1];
    const float* w_proj = (const float*)d_in[2];
    float* out = (float*)d_out;

    static bool attr_done = false;
    if (!attr_done) {
        cudaFuncSetAttribute(attn_mma, cudaFuncAttributeMaxDynamicSharedMemorySize, ATTN_SMEM);
        cudaFuncSetAttribute(mma_gemm, cudaFuncAttributeMaxDynamicSharedMemorySize, GEMM_SMEM);
        attr_done = true;
    }

    split_x_kernel<<<MROWS*DM/256, 256>>>(x);
    split_wt_kernel<<<dim3(96, 32), 256>>>(w_qkv, 3*DM, 0);
    split_wt_kernel<<<dim3(32, 32), 256>>>(w_proj, DM, 1);
    mma_gemm<<<dim3(24, 32), 256, GEMM_SMEM>>>(nullptr, 0);
    attn_mma<<<dim3(16, 32), 256, ATTN_SMEM>>>();
    mma_gemm<<<dim3(8, 32), 256, GEMM_SMEM>>>(out, 1);
}

// round 11
// speedup vs baseline: 1.3958x; 1.0123x over previous
#include <cuda_runtime.h>
#include <cuda_fp16.h>
#include <cstdint>

constexpr int BATCH = 2, NSEQ = 2048, DM = 1024, NH = 16, DH = 64;
constexpr int MROWS = BATCH * NSEQ;

// Activations single fp16; weights split hi/lo (exact to ~2^-22); Q split for attention.
__device__ __align__(16) __half g_x[MROWS*DM];
__device__ __align__(16) __half g_wqkv_hi[3*DM*DM], g_wqkv_lo[3*DM*DM];  // [3072][1024] (transposed)
__device__ __align__(16) __half g_wp_hi[DM*DM],     g_wp_lo[DM*DM];      // [1024][1024] (transposed)
__device__ __align__(16) __half g_q_hi[MROWS*NH*DH], g_q_lo[MROWS*NH*DH]; // [bh][n][d] (pre-scaled)
__device__ __align__(16) __half g_k[MROWS*NH*DH];                        // [bh][n][d]
__device__ __align__(16) __half g_v[MROWS*NH*DH];                        // [bh][d][n] (transposed)
__device__ __align__(16) __half g_att[MROWS*DM];                         // [4096][1024]

// ---------------- helpers ----------------
__device__ __forceinline__ void ldsm4(uint32_t a, uint32_t& r0, uint32_t& r1, uint32_t& r2, uint32_t& r3) {
    asm volatile("ldmatrix.sync.aligned.m8n8.x4.shared.b16 {%0,%1,%2,%3}, [%4];\n"
                 : "=r"(r0), "=r"(r1), "=r"(r2), "=r"(r3) : "r"(a));
}
__device__ __forceinline__ void mma16816(float* c, const uint32_t* a, uint32_t b0, uint32_t b1) {
    asm volatile("mma.sync.aligned.m16n8k16.row.col.f32.f16.f16.f32 "
                 "{%0,%1,%2,%3}, {%4,%5,%6,%7}, {%8,%9}, {%0,%1,%2,%3};\n"
                 : "+f"(c[0]), "+f"(c[1]), "+f"(c[2]), "+f"(c[3])
                 : "r"(a[0]), "r"(a[1]), "r"(a[2]), "r"(a[3]), "r"(b0), "r"(b1));
}
__device__ __forceinline__ void split2h(float a, float b, uint32_t& hi, uint32_t& lo) {
    __half ha = __float2half_rn(a), hb = __float2half_rn(b);
    __half2 h2 = __halves2half2(ha, hb);
    __half2 l2 = __halves2half2(__float2half_rn(a - __half2float(ha)),
                                __float2half_rn(b - __half2float(hb)));
    hi = *(uint32_t*)&h2; lo = *(uint32_t*)&l2;
}
__device__ __forceinline__ uint32_t pack2h(float a, float b) {
    __half2 h2 = __halves2half2(__float2half_rn(a), __float2half_rn(b));
    return *(uint32_t*)&h2;
}
__device__ __forceinline__ void cp_async16(uint32_t dst, const void* src) {
    asm volatile("cp.async.cg.shared.global [%0], [%1], 16;\n" :: "r"(dst), "l"(src) : "memory");
}
__device__ __forceinline__ void cp_commit() { asm volatile("cp.async.commit_group;\n" ::: "memory"); }
template<int N> __device__ __forceinline__ void cp_wait() {
    asm volatile("cp.async.wait_group %0;\n" :: "n"(N) : "memory");
}

// ---------------- prep kernels ----------------
__global__ void round_x_kernel(const float* __restrict__ src) {
    int i = blockIdx.x * 256 + threadIdx.x;
    g_x[i] = __float2half_rn(src[i]);
}
// transpose [1024][N] -> [N][1024], split fp16 hi/lo. mode 0 = w_qkv, 1 = w_proj
__global__ void split_wt_kernel(const float* __restrict__ src, int N, int mode) {
    __shared__ float t[32][33];
    int n0 = blockIdx.x * 32, k0 = blockIdx.y * 32;
    int tx = threadIdx.x & 31, ty0 = threadIdx.x >> 5;
    for (int ty = ty0; ty < 32; ty += 8) t[ty][tx] = src[(size_t)(k0+ty)*N + n0 + tx];
    __syncthreads();
    __half* dh = mode ? g_wp_hi : g_wqkv_hi;
    __half* dl = mode ? g_wp_lo : g_wqkv_lo;
    for (int ty = ty0; ty < 32; ty += 8) {
        float v = t[tx][ty];
        __half h = __float2half_rn(v);
        size_t o = (size_t)(n0+ty)*1024 + k0 + tx;
        dh[o] = h; dl[o] = __float2half_rn(v - __half2float(h));
    }
}

// =====================================================================
// fp16 GEMM, B-split: C = A @ (Bhi+Blo)^T, BK=32 stages, 3-stage ring.
// smem/stage: 3 planes (A, Bhi, Blo) x 128 rows x 64B = 24KB.
// 8 warps (2m x 4n), 2 CTA/SM.
// mode 0: qkv (scatter q split / k / v).  mode 1: proj (fp32 out).
// =====================================================================
constexpr uint32_t G_STAGE = 3u * 128u * 64u;    // 24576 bytes
constexpr int GEMM_SMEM = 3 * (int)G_STAGE;      // 73728

__global__ __launch_bounds__(256, 2) void mma_gemm(float* __restrict__ Cout, int mode)
{
    extern __shared__ __align__(16) char dynsm[];
    const uint32_t sbase = (uint32_t)__cvta_generic_to_shared(dynsm);

    const __half* Ax  = mode ? g_att    : g_x;
    const __half* Bhi = mode ? g_wp_hi  : g_wqkv_hi;
    const __half* Blo = mode ? g_wp_lo  : g_wqkv_lo;

    const int m0 = blockIdx.y * 128, n0 = blockIdx.x * 128;
    const int tid = threadIdx.x, w = tid >> 5, lane = tid & 31;
    const int gid = lane >> 2, tig = lane & 3;
    const int wm = (w & 1) * 64, wn = (w >> 1) * 32;

    const __half* planes[3] = { Ax  + (size_t)m0 * 1024,
                                Bhi + (size_t)n0 * 1024,
                                Blo + (size_t)n0 * 1024 };

    // per stage: 3 planes x 128 rows x 4 cells(16B) = 1536 chunks, 6/thread
    auto issue_stage = [&](int s) {
        const uint32_t sbuf = sbase + (uint32_t)(s % 3) * G_STAGE;
        #pragma unroll
        for (int i = 0; i < 6; i++) {
            const int u = tid + 256 * i;
            const int plane = u >> 9, rem = u & 511;
            const int row = rem >> 2, cell = rem & 3;
            const uint32_t csw = (uint32_t)(cell ^ ((row >> 1) & 3));
            cp_async16(sbuf + (uint32_t)plane * 8192u + (uint32_t)row * 64u + csw * 16u,
                       planes[plane] + (size_t)row * 1024 + s * 32 + cell * 8);
        }
        cp_commit();
    };

    const int a_r = lane & 15, a_k8 = lane >> 4;
    const int b_r = (lane & 7) + ((lane >> 4) & 1) * 8, b_k8 = (lane >> 3) & 1;

    issue_stage(0);
    issue_stage(1);

    float acc[4][4][4] = {};

    for (int s = 0; s < 32; s++) {
        cp_wait<1>();
        __syncthreads();
        if (s + 2 < 32) issue_stage(s + 2);
        else cp_commit();

        const uint32_t bo = sbase + (uint32_t)(s % 3) * G_STAGE;

        #pragma unroll
        for (int hk = 0; hk < 2; hk++) {
            // B fragments: 2 n-groups x 2 planes (hi, lo)
            uint32_t bf[2][2][4];
            #pragma unroll
            for (int g = 0; g < 2; g++) {
                const int row = wn + g * 16 + b_r;
                const uint32_t csw = (uint32_t)((hk * 2 + b_k8) ^ ((row >> 1) & 3));
                const uint32_t ad = bo + 8192u + (uint32_t)row * 64u + csw * 16u;
                ldsm4(ad,         bf[0][g][0], bf[0][g][1], bf[0][g][2], bf[0][g][3]);
                ldsm4(ad + 8192u, bf[1][g][0], bf[1][g][1], bf[1][g][2], bf[1][g][3]);
            }
            // A fragments: single plane, double-buffered across i
            uint32_t ah[2][4];
            auto lda = [&](int i, int b) {
                const int row = wm + i * 16 + a_r;
                const uint32_t csw = (uint32_t)((hk * 2 + a_k8) ^ ((row >> 1) & 3));
                ldsm4(bo + (uint32_t)row * 64u + csw * 16u,
                      ah[b][0], ah[b][1], ah[b][2], ah[b][3]);
            };
            lda(0, 0);
            #pragma unroll
            for (int i = 0; i < 4; i++) {
                if (i < 3) lda(i + 1, (i + 1) & 1);
                const int cb = i & 1;
                #pragma unroll
                for (int jn = 0; jn < 4; jn++) {
                    const int g = jn >> 1, h2 = (jn & 1) * 2;
                    mma16816(acc[i][jn], ah[cb], bf[0][g][h2], bf[0][g][h2+1]);
                }
                #pragma unroll
                for (int jn = 0; jn < 4; jn++) {
                    const int g = jn >> 1, h2 = (jn & 1) * 2;
                    mma16816(acc[i][jn], ah[cb], bf[1][g][h2], bf[1][g][h2+1]);
                }
            }
        }
    }

    // ---------------- epilogue ----------------
    #pragma unroll
    for (int i = 0; i < 4; i++) {
        const int row0 = m0 + wm + i*16 + gid;
        #pragma unroll
        for (int jn = 0; jn < 4; jn++) {
            const int col = n0 + wn + jn*8 + tig*2;
            if (mode == 1) {
                *(float2*)&Cout[(size_t)row0*1024 + col]     = make_float2(acc[i][jn][0], acc[i][jn][1]);
                *(float2*)&Cout[(size_t)(row0+8)*1024 + col] = make_float2(acc[i][jn][2], acc[i][jn][3]);
            } else {
                #pragma unroll
                for (int r = 0; r < 4; r++) {
                    const int rr = row0 + ((r >= 2) ? 8 : 0), cc = col + (r & 1);
                    float v = acc[i][jn][r];
                    const int which = cc % 3, hd = cc / 3, h = hd >> 6, d = hd & 63;
                    const int bb = rr >> 11, nn = rr & 2047;
                    if (which == 0) {
                        v *= 0.125f;
                        const size_t o = ((size_t)(bb*16 + h)*2048 + nn)*64 + d;
                        __half h16 = __float2half_rn(v);
                        g_q_hi[o] = h16; g_q_lo[o] = __float2half_rn(v - __half2float(h16));
                    } else if (which == 1) {
                        g_k[((size_t)(bb*16 + h)*2048 + nn)*64 + d] = __float2half_rn(v);
                    } else {
                        g_v[((size_t)(bb*16 + h)*64 + d)*2048 + nn] = __float2half_rn(v);
                    }
                }
            }
        }
    }
}

// =====================================================================
// fp16 causal flash attention: Q split (A), K/V single fp16 (B).
// PAIRED k-tiles: one cp.async stage = 128 K-rows + 128 V-cols,
// ONE barrier per 2 k-tiles.  smem: Q 32KB + 2 stages x 32KB = 96KB.
// =====================================================================
constexpr int ATTN_SMEM = 98304;

__global__ __launch_bounds__(256, 2) void attn_mma()
{
    extern __shared__ __align__(16) __half dsm[];
    constexpr int QHI = 0, QLO = 8192;          // element (half) offsets

    const int qt = (int)gridDim.x - 1 - (int)blockIdx.x;
    const int bh = blockIdx.y, bb = bh >> 4, hh = bh & 15;
    const size_t base = (size_t)bh * (2048*64);
    const int tid = threadIdx.x, w = tid >> 5, lane = tid & 31;
    const int gid = lane >> 2, tig = lane & 3;
    const uint32_t sbase = (uint32_t)__cvta_generic_to_shared(dsm);
    const int a_r = lane & 15, a_k8 = lane >> 4;
    const int b_r = (lane & 7) + ((lane >> 4) & 1) * 8, b_k8 = (lane >> 3) & 1;

    // stage loader: K 128 rows x 8 cells + V 2 subtiles x 64 rows x 8 cells = 2048 chunks, 8/thread
    auto issue_kv = [&](int st) {
        const uint32_t sbuf = sbase + 32768u + (uint32_t)(st & 1) * 32768u;   // bytes
        #pragma unroll
        for (int i = 0; i < 8; i++) {
            const int u = tid + 256 * i;
            if ((u >> 10) == 0) {
                const int rem = u & 1023;
                const int row = rem >> 3, c16 = rem & 7;
                cp_async16(sbuf + (uint32_t)row * 128u + (uint32_t)((c16 ^ (row & 7)) * 16),
                           g_k + base + (size_t)(st * 128 + row) * 64 + c16 * 8);
            } else {
                const int rem = u & 1023;
                const int sub = rem >> 9, rem2 = rem & 511;
                const int row = rem2 >> 3, c16 = rem2 & 7;
                cp_async16(sbuf + 16384u + (uint32_t)sub * 8192u
                               + (uint32_t)row * 128u + (uint32_t)((c16 ^ (row & 7)) * 16),
                           g_v + base + (size_t)row * 2048 + (size_t)(st * 128 + sub * 64) + c16 * 8);
            }
        }
        cp_commit();
    };

    // load Q tile (128 x 64), both planes
    #pragma unroll
    for (int it = 0; it < 4; it++) {
        const int u = tid + 256*it, r = u >> 3, c16 = u & 7;
        const int so = r*64 + ((c16 ^ (r & 7))*8);
        const size_t go = base + (size_t)(qt*128 + r)*64 + c16*8;
        *(uint4*)&dsm[QHI + so] = *(const uint4*)(g_q_hi + go);
        *(uint4*)&dsm[QLO + so] = *(const uint4*)(g_q_lo + go);
    }

    float s[8][4], o[8][4] = {};
    float mr0 = -1e30f, mr1 = -1e30f, lr0 = 0.f, lr1 = 0.f;
    const int row0g = qt*128 + w*16 + gid, row1g = row0g + 8;
    const int nstages = qt + 1;   // 2 k-tiles per stage, ntiles = 2qt+2

    issue_kv(0);

    for (int st = 0; st < nstages; st++) {
        cp_wait<0>();
        __syncthreads();
        if (st + 1 < nstages) issue_kv(st + 1);

        const int kbase_e = 16384 + (st & 1) * 16384;   // stage base (elements)

        #pragma unroll
        for (int sub = 0; sub < 2; sub++) {
            const int kt = st * 2 + sub;
            const int koff = kbase_e + sub * 4096;           // K subtile
            const int voff = kbase_e + 8192 + sub * 4096;    // V subtile

            #pragma unroll
            for (int j = 0; j < 8; j++)
                #pragma unroll
                for (int r = 0; r < 4; r++) s[j][r] = 0.f;
            #pragma unroll
            for (int kk = 0; kk < 4; kk++) {
                uint32_t aqh[4], aql[4];
                {
                    const int r = w*16 + a_r, c16 = kk*2 + a_k8;
                    const int so = r*64 + ((c16 ^ (r & 7))*8);
                    ldsm4(sbase + (uint32_t)(QHI + so)*2, aqh[0], aqh[1], aqh[2], aqh[3]);
                    ldsm4(sbase + (uint32_t)(QLO + so)*2, aql[0], aql[1], aql[2], aql[3]);
                }
                uint32_t bk[4][4];
                #pragma unroll
                for (int g = 0; g < 4; g++) {
                    const int r = g*16 + b_r, c16 = kk*2 + b_k8;
                    const int so = r*64 + ((c16 ^ (r & 7))*8);
                    ldsm4(sbase + (uint32_t)(koff + so)*2, bk[g][0], bk[g][1], bk[g][2], bk[g][3]);
                }
                #pragma unroll
                for (int j8 = 0; j8 < 8; j8++) {
                    const int g = j8 >> 1, h = (j8 & 1)*2;
                    mma16816(s[j8], aqh, bk[g][h], bk[g][h+1]);
                }
                #pragma unroll
                for (int j8 = 0; j8 < 8; j8++) {
                    const int g = j8 >> 1, h = (j8 & 1)*2;
                    mma16816(s[j8], aql, bk[g][h], bk[g][h+1]);
                }
            }

            if (kt >= 2*qt) {
                #pragma unroll
                for (int j8 = 0; j8 < 8; j8++) {
                    const int c = kt*64 + j8*8 + tig*2;
                    if (c > row0g)   s[j8][0] = -1e30f;
                    if (c+1 > row0g) s[j8][1] = -1e30f;
                    if (c > row1g)   s[j8][2] = -1e30f;
                    if (c+1 > row1g) s[j8][3] = -1e30f;
                }
            }

            float mx0 = -1e30f, mx1 = -1e30f;
            #pragma unroll
            for (int j8 = 0; j8 < 8; j8++) {
                mx0 = fmaxf(mx0, fmaxf(s[j8][0], s[j8][1]));
                mx1 = fmaxf(mx1, fmaxf(s[j8][2], s[j8][3]));
            }
            mx0 = fmaxf(mx0, __shfl_xor_sync(~0u, mx0, 1)); mx0 = fmaxf(mx0, __shfl_xor_sync(~0u, mx0, 2));
            mx1 = fmaxf(mx1, __shfl_xor_sync(~0u, mx1, 1)); mx1 = fmaxf(mx1, __shfl_xor_sync(~0u, mx1, 2));
            const float mn0 = fmaxf(mr0, mx0), mn1 = fmaxf(mr1, mx1);
            const float f0 = __expf(mr0 - mn0), f1 = __expf(mr1 - mn1);
            mr0 = mn0; mr1 = mn1;
            float s0 = 0.f, s1 = 0.f;
            #pragma unroll
            for (int j8 = 0; j8 < 8; j8++) {
                s[j8][0] = __expf(s[j8][0] - mn0); s[j8][1] = __expf(s[j8][1] - mn0);
                s[j8][2] = __expf(s[j8][2] - mn1); s[j8][3] = __expf(s[j8][3] - mn1);
                s0 += s[j8][0] + s[j8][1]; s1 += s[j8][2] + s[j8][3];
            }
            s0 += __shfl_xor_sync(~0u, s0, 1); s0 += __shfl_xor_sync(~0u, s0, 2);
            s1 += __shfl_xor_sync(~0u, s1, 1); s1 += __shfl_xor_sync(~0u, s1, 2);
            lr0 = lr0*f0 + s0; lr1 = lr1*f1 + s1;
            #pragma unroll
            for (int j8 = 0; j8 < 8; j8++) {
                o[j8][0] *= f0; o[j8][1] *= f0; o[j8][2] *= f1; o[j8][3] *= f1;
            }

            #pragma unroll
            for (int kk = 0; kk < 4; kk++) {
                uint32_t aph[4], apl[4];
                split2h(s[2*kk][0],   s[2*kk][1],   aph[0], apl[0]);
                split2h(s[2*kk][2],   s[2*kk][3],   aph[1], apl[1]);
                split2h(s[2*kk+1][0], s[2*kk+1][1], aph[2], apl[2]);
                split2h(s[2*kk+1][2], s[2*kk+1][3], aph[3], apl[3]);
                uint32_t bv[4][4];
                #pragma unroll
                for (int g = 0; g < 4; g++) {
                    const int r = g*16 + b_r, c16 = kk*2 + b_k8;
                    const int so = r*64 + ((c16 ^ (r & 7))*8);
                    ldsm4(sbase + (uint32_t)(voff + so)*2, bv[g][0], bv[g][1], bv[g][2], bv[g][3]);
                }
                #pragma unroll
                for (int j8 = 0; j8 < 8; j8++) {
                    const int g = j8 >> 1, h = (j8 & 1)*2;
                    mma16816(o[j8], aph, bv[g][h], bv[g][h+1]);
                }
                #pragma unroll
                for (int j8 = 0; j8 < 8; j8++) {
                    const int g = j8 >> 1, h = (j8 & 1)*2;
                    mma16816(o[j8], apl, bv[g][h], bv[g][h+1]);
                }
            }
        }
    }

    // epilogue: att single fp16
    const float i0 = 1.f / lr0, i1 = 1.f / lr1;
    #pragma unroll
    for (int j8 = 0; j8 < 8; j8++) {
        const int col = hh*64 + j8*8 + tig*2;
        size_t ob = ((size_t)bb*2048 + row0g) * DM + col;
        *(uint32_t*)&g_att[ob] = pack2h(o[j8][0]*i0, o[j8][1]*i0);
        ob = ((size_t)bb*2048 + row1g) * DM + col;
        *(uint32_t*)&g_att[ob] = pack2h(o[j8][2]*i1, o[j8][3]*i1);
    }
}

extern "C" void kernel_launch(void* const* d_in, const int* in_sizes, int n_in,
                              void* d_out, int out_size)
{
    (void)in_sizes; (void)n_in; (void)out_size;
    const float* x      = (const float*)d_in[0];
    const float* w_qkv  = (const float*)d_in[1];
    const float* w_proj = (const float*)d_in[2];
    float* out = (float*)d_out;

    static bool attr_done = false;
    if (!attr_done) {
        cudaFuncSetAttribute(attn_mma, cudaFuncAttributeMaxDynamicSharedMemorySize, ATTN_SMEM);
        cudaFuncSetAttribute(mma_gemm, cudaFuncAttributeMaxDynamicSharedMemorySize, GEMM_SMEM);
        attr_done = true;
    }

    round_x_kernel<<<MROWS*DM/256, 256>>>(x);
    split_wt_kernel<<<dim3(96, 32), 256>>>(w_qkv, 3*DM, 0);
    split_wt_kernel<<<dim3(32, 32), 256>>>(w_proj, DM, 1);
    mma_gemm<<<dim3(24, 32), 256, GEMM_SMEM>>>(nullptr, 0);
    attn_mma<<<dim3(16, 32), 256, ATTN_SMEM>>>();
    mma_gemm<<<dim3(8, 32), 256, GEMM_SMEM>>>(out, 1);
}

// round 12
// speedup vs baseline: 1.7053x; 1.2218x over previous
#include <cuda_runtime.h>
#include <cuda_fp16.h>
#include <cstdint>

constexpr int BATCH = 2, NSEQ = 2048, DM = 1024, NH = 16, DH = 64;
constexpr int MROWS = BATCH * NSEQ;

__device__ __align__(16) __half g_x[MROWS*DM];
__device__ __align__(16) __half g_wqk_hi[2*DM*DM], g_wqk_lo[2*DM*DM];  // [2048][1024]: rows 0..1023 = Wq, 1024..2047 = Wk
__device__ __align__(16) __half g_wv[DM*DM];                            // [1024][1024] single fp16
__device__ __align__(16) __half g_wp_hi[DM*DM],    g_wp_lo[DM*DM];      // [1024][1024]
__device__ __align__(16) __half g_q_hi[MROWS*NH*DH], g_q_lo[MROWS*NH*DH]; // [bh][n][d] (pre-scaled)
__device__ __align__(16) __half g_k[MROWS*NH*DH];                       // [bh][n][d]
__device__ __align__(16) __half g_v[MROWS*NH*DH];                       // [bh][d][n] (transposed)
__device__ __align__(16) __half g_att[MROWS*DM];                        // [4096][1024]

// ---------------- helpers ----------------
__device__ __forceinline__ void ldsm4(uint32_t a, uint32_t& r0, uint32_t& r1, uint32_t& r2, uint32_t& r3) {
    asm volatile("ldmatrix.sync.aligned.m8n8.x4.shared.b16 {%0,%1,%2,%3}, [%4];\n"
                 : "=r"(r0), "=r"(r1), "=r"(r2), "=r"(r3) : "r"(a));
}
__device__ __forceinline__ void mma16816(float* c, const uint32_t* a, uint32_t b0, uint32_t b1) {
    asm volatile("mma.sync.aligned.m16n8k16.row.col.f32.f16.f16.f32 "
                 "{%0,%1,%2,%3}, {%4,%5,%6,%7}, {%8,%9}, {%0,%1,%2,%3};\n"
                 : "+f"(c[0]), "+f"(c[1]), "+f"(c[2]), "+f"(c[3])
                 : "r"(a[0]), "r"(a[1]), "r"(a[2]), "r"(a[3]), "r"(b0), "r"(b1));
}
__device__ __forceinline__ void split2h(float a, float b, uint32_t& hi, uint32_t& lo) {
    __half ha = __float2half_rn(a), hb = __float2half_rn(b);
    __half2 h2 = __halves2half2(ha, hb);
    __half2 l2 = __halves2half2(__float2half_rn(a - __half2float(ha)),
                                __float2half_rn(b - __half2float(hb)));
    hi = *(uint32_t*)&h2; lo = *(uint32_t*)&l2;
}
__device__ __forceinline__ uint32_t pack2h(float a, float b) {
    __half2 h2 = __halves2half2(__float2half_rn(a), __float2half_rn(b));
    return *(uint32_t*)&h2;
}
__device__ __forceinline__ void cp_async16(uint32_t dst, const void* src) {
    asm volatile("cp.async.cg.shared.global [%0], [%1], 16;\n" :: "r"(dst), "l"(src) : "memory");
}
__device__ __forceinline__ void cp_commit() { asm volatile("cp.async.commit_group;\n" ::: "memory"); }
template<int N> __device__ __forceinline__ void cp_wait() {
    asm volatile("cp.async.wait_group %0;\n" :: "n"(N) : "memory");
}

// ---------------- prep kernels ----------------
__global__ void round_x_kernel(const float* __restrict__ src) {
    int i = blockIdx.x * 256 + threadIdx.x;
    g_x[i] = __float2half_rn(src[i]);
}
// w_qkv [1024][3072] -> de-interleave + transpose: Wqk split (2048 rows), Wv single (1024 rows)
__global__ void split_wqkv_kernel(const float* __restrict__ src) {
    __shared__ float t[32][33];
    int n0 = blockIdx.x * 32, k0 = blockIdx.y * 32;
    int tx = threadIdx.x & 31, ty0 = threadIdx.x >> 5;
    for (int ty = ty0; ty < 32; ty += 8) t[ty][tx] = src[(size_t)(k0+ty)*3072 + n0 + tx];
    __syncthreads();
    for (int ty = ty0; ty < 32; ty += 8) {
        const int n = n0 + ty, k = k0 + tx;
        const float v = t[tx][ty];
        const int which = n % 3, hd = n / 3;
        if (which == 2) {
            g_wv[(size_t)hd * 1024 + k] = __float2half_rn(v);
        } else {
            const int row = which * 1024 + hd;      // 0..1023 q, 1024..2047 k
            __half h = __float2half_rn(v);
            const size_t o = (size_t)row * 1024 + k;
            g_wqk_hi[o] = h;
            g_wqk_lo[o] = __float2half_rn(v - __half2float(h));
        }
    }
}
// w_proj [1024][1024] -> transpose + split
__global__ void split_wp_kernel(const float* __restrict__ src) {
    __shared__ float t[32][33];
    int n0 = blockIdx.x * 32, k0 = blockIdx.y * 32;
    int tx = threadIdx.x & 31, ty0 = threadIdx.x >> 5;
    for (int ty = ty0; ty < 32; ty += 8) t[ty][tx] = src[(size_t)(k0+ty)*1024 + n0 + tx];
    __syncthreads();
    for (int ty = ty0; ty < 32; ty += 8) {
        float v = t[tx][ty];
        __half h = __float2half_rn(v);
        size_t o = (size_t)(n0+ty)*1024 + k0 + tx;
        g_wp_hi[o] = h; g_wp_lo[o] = __float2half_rn(v - __half2float(h));
    }
}

// =====================================================================
// 2-term GEMM (B split): C = A @ (Bhi+Blo)^T.  BK=32, 3-stage ring.
// mode 0: qk (scatter q split / k).  mode 1: proj (fp32 out).
// =====================================================================
constexpr uint32_t G_STAGE = 3u * 128u * 64u;    // 24576 bytes
constexpr int GEMM_SMEM = 3 * (int)G_STAGE;      // 73728

__global__ __launch_bounds__(256, 2) void gemm2(float* __restrict__ Cout, int mode)
{
    extern __shared__ __align__(16) char dynsm[];
    const uint32_t sbase = (uint32_t)__cvta_generic_to_shared(dynsm);

    const __half* Ax  = mode ? g_att   : g_x;
    const __half* Bhi = mode ? g_wp_hi : g_wqk_hi;
    const __half* Blo = mode ? g_wp_lo : g_wqk_lo;

    const int m0 = blockIdx.y * 128, n0 = blockIdx.x * 128;
    const int tid = threadIdx.x, w = tid >> 5, lane = tid & 31;
    const int gid = lane >> 2, tig = lane & 3;
    const int wm = (w & 1) * 64, wn = (w >> 1) * 32;

    const __half* planes[3] = { Ax  + (size_t)m0 * 1024,
                                Bhi + (size_t)n0 * 1024,
                                Blo + (size_t)n0 * 1024 };

    auto issue_stage = [&](int s) {
        const uint32_t sbuf = sbase + (uint32_t)(s % 3) * G_STAGE;
        #pragma unroll
        for (int i = 0; i < 6; i++) {
            const int u = tid + 256 * i;
            const int plane = u >> 9, rem = u & 511;
            const int row = rem >> 2, cell = rem & 3;
            const uint32_t csw = (uint32_t)(cell ^ ((row >> 1) & 3));
            cp_async16(sbuf + (uint32_t)plane * 8192u + (uint32_t)row * 64u + csw * 16u,
                       planes[plane] + (size_t)row * 1024 + s * 32 + cell * 8);
        }
        cp_commit();
    };

    const int a_r = lane & 15, a_k8 = lane >> 4;
    const int b_r = (lane & 7) + ((lane >> 4) & 1) * 8, b_k8 = (lane >> 3) & 1;

    issue_stage(0);
    issue_stage(1);

    float acc[4][4][4] = {};

    for (int s = 0; s < 32; s++) {
        cp_wait<1>();
        __syncthreads();
        if (s + 2 < 32) issue_stage(s + 2);
        else cp_commit();

        const uint32_t bo = sbase + (uint32_t)(s % 3) * G_STAGE;

        #pragma unroll
        for (int hk = 0; hk < 2; hk++) {
            uint32_t bf[2][2][4];
            #pragma unroll
            for (int g = 0; g < 2; g++) {
                const int row = wn + g * 16 + b_r;
                const uint32_t csw = (uint32_t)((hk * 2 + b_k8) ^ ((row >> 1) & 3));
                const uint32_t ad = bo + 8192u + (uint32_t)row * 64u + csw * 16u;
                ldsm4(ad,         bf[0][g][0], bf[0][g][1], bf[0][g][2], bf[0][g][3]);
                ldsm4(ad + 8192u, bf[1][g][0], bf[1][g][1], bf[1][g][2], bf[1][g][3]);
            }
            uint32_t ah[2][4];
            auto lda = [&](int i, int b) {
                const int row = wm + i * 16 + a_r;
                const uint32_t csw = (uint32_t)((hk * 2 + a_k8) ^ ((row >> 1) & 3));
                ldsm4(bo + (uint32_t)row * 64u + csw * 16u,
                      ah[b][0], ah[b][1], ah[b][2], ah[b][3]);
            };
            lda(0, 0);
            #pragma unroll
            for (int i = 0; i < 4; i++) {
                if (i < 3) lda(i + 1, (i + 1) & 1);
                const int cb = i & 1;
                #pragma unroll
                for (int jn = 0; jn < 4; jn++) {
                    const int g = jn >> 1, h2 = (jn & 1) * 2;
                    mma16816(acc[i][jn], ah[cb], bf[0][g][h2], bf[0][g][h2+1]);
                }
                #pragma unroll
                for (int jn = 0; jn < 4; jn++) {
                    const int g = jn >> 1, h2 = (jn & 1) * 2;
                    mma16816(acc[i][jn], ah[cb], bf[1][g][h2], bf[1][g][h2+1]);
                }
            }
        }
    }

    #pragma unroll
    for (int i = 0; i < 4; i++) {
        const int row0 = m0 + wm + i*16 + gid;
        #pragma unroll
        for (int jn = 0; jn < 4; jn++) {
            const int col = n0 + wn + jn*8 + tig*2;
            if (mode == 1) {
                *(float2*)&Cout[(size_t)row0*1024 + col]     = make_float2(acc[i][jn][0], acc[i][jn][1]);
                *(float2*)&Cout[(size_t)(row0+8)*1024 + col] = make_float2(acc[i][jn][2], acc[i][jn][3]);
            } else {
                #pragma unroll
                for (int r = 0; r < 4; r++) {
                    const int rr = row0 + ((r >= 2) ? 8 : 0), cc = col + (r & 1);
                    float v = acc[i][jn][r];
                    const int bb = rr >> 11, nn = rr & 2047;
                    if (cc < 1024) {        // q: split + pre-scale
                        v *= 0.125f;
                        const int h = cc >> 6, d = cc & 63;
                        const size_t o = ((size_t)(bb*16 + h)*2048 + nn)*64 + d;
                        __half h16 = __float2half_rn(v);
                        g_q_hi[o] = h16; g_q_lo[o] = __float2half_rn(v - __half2float(h16));
                    } else {                // k: single
                        const int c2 = cc - 1024, h = c2 >> 6, d = c2 & 63;
                        g_k[((size_t)(bb*16 + h)*2048 + nn)*64 + d] = __float2half_rn(v);
                    }
                }
            }
        }
    }
}

// =====================================================================
// 1-term GEMM: V = x @ Wv^T (single fp16 both sides).  2-plane stages.
// Epilogue scatters v transposed [bh][d][n].
// =====================================================================
constexpr uint32_t G1_STAGE = 2u * 128u * 64u;   // 16384 bytes
constexpr int G1_SMEM = 3 * (int)G1_STAGE;       // 49152

__global__ __launch_bounds__(256, 2) void gemm1_v()
{
    extern __shared__ __align__(16) char dynsm[];
    const uint32_t sbase = (uint32_t)__cvta_generic_to_shared(dynsm);

    const int m0 = blockIdx.y * 128, n0 = blockIdx.x * 128;
    const int tid = threadIdx.x, w = tid >> 5, lane = tid & 31;
    const int gid = lane >> 2, tig = lane & 3;
    const int wm = (w & 1) * 64, wn = (w >> 1) * 32;

    const __half* planes[2] = { g_x  + (size_t)m0 * 1024,
                                g_wv + (size_t)n0 * 1024 };

    // per stage: 2 planes x 128 rows x 4 cells = 1024 chunks, 4/thread
    auto issue_stage = [&](int s) {
        const uint32_t sbuf = sbase + (uint32_t)(s % 3) * G1_STAGE;
        #pragma unroll
        for (int i = 0; i < 4; i++) {
            const int u = tid + 256 * i;
            const int plane = u >> 9, rem = u & 511;
            const int row = rem >> 2, cell = rem & 3;
            const uint32_t csw = (uint32_t)(cell ^ ((row >> 1) & 3));
            cp_async16(sbuf + (uint32_t)plane * 8192u + (uint32_t)row * 64u + csw * 16u,
                       planes[plane] + (size_t)row * 1024 + s * 32 + cell * 8);
        }
        cp_commit();
    };

    const int a_r = lane & 15, a_k8 = lane >> 4;
    const int b_r = (lane & 7) + ((lane >> 4) & 1) * 8, b_k8 = (lane >> 3) & 1;

    issue_stage(0);
    issue_stage(1);

    float acc[4][4][4] = {};

    for (int s = 0; s < 32; s++) {
        cp_wait<1>();
        __syncthreads();
        if (s + 2 < 32) issue_stage(s + 2);
        else cp_commit();

        const uint32_t bo = sbase + (uint32_t)(s % 3) * G1_STAGE;

        #pragma unroll
        for (int hk = 0; hk < 2; hk++) {
            uint32_t bf[2][4];
            #pragma unroll
            for (int g = 0; g < 2; g++) {
                const int row = wn + g * 16 + b_r;
                const uint32_t csw = (uint32_t)((hk * 2 + b_k8) ^ ((row >> 1) & 3));
                ldsm4(bo + 8192u + (uint32_t)row * 64u + csw * 16u,
                      bf[g][0], bf[g][1], bf[g][2], bf[g][3]);
            }
            uint32_t ah[2][4];
            auto lda = [&](int i, int b) {
                const int row = wm + i * 16 + a_r;
                const uint32_t csw = (uint32_t)((hk * 2 + a_k8) ^ ((row >> 1) & 3));
                ldsm4(bo + (uint32_t)row * 64u + csw * 16u,
                      ah[b][0], ah[b][1], ah[b][2], ah[b][3]);
            };
            lda(0, 0);
            #pragma unroll
            for (int i = 0; i < 4; i++) {
                if (i < 3) lda(i + 1, (i + 1) & 1);
                const int cb = i & 1;
                #pragma unroll
                for (int jn = 0; jn < 4; jn++) {
                    const int g = jn >> 1, h2 = (jn & 1) * 2;
                    mma16816(acc[i][jn], ah[cb], bf[g][h2], bf[g][h2+1]);
                }
            }
        }
    }

    #pragma unroll
    for (int i = 0; i < 4; i++) {
        const int row0 = m0 + wm + i*16 + gid;
        #pragma unroll
        for (int jn = 0; jn < 4; jn++) {
            const int col = n0 + wn + jn*8 + tig*2;
            #pragma unroll
            for (int r = 0; r < 4; r++) {
                const int rr = row0 + ((r >= 2) ? 8 : 0), cc = col + (r & 1);
                const int bb = rr >> 11, nn = rr & 2047;
                const int h = cc >> 6, d = cc & 63;
                g_v[((size_t)(bb*16 + h)*64 + d)*2048 + nn] = __float2half_rn(acc[i][jn][r]);
            }
        }
    }
}

// =====================================================================
// fp16 causal flash attention: Q split (2-term QK), single-fp16 P (1-term PV).
// Paired k-tiles per cp.async stage; one barrier per 2 k-tiles.
// smem: Q 32KB + 2 stages x 32KB = 96KB.
// =====================================================================
constexpr int ATTN_SMEM = 98304;

__global__ __launch_bounds__(256, 2) void attn_mma()
{
    extern __shared__ __align__(16) __half dsm[];
    constexpr int QHI = 0, QLO = 8192;

    const int qt = (int)gridDim.x - 1 - (int)blockIdx.x;
    const int bh = blockIdx.y, bb = bh >> 4, hh = bh & 15;
    const size_t base = (size_t)bh * (2048*64);
    const int tid = threadIdx.x, w = tid >> 5, lane = tid & 31;
    const int gid = lane >> 2, tig = lane & 3;
    const uint32_t sbase = (uint32_t)__cvta_generic_to_shared(dsm);
    const int a_r = lane & 15, a_k8 = lane >> 4;
    const int b_r = (lane & 7) + ((lane >> 4) & 1) * 8, b_k8 = (lane >> 3) & 1;

    auto issue_kv = [&](int st) {
        const uint32_t sbuf = sbase + 32768u + (uint32_t)(st & 1) * 32768u;
        #pragma unroll
        for (int i = 0; i < 8; i++) {
            const int u = tid + 256 * i;
            if ((u >> 10) == 0) {
                const int rem = u & 1023;
                const int row = rem >> 3, c16 = rem & 7;
                cp_async16(sbuf + (uint32_t)row * 128u + (uint32_t)((c16 ^ (row & 7)) * 16),
                           g_k + base + (size_t)(st * 128 + row) * 64 + c16 * 8);
            } else {
                const int rem = u & 1023;
                const int sub = rem >> 9, rem2 = rem & 511;
                const int row = rem2 >> 3, c16 = rem2 & 7;
                cp_async16(sbuf + 16384u + (uint32_t)sub * 8192u
                               + (uint32_t)row * 128u + (uint32_t)((c16 ^ (row & 7)) * 16),
                           g_v + base + (size_t)row * 2048 + (size_t)(st * 128 + sub * 64) + c16 * 8);
            }
        }
        cp_commit();
    };

    #pragma unroll
    for (int it = 0; it < 4; it++) {
        const int u = tid + 256*it, r = u >> 3, c16 = u & 7;
        const int so = r*64 + ((c16 ^ (r & 7))*8);
        const size_t go = base + (size_t)(qt*128 + r)*64 + c16*8;
        *(uint4*)&dsm[QHI + so] = *(const uint4*)(g_q_hi + go);
        *(uint4*)&dsm[QLO + so] = *(const uint4*)(g_q_lo + go);
    }

    float s[8][4], o[8][4] = {};
    float mr0 = -1e30f, mr1 = -1e30f, lr0 = 0.f, lr1 = 0.f;
    const int row0g = qt*128 + w*16 + gid, row1g = row0g + 8;
    const int nstages = qt + 1;

    issue_kv(0);

    for (int st = 0; st < nstages; st++) {
        cp_wait<0>();
        __syncthreads();
        if (st + 1 < nstages) issue_kv(st + 1);

        const int kbase_e = 16384 + (st & 1) * 16384;

        #pragma unroll
        for (int sub = 0; sub < 2; sub++) {
            const int kt = st * 2 + sub;
            const int koff = kbase_e + sub * 4096;
            const int voff = kbase_e + 8192 + sub * 4096;

            #pragma unroll
            for (int j = 0; j < 8; j++)
                #pragma unroll
                for (int r = 0; r < 4; r++) s[j][r] = 0.f;
            #pragma unroll
            for (int kk = 0; kk < 4; kk++) {
                uint32_t aqh[4], aql[4];
                {
                    const int r = w*16 + a_r, c16 = kk*2 + a_k8;
                    const int so = r*64 + ((c16 ^ (r & 7))*8);
                    ldsm4(sbase + (uint32_t)(QHI + so)*2, aqh[0], aqh[1], aqh[2], aqh[3]);
                    ldsm4(sbase + (uint32_t)(QLO + so)*2, aql[0], aql[1], aql[2], aql[3]);
                }
                uint32_t bk[4][4];
                #pragma unroll
                for (int g = 0; g < 4; g++) {
                    const int r = g*16 + b_r, c16 = kk*2 + b_k8;
                    const int so = r*64 + ((c16 ^ (r & 7))*8);
                    ldsm4(sbase + (uint32_t)(koff + so)*2, bk[g][0], bk[g][1], bk[g][2], bk[g][3]);
                }
                #pragma unroll
                for (int j8 = 0; j8 < 8; j8++) {
                    const int g = j8 >> 1, h = (j8 & 1)*2;
                    mma16816(s[j8], aqh, bk[g][h], bk[g][h+1]);
                }
                #pragma unroll
                for (int j8 = 0; j8 < 8; j8++) {
                    const int g = j8 >> 1, h = (j8 & 1)*2;
                    mma16816(s[j8], aql, bk[g][h], bk[g][h+1]);
                }
            }

            if (kt >= 2*qt) {
                #pragma unroll
                for (int j8 = 0; j8 < 8; j8++) {
                    const int c = kt*64 + j8*8 + tig*2;
                    if (c > row0g)   s[j8][0] = -1e30f;
                    if (c+1 > row0g) s[j8][1] = -1e30f;
                    if (c > row1g)   s[j8][2] = -1e30f;
                    if (c+1 > row1g) s[j8][3] = -1e30f;
                }
            }

            float mx0 = -1e30f, mx1 = -1e30f;
            #pragma unroll
            for (int j8 = 0; j8 < 8; j8++) {
                mx0 = fmaxf(mx0, fmaxf(s[j8][0], s[j8][1]));
                mx1 = fmaxf(mx1, fmaxf(s[j8][2], s[j8][3]));
            }
            mx0 = fmaxf(mx0, __shfl_xor_sync(~0u, mx0, 1)); mx0 = fmaxf(mx0, __shfl_xor_sync(~0u, mx0, 2));
            mx1 = fmaxf(mx1, __shfl_xor_sync(~0u, mx1, 1)); mx1 = fmaxf(mx1, __shfl_xor_sync(~0u, mx1, 2));
            const float mn0 = fmaxf(mr0, mx0), mn1 = fmaxf(mr1, mx1);
            const float f0 = __expf(mr0 - mn0), f1 = __expf(mr1 - mn1);
            mr0 = mn0; mr1 = mn1;
            float s0 = 0.f, s1 = 0.f;
            #pragma unroll
            for (int j8 = 0; j8 < 8; j8++) {
                s[j8][0] = __expf(s[j8][0] - mn0); s[j8][1] = __expf(s[j8][1] - mn0);
                s[j8][2] = __expf(s[j8][2] - mn1); s[j8][3] = __expf(s[j8][3] - mn1);
                s0 += s[j8][0] + s[j8][1]; s1 += s[j8][2] + s[j8][3];
            }
            s0 += __shfl_xor_sync(~0u, s0, 1); s0 += __shfl_xor_sync(~0u, s0, 2);
            s1 += __shfl_xor_sync(~0u, s1, 1); s1 += __shfl_xor_sync(~0u, s1, 2);
            lr0 = lr0*f0 + s0; lr1 = lr1*f1 + s1;
            #pragma unroll
            for (int j8 = 0; j8 < 8; j8++) {
                o[j8][0] *= f0; o[j8][1] *= f0; o[j8][2] *= f1; o[j8][3] *= f1;
            }

            // PV: single-fp16 P (1-term)
            #pragma unroll
            for (int kk = 0; kk < 4; kk++) {
                uint32_t ap[4];
                ap[0] = pack2h(s[2*kk][0],   s[2*kk][1]);
                ap[1] = pack2h(s[2*kk][2],   s[2*kk][3]);
                ap[2] = pack2h(s[2*kk+1][0], s[2*kk+1][1]);
                ap[3] = pack2h(s[2*kk+1][2], s[2*kk+1][3]);
                uint32_t bv[4][4];
                #pragma unroll
                for (int g = 0; g < 4; g++) {
                    const int r = g*16 + b_r, c16 = kk*2 + b_k8;
                    const int so = r*64 + ((c16 ^ (r & 7))*8);
                    ldsm4(sbase + (uint32_t)(voff + so)*2, bv[g][0], bv[g][1], bv[g][2], bv[g][3]);
                }
                #pragma unroll
                for (int j8 = 0; j8 < 8; j8++) {
                    const int g = j8 >> 1, h = (j8 & 1)*2;
                    mma16816(o[j8], ap, bv[g][h], bv[g][h+1]);
                }
            }
        }
    }

    const float i0 = 1.f / lr0, i1 = 1.f / lr1;
    #pragma unroll
    for (int j8 = 0; j8 < 8; j8++) {
        const int col = hh*64 + j8*8 + tig*2;
        size_t ob = ((size_t)bb*2048 + row0g) * DM + col;
        *(uint32_t*)&g_att[ob] = pack2h(o[j8][0]*i0, o[j8][1]*i0);
        ob = ((size_t)bb*2048 + row1g) * DM + col;
        *(uint32_t*)&g_att[ob] = pack2h(o[j8][2]*i1, o[j8][3]*i1);
    }
}

extern "C" void kernel_launch(void* const* d_in, const int* in_sizes, int n_in,
                              void* d_out, int out_size)
{
    (void)in_sizes; (void)n_in; (void)out_size;
    const float* x      = (const float*)d_in[0];
    const float* w_qkv  = (const float*)d_in[1];
    const float* w_proj = (const float*)d_in[2];
    float* out = (float*)d_out;

    static bool attr_done = false;
    if (!attr_done) {
        cudaFuncSetAttribute(attn_mma, cudaFuncAttributeMaxDynamicSharedMemorySize, ATTN_SMEM);
        cudaFuncSetAttribute(gemm2,    cudaFuncAttributeMaxDynamicSharedMemorySize, GEMM_SMEM);
        cudaFuncSetAttribute(gemm1_v,  cudaFuncAttributeMaxDynamicSharedMemorySize, G1_SMEM);
        attr_done = true;
    }

    round_x_kernel<<<MROWS*DM/256, 256>>>(x);
    split_wqkv_kernel<<<dim3(96, 32), 256>>>(w_qkv);
    split_wp_kernel<<<dim3(32, 32), 256>>>(w_proj);
    gemm2<<<dim3(16, 32), 256, GEMM_SMEM>>>(nullptr, 0);   // q (split) + k
    gemm1_v<<<dim3(8, 32), 256, G1_SMEM>>>();              // v (single)
    attn_mma<<<dim3(16, 32), 256, ATTN_SMEM>>>();
    gemm2<<<dim3(8, 32), 256, GEMM_SMEM>>>(out, 1);        // proj
}

// round 13
// speedup vs baseline: 2.0451x; 1.1993x over previous
#include <cuda_runtime.h>
#include <cuda_fp16.h>
#include <cstdint>

constexpr int BATCH = 2, NSEQ = 2048, DM = 1024, NH = 16, DH = 64;
constexpr int MROWS = BATCH * NSEQ;

__device__ __align__(16) __half g_x[MROWS*DM];
__device__ __align__(16) __half g_wqk_hi[2*DM*DM], g_wqk_lo[2*DM*DM];  // [2048][1024]: 0..1023 Wq, 1024..2047 Wk
__device__ __align__(16) __half g_wv[DM*DM];                            // [1024][1024] single
__device__ __align__(16) __half g_wp[DM*DM];                            // [1024][1024] single
__device__ __align__(16) __half g_q[MROWS*NH*DH];                       // [bh][n][d] (pre-scaled, single)
__device__ __align__(16) __half g_k[MROWS*NH*DH];                       // [bh][n][d]
__device__ __align__(16) __half g_v[MROWS*NH*DH];                       // [bh][d][n] (transposed)
__device__ __align__(16) __half g_att[MROWS*DM];                        // [4096][1024]

// ---------------- helpers ----------------
__device__ __forceinline__ void ldsm4(uint32_t a, uint32_t& r0, uint32_t& r1, uint32_t& r2, uint32_t& r3) {
    asm volatile("ldmatrix.sync.aligned.m8n8.x4.shared.b16 {%0,%1,%2,%3}, [%4];\n"
                 : "=r"(r0), "=r"(r1), "=r"(r2), "=r"(r3) : "r"(a));
}
__device__ __forceinline__ void mma16816(float* c, const uint32_t* a, uint32_t b0, uint32_t b1) {
    asm volatile("mma.sync.aligned.m16n8k16.row.col.f32.f16.f16.f32 "
                 "{%0,%1,%2,%3}, {%4,%5,%6,%7}, {%8,%9}, {%0,%1,%2,%3};\n"
                 : "+f"(c[0]), "+f"(c[1]), "+f"(c[2]), "+f"(c[3])
                 : "r"(a[0]), "r"(a[1]), "r"(a[2]), "r"(a[3]), "r"(b0), "r"(b1));
}
__device__ __forceinline__ uint32_t pack2h(float a, float b) {
    __half2 h2 = __halves2half2(__float2half_rn(a), __float2half_rn(b));
    return *(uint32_t*)&h2;
}
__device__ __forceinline__ void cp_async16(uint32_t dst, const void* src) {
    asm volatile("cp.async.cg.shared.global [%0], [%1], 16;\n" :: "r"(dst), "l"(src) : "memory");
}
__device__ __forceinline__ void cp_commit() { asm volatile("cp.async.commit_group;\n" ::: "memory"); }
template<int N> __device__ __forceinline__ void cp_wait() {
    asm volatile("cp.async.wait_group %0;\n" :: "n"(N) : "memory");
}

// ---------------- prep kernels ----------------
__global__ void round_x_kernel(const float* __restrict__ src) {
    int i = blockIdx.x * 256 + threadIdx.x;
    g_x[i] = __float2half_rn(src[i]);
}
// w_qkv [1024][3072] -> de-interleave + transpose: Wqk split (2048 rows), Wv single
__global__ void split_wqkv_kernel(const float* __restrict__ src) {
    __shared__ float t[32][33];
    int n0 = blockIdx.x * 32, k0 = blockIdx.y * 32;
    int tx = threadIdx.x & 31, ty0 = threadIdx.x >> 5;
    for (int ty = ty0; ty < 32; ty += 8) t[ty][tx] = src[(size_t)(k0+ty)*3072 + n0 + tx];
    __syncthreads();
    for (int ty = ty0; ty < 32; ty += 8) {
        const int n = n0 + ty, k = k0 + tx;
        const float v = t[tx][ty];
        const int which = n % 3, hd = n / 3;
        if (which == 2) {
            g_wv[(size_t)hd * 1024 + k] = __float2half_rn(v);
        } else {
            const int row = which * 1024 + hd;
            __half h = __float2half_rn(v);
            const size_t o = (size_t)row * 1024 + k;
            g_wqk_hi[o] = h;
            g_wqk_lo[o] = __float2half_rn(v - __half2float(h));
        }
    }
}
// w_proj [1024][1024] -> transpose, single fp16
__global__ void round_wp_kernel(const float* __restrict__ src) {
    __shared__ float t[32][33];
    int n0 = blockIdx.x * 32, k0 = blockIdx.y * 32;
    int tx = threadIdx.x & 31, ty0 = threadIdx.x >> 5;
    for (int ty = ty0; ty < 32; ty += 8) t[ty][tx] = src[(size_t)(k0+ty)*1024 + n0 + tx];
    __syncthreads();
    for (int ty = ty0; ty < 32; ty += 8)
        g_wp[(size_t)(n0+ty)*1024 + k0 + tx] = __float2half_rn(t[tx][ty]);
}

// =====================================================================
// 2-term GEMM (B split): qk = x @ (Wqk_hi+Wqk_lo)^T.  BK=32, 3-stage ring.
// Epilogue: scatter q (pre-scaled, single fp16) and k.
// =====================================================================
constexpr uint32_t G_STAGE = 3u * 128u * 64u;    // 24576 bytes
constexpr int GEMM_SMEM = 3 * (int)G_STAGE;      // 73728

__global__ __launch_bounds__(256, 2) void gemm2_qk()
{
    extern __shared__ __align__(16) char dynsm[];
    const uint32_t sbase = (uint32_t)__cvta_generic_to_shared(dynsm);

    const int m0 = blockIdx.y * 128, n0 = blockIdx.x * 128;
    const int tid = threadIdx.x, w = tid >> 5, lane = tid & 31;
    const int gid = lane >> 2, tig = lane & 3;
    const int wm = (w & 1) * 64, wn = (w >> 1) * 32;

    const __half* planes[3] = { g_x      + (size_t)m0 * 1024,
                                g_wqk_hi + (size_t)n0 * 1024,
                                g_wqk_lo + (size_t)n0 * 1024 };

    auto issue_stage = [&](int s) {
        const uint32_t sbuf = sbase + (uint32_t)(s % 3) * G_STAGE;
        #pragma unroll
        for (int i = 0; i < 6; i++) {
            const int u = tid + 256 * i;
            const int plane = u >> 9, rem = u & 511;
            const int row = rem >> 2, cell = rem & 3;
            const uint32_t csw = (uint32_t)(cell ^ ((row >> 1) & 3));
            cp_async16(sbuf + (uint32_t)plane * 8192u + (uint32_t)row * 64u + csw * 16u,
                       planes[plane] + (size_t)row * 1024 + s * 32 + cell * 8);
        }
        cp_commit();
    };

    const int a_r = lane & 15, a_k8 = lane >> 4;
    const int b_r = (lane & 7) + ((lane >> 4) & 1) * 8, b_k8 = (lane >> 3) & 1;

    issue_stage(0);
    issue_stage(1);

    float acc[4][4][4] = {};

    for (int s = 0; s < 32; s++) {
        cp_wait<1>();
        __syncthreads();
        if (s + 2 < 32) issue_stage(s + 2);
        else cp_commit();

        const uint32_t bo = sbase + (uint32_t)(s % 3) * G_STAGE;

        #pragma unroll
        for (int hk = 0; hk < 2; hk++) {
            uint32_t bf[2][2][4];
            #pragma unroll
            for (int g = 0; g < 2; g++) {
                const int row = wn + g * 16 + b_r;
                const uint32_t csw = (uint32_t)((hk * 2 + b_k8) ^ ((row >> 1) & 3));
                const uint32_t ad = bo + 8192u + (uint32_t)row * 64u + csw * 16u;
                ldsm4(ad,         bf[0][g][0], bf[0][g][1], bf[0][g][2], bf[0][g][3]);
                ldsm4(ad + 8192u, bf[1][g][0], bf[1][g][1], bf[1][g][2], bf[1][g][3]);
            }
            uint32_t ah[2][4];
            auto lda = [&](int i, int b) {
                const int row = wm + i * 16 + a_r;
                const uint32_t csw = (uint32_t)((hk * 2 + a_k8) ^ ((row >> 1) & 3));
                ldsm4(bo + (uint32_t)row * 64u + csw * 16u,
                      ah[b][0], ah[b][1], ah[b][2], ah[b][3]);
            };
            lda(0, 0);
            #pragma unroll
            for (int i = 0; i < 4; i++) {
                if (i < 3) lda(i + 1, (i + 1) & 1);
                const int cb = i & 1;
                #pragma unroll
                for (int jn = 0; jn < 4; jn++) {
                    const int g = jn >> 1, h2 = (jn & 1) * 2;
                    mma16816(acc[i][jn], ah[cb], bf[0][g][h2], bf[0][g][h2+1]);
                }
                #pragma unroll
                for (int jn = 0; jn < 4; jn++) {
                    const int g = jn >> 1, h2 = (jn & 1) * 2;
                    mma16816(acc[i][jn], ah[cb], bf[1][g][h2], bf[1][g][h2+1]);
                }
            }
        }
    }

    #pragma unroll
    for (int i = 0; i < 4; i++) {
        const int row0 = m0 + wm + i*16 + gid;
        #pragma unroll
        for (int jn = 0; jn < 4; jn++) {
            const int col = n0 + wn + jn*8 + tig*2;
            #pragma unroll
            for (int r = 0; r < 4; r++) {
                const int rr = row0 + ((r >= 2) ? 8 : 0), cc = col + (r & 1);
                float v = acc[i][jn][r];
                const int bb = rr >> 11, nn = rr & 2047;
                if (cc < 1024) {        // q: pre-scale, single fp16
                    const int h = cc >> 6, d = cc & 63;
                    g_q[((size_t)(bb*16 + h)*2048 + nn)*64 + d] = __float2half_rn(v * 0.125f);
                } else {                // k
                    const int c2 = cc - 1024, h = c2 >> 6, d = c2 & 63;
                    g_k[((size_t)(bb*16 + h)*2048 + nn)*64 + d] = __float2half_rn(v);
                }
            }
        }
    }
}

// =====================================================================
// 1-term GEMM (single fp16 both sides). mode 0: v = x@Wv^T (scatter v
// transposed). mode 1: out = att@Wp^T (fp32 out). 2-plane stages.
// =====================================================================
constexpr uint32_t G1_STAGE = 2u * 128u * 64u;   // 16384 bytes
constexpr int G1_SMEM = 3 * (int)G1_STAGE;       // 49152

__global__ __launch_bounds__(256, 2) void gemm1(float* __restrict__ Cout, int mode)
{
    extern __shared__ __align__(16) char dynsm[];
    const uint32_t sbase = (uint32_t)__cvta_generic_to_shared(dynsm);

    const __half* Ax = mode ? g_att : g_x;
    const __half* Bw = mode ? g_wp  : g_wv;

    const int m0 = blockIdx.y * 128, n0 = blockIdx.x * 128;
    const int tid = threadIdx.x, w = tid >> 5, lane = tid & 31;
    const int gid = lane >> 2, tig = lane & 3;
    const int wm = (w & 1) * 64, wn = (w >> 1) * 32;

    const __half* planes[2] = { Ax + (size_t)m0 * 1024, Bw + (size_t)n0 * 1024 };

    auto issue_stage = [&](int s) {
        const uint32_t sbuf = sbase + (uint32_t)(s % 3) * G1_STAGE;
        #pragma unroll
        for (int i = 0; i < 4; i++) {
            const int u = tid + 256 * i;
            const int plane = u >> 9, rem = u & 511;
            const int row = rem >> 2, cell = rem & 3;
            const uint32_t csw = (uint32_t)(cell ^ ((row >> 1) & 3));
            cp_async16(sbuf + (uint32_t)plane * 8192u + (uint32_t)row * 64u + csw * 16u,
                       planes[plane] + (size_t)row * 1024 + s * 32 + cell * 8);
        }
        cp_commit();
    };

    const int a_r = lane & 15, a_k8 = lane >> 4;
    const int b_r = (lane & 7) + ((lane >> 4) & 1) * 8, b_k8 = (lane >> 3) & 1;

    issue_stage(0);
    issue_stage(1);

    float acc[4][4][4] = {};

    for (int s = 0; s < 32; s++) {
        cp_wait<1>();
        __syncthreads();
        if (s + 2 < 32) issue_stage(s + 2);
        else cp_commit();

        const uint32_t bo = sbase + (uint32_t)(s % 3) * G1_STAGE;

        #pragma unroll
        for (int hk = 0; hk < 2; hk++) {
            uint32_t bf[2][4];
            #pragma unroll
            for (int g = 0; g < 2; g++) {
                const int row = wn + g * 16 + b_r;
                const uint32_t csw = (uint32_t)((hk * 2 + b_k8) ^ ((row >> 1) & 3));
                ldsm4(bo + 8192u + (uint32_t)row * 64u + csw * 16u,
                      bf[g][0], bf[g][1], bf[g][2], bf[g][3]);
            }
            uint32_t ah[2][4];
            auto lda = [&](int i, int b) {
                const int row = wm + i * 16 + a_r;
                const uint32_t csw = (uint32_t)((hk * 2 + a_k8) ^ ((row >> 1) & 3));
                ldsm4(bo + (uint32_t)row * 64u + csw * 16u,
                      ah[b][0], ah[b][1], ah[b][2], ah[b][3]);
            };
            lda(0, 0);
            #pragma unroll
            for (int i = 0; i < 4; i++) {
                if (i < 3) lda(i + 1, (i + 1) & 1);
                const int cb = i & 1;
                #pragma unroll
                for (int jn = 0; jn < 4; jn++) {
                    const int g = jn >> 1, h2 = (jn & 1) * 2;
                    mma16816(acc[i][jn], ah[cb], bf[g][h2], bf[g][h2+1]);
                }
            }
        }
    }

    #pragma unroll
    for (int i = 0; i < 4; i++) {
        const int row0 = m0 + wm + i*16 + gid;
        #pragma unroll
        for (int jn = 0; jn < 4; jn++) {
            const int col = n0 + wn + jn*8 + tig*2;
            if (mode == 1) {
                *(float2*)&Cout[(size_t)row0*1024 + col]     = make_float2(acc[i][jn][0], acc[i][jn][1]);
                *(float2*)&Cout[(size_t)(row0+8)*1024 + col] = make_float2(acc[i][jn][2], acc[i][jn][3]);
            } else {
                #pragma unroll
                for (int r = 0; r < 4; r++) {
                    const int rr = row0 + ((r >= 2) ? 8 : 0), cc = col + (r & 1);
                    const int bb = rr >> 11, nn = rr & 2047;
                    const int h = cc >> 6, d = cc & 63;
                    g_v[((size_t)(bb*16 + h)*64 + d)*2048 + nn] = __float2half_rn(acc[i][jn][r]);
                }
            }
        }
    }
}

// =====================================================================
// fp16 causal flash attention: single-fp16 Q, K, V, P (1-term QK and PV).
// Paired k-tiles per cp.async stage; one barrier per 2 k-tiles.
// smem: Q 16KB + 2 stages x 32KB = 80KB.
// =====================================================================
constexpr int ATTN_SMEM = 81920;

__global__ __launch_bounds__(256, 2) void attn_mma()
{
    extern __shared__ __align__(16) __half dsm[];

    const int qt = (int)gridDim.x - 1 - (int)blockIdx.x;
    const int bh = blockIdx.y, bb = bh >> 4, hh = bh & 15;
    const size_t base = (size_t)bh * (2048*64);
    const int tid = threadIdx.x, w = tid >> 5, lane = tid & 31;
    const int gid = lane >> 2, tig = lane & 3;
    const uint32_t sbase = (uint32_t)__cvta_generic_to_shared(dsm);
    const int a_r = lane & 15, a_k8 = lane >> 4;
    const int b_r = (lane & 7) + ((lane >> 4) & 1) * 8, b_k8 = (lane >> 3) & 1;

    auto issue_kv = [&](int st) {
        const uint32_t sbuf = sbase + 16384u + (uint32_t)(st & 1) * 32768u;
        #pragma unroll
        for (int i = 0; i < 8; i++) {
            const int u = tid + 256 * i;
            if ((u >> 10) == 0) {
                const int rem = u & 1023;
                const int row = rem >> 3, c16 = rem & 7;
                cp_async16(sbuf + (uint32_t)row * 128u + (uint32_t)((c16 ^ (row & 7)) * 16),
                           g_k + base + (size_t)(st * 128 + row) * 64 + c16 * 8);
            } else {
                const int rem = u & 1023;
                const int sub = rem >> 9, rem2 = rem & 511;
                const int row = rem2 >> 3, c16 = rem2 & 7;
                cp_async16(sbuf + 16384u + (uint32_t)sub * 8192u
                               + (uint32_t)row * 128u + (uint32_t)((c16 ^ (row & 7)) * 16),
                           g_v + base + (size_t)row * 2048 + (size_t)(st * 128 + sub * 64) + c16 * 8);
            }
        }
        cp_commit();
    };

    // load Q tile (128 x 64), single plane
    #pragma unroll
    for (int it = 0; it < 4; it++) {
        const int u = tid + 256*it, r = u >> 3, c16 = u & 7;
        const int so = r*64 + ((c16 ^ (r & 7))*8);
        *(uint4*)&dsm[so] = *(const uint4*)(g_q + base + (size_t)(qt*128 + r)*64 + c16*8);
    }

    float s[8][4], o[8][4] = {};
    float mr0 = -1e30f, mr1 = -1e30f, lr0 = 0.f, lr1 = 0.f;
    const int row0g = qt*128 + w*16 + gid, row1g = row0g + 8;
    const int nstages = qt + 1;

    issue_kv(0);

    for (int st = 0; st < nstages; st++) {
        cp_wait<0>();
        __syncthreads();
        if (st + 1 < nstages) issue_kv(st + 1);

        const int kbase_e = 8192 + (st & 1) * 16384;

        #pragma unroll
        for (int sub = 0; sub < 2; sub++) {
            const int kt = st * 2 + sub;
            const int koff = kbase_e + sub * 4096;
            const int voff = kbase_e + 8192 + sub * 4096;

            #pragma unroll
            for (int j = 0; j < 8; j++)
                #pragma unroll
                for (int r = 0; r < 4; r++) s[j][r] = 0.f;
            #pragma unroll
            for (int kk = 0; kk < 4; kk++) {
                uint32_t aq[4];
                {
                    const int r = w*16 + a_r, c16 = kk*2 + a_k8;
                    const int so = r*64 + ((c16 ^ (r & 7))*8);
                    ldsm4(sbase + (uint32_t)so*2, aq[0], aq[1], aq[2], aq[3]);
                }
                uint32_t bk[4][4];
                #pragma unroll
                for (int g = 0; g < 4; g++) {
                    const int r = g*16 + b_r, c16 = kk*2 + b_k8;
                    const int so = r*64 + ((c16 ^ (r & 7))*8);
                    ldsm4(sbase + (uint32_t)(koff + so)*2, bk[g][0], bk[g][1], bk[g][2], bk[g][3]);
                }
                #pragma unroll
                for (int j8 = 0; j8 < 8; j8++) {
                    const int g = j8 >> 1, h = (j8 & 1)*2;
                    mma16816(s[j8], aq, bk[g][h], bk[g][h+1]);
                }
            }

            if (kt >= 2*qt) {
                #pragma unroll
                for (int j8 = 0; j8 < 8; j8++) {
                    const int c = kt*64 + j8*8 + tig*2;
                    if (c > row0g)   s[j8][0] = -1e30f;
                    if (c+1 > row0g) s[j8][1] = -1e30f;
                    if (c > row1g)   s[j8][2] = -1e30f;
                    if (c+1 > row1g) s[j8][3] = -1e30f;
                }
            }

            float mx0 = -1e30f, mx1 = -1e30f;
            #pragma unroll
            for (int j8 = 0; j8 < 8; j8++) {
                mx0 = fmaxf(mx0, fmaxf(s[j8][0], s[j8][1]));
                mx1 = fmaxf(mx1, fmaxf(s[j8][2], s[j8][3]));
            }
            mx0 = fmaxf(mx0, __shfl_xor_sync(~0u, mx0, 1)); mx0 = fmaxf(mx0, __shfl_xor_sync(~0u, mx0, 2));
            mx1 = fmaxf(mx1, __shfl_xor_sync(~0u, mx1, 1)); mx1 = fmaxf(mx1, __shfl_xor_sync(~0u, mx1, 2));
            const float mn0 = fmaxf(mr0, mx0), mn1 = fmaxf(mr1, mx1);
            const float f0 = __expf(mr0 - mn0), f1 = __expf(mr1 - mn1);
            mr0 = mn0; mr1 = mn1;
            float s0 = 0.f, s1 = 0.f;
            #pragma unroll
            for (int j8 = 0; j8 < 8; j8++) {
                s[j8][0] = __expf(s[j8][0] - mn0); s[j8][1] = __expf(s[j8][1] - mn0);
                s[j8][2] = __expf(s[j8][2] - mn1); s[j8][3] = __expf(s[j8][3] - mn1);
                s0 += s[j8][0] + s[j8][1]; s1 += s[j8][2] + s[j8][3];
            }
            s0 += __shfl_xor_sync(~0u, s0, 1); s0 += __shfl_xor_sync(~0u, s0, 2);
            s1 += __shfl_xor_sync(~0u, s1, 1); s1 += __shfl_xor_sync(~0u, s1, 2);
            lr0 = lr0*f0 + s0; lr1 = lr1*f1 + s1;
            #pragma unroll
            for (int j8 = 0; j8 < 8; j8++) {
                o[j8][0] *= f0; o[j8][1] *= f0; o[j8][2] *= f1; o[j8][3] *= f1;
            }

            #pragma unroll
            for (int kk = 0; kk < 4; kk++) {
                uint32_t ap[4];
                ap[0] = pack2h(s[2*kk][0],   s[2*kk][1]);
                ap[1] = pack2h(s[2*kk][2],   s[2*kk][3]);
                ap[2] = pack2h(s[2*kk+1][0], s[2*kk+1][1]);
                ap[3] = pack2h(s[2*kk+1][2], s[2*kk+1][3]);
                uint32_t bv[4][4];
                #pragma unroll
                for (int g = 0; g < 4; g++) {
                    const int r = g*16 + b_r, c16 = kk*2 + b_k8;
                    const int so = r*64 + ((c16 ^ (r & 7))*8);
                    ldsm4(sbase + (uint32_t)(voff + so)*2, bv[g][0], bv[g][1], bv[g][2], bv[g][3]);
                }
                #pragma unroll
                for (int j8 = 0; j8 < 8; j8++) {
                    const int g = j8 >> 1, h = (j8 & 1)*2;
                    mma16816(o[j8], ap, bv[g][h], bv[g][h+1]);
                }
            }
        }
    }

    const float i0 = 1.f / lr0, i1 = 1.f / lr1;
    #pragma unroll
    for (int j8 = 0; j8 < 8; j8++) {
        const int col = hh*64 + j8*8 + tig*2;
        size_t ob = ((size_t)bb*2048 + row0g) * DM + col;
        *(uint32_t*)&g_att[ob] = pack2h(o[j8][0]*i0, o[j8][1]*i0);
        ob = ((size_t)bb*2048 + row1g) * DM + col;
        *(uint32_t*)&g_att[ob] = pack2h(o[j8][2]*i1, o[j8][3]*i1);
    }
}

extern "C" void kernel_launch(void* const* d_in, const int* in_sizes, int n_in,
                              void* d_out, int out_size)
{
    (void)in_sizes; (void)n_in; (void)out_size;
    const float* x      = (const float*)d_in[0];
    const float* w_qkv  = (const float*)d_in[1];
    const float* w_proj = (const float*)d_in[2];
    float* out = (float*)d_out;

    static bool attr_done = false;
    if (!attr_done) {
        cudaFuncSetAttribute(attn_mma, cudaFuncAttributeMaxDynamicSharedMemorySize, ATTN_SMEM);
        cudaFuncSetAttribute(gemm2_qk, cudaFuncAttributeMaxDynamicSharedMemorySize, GEMM_SMEM);
        cudaFuncSetAttribute(gemm1,    cudaFuncAttributeMaxDynamicSharedMemorySize, G1_SMEM);
        attr_done = true;
    }

    round_x_kernel<<<MROWS*DM/256, 256>>>(x);
    split_wqkv_kernel<<<dim3(96, 32), 256>>>(w_qkv);
    round_wp_kernel<<<dim3(32, 32), 256>>>(w_proj);
    gemm2_qk<<<dim3(16, 32), 256, GEMM_SMEM>>>();          // q + k (2-term W)
    gemm1<<<dim3(8, 32), 256, G1_SMEM>>>(nullptr, 0);      // v (1-term)
    attn_mma<<<dim3(16, 32), 256, ATTN_SMEM>>>();
    gemm1<<<dim3(8, 32), 256, G1_SMEM>>>(out, 1);          // proj (1-term)
}

// round 14
// speedup vs baseline: 2.2824x; 1.1160x over previous
#include <cuda_runtime.h>
#include <cuda_fp16.h>
#include <cstdint>

constexpr int BATCH = 2, NSEQ = 2048, DM = 1024, NH = 16, DH = 64;
constexpr int MROWS = BATCH * NSEQ;

__device__ __align__(16) __half g_x[MROWS*DM];
__device__ __align__(16) __half g_wqk_hi[2*DM*DM], g_wqk_lo[2*DM*DM];  // [2048][1024]: 0..1023 Wq, 1024..2047 Wk
__device__ __align__(16) __half g_wv[DM*DM];                            // [1024][1024] single
__device__ __align__(16) __half g_wp[DM*DM];                            // [1024][1024] single
__device__ __align__(16) __half g_q[MROWS*NH*DH];                       // [bh][n][d] (pre-scaled, single)
__device__ __align__(16) __half g_k[MROWS*NH*DH];                       // [bh][n][d]
__device__ __align__(16) __half g_v[MROWS*NH*DH];                       // [bh][d][n] (transposed)
__device__ __align__(16) __half g_att[MROWS*DM];                        // [4096][1024]

// ---------------- helpers ----------------
__device__ __forceinline__ void ldsm4(uint32_t a, uint32_t& r0, uint32_t& r1, uint32_t& r2, uint32_t& r3) {
    asm volatile("ldmatrix.sync.aligned.m8n8.x4.shared.b16 {%0,%1,%2,%3}, [%4];\n"
                 : "=r"(r0), "=r"(r1), "=r"(r2), "=r"(r3) : "r"(a));
}
__device__ __forceinline__ void mma16816(float* c, const uint32_t* a, uint32_t b0, uint32_t b1) {
    asm volatile("mma.sync.aligned.m16n8k16.row.col.f32.f16.f16.f32 "
                 "{%0,%1,%2,%3}, {%4,%5,%6,%7}, {%8,%9}, {%0,%1,%2,%3};\n"
                 : "+f"(c[0]), "+f"(c[1]), "+f"(c[2]), "+f"(c[3])
                 : "r"(a[0]), "r"(a[1]), "r"(a[2]), "r"(a[3]), "r"(b0), "r"(b1));
}
__device__ __forceinline__ uint32_t pack2h(float a, float b) {
    __half2 h2 = __halves2half2(__float2half_rn(a), __float2half_rn(b));
    return *(uint32_t*)&h2;
}
__device__ __forceinline__ void cp_async16(uint32_t dst, const void* src) {
    asm volatile("cp.async.cg.shared.global [%0], [%1], 16;\n" :: "r"(dst), "l"(src) : "memory");
}
__device__ __forceinline__ void cp_commit() { asm volatile("cp.async.commit_group;\n" ::: "memory"); }
template<int N> __device__ __forceinline__ void cp_wait() {
    asm volatile("cp.async.wait_group %0;\n" :: "n"(N) : "memory");
}

// =====================================================================
// Fused prep: blocks 0..3071 split w_qkv, 3072..4095 round w_proj,
// 4096..6143 round x (8 floats/thread, vectorized).
// =====================================================================
__global__ void prep_kernel(const float* __restrict__ x,
                            const float* __restrict__ wqkv,
                            const float* __restrict__ wp)
{
    __shared__ float t[32][33];
    const int bid = blockIdx.x;
    const int tx = threadIdx.x & 31, ty0 = threadIdx.x >> 5;

    if (bid < 3072) {
        // w_qkv [1024][3072] -> de-interleave + transpose: Wqk split, Wv single
        const int n0 = (bid % 96) * 32, k0 = (bid / 96) * 32;
        for (int ty = ty0; ty < 32; ty += 8) t[ty][tx] = wqkv[(size_t)(k0+ty)*3072 + n0 + tx];
        __syncthreads();
        for (int ty = ty0; ty < 32; ty += 8) {
            const int n = n0 + ty, k = k0 + tx;
            const float v = t[tx][ty];
            const int which = n % 3, hd = n / 3;
            if (which == 2) {
                g_wv[(size_t)hd * 1024 + k] = __float2half_rn(v);
            } else {
                const int row = which * 1024 + hd;
                __half h = __float2half_rn(v);
                const size_t o = (size_t)row * 1024 + k;
                g_wqk_hi[o] = h;
                g_wqk_lo[o] = __float2half_rn(v - __half2float(h));
            }
        }
    } else if (bid < 4096) {
        // w_proj [1024][1024] -> transpose, single fp16
        const int b2 = bid - 3072;
        const int n0 = (b2 & 31) * 32, k0 = (b2 >> 5) * 32;
        for (int ty = ty0; ty < 32; ty += 8) t[ty][tx] = wp[(size_t)(k0+ty)*1024 + n0 + tx];
        __syncthreads();
        for (int ty = ty0; ty < 32; ty += 8)
            g_wp[(size_t)(n0+ty)*1024 + k0 + tx] = __float2half_rn(t[tx][ty]);
    } else {
        // x: 4M floats; 2048 blocks x 256 thr x 8 elems
        const size_t idx = ((size_t)(bid - 4096) * 256 + threadIdx.x) * 8;
        const float4 a = *(const float4*)(x + idx);
        const float4 b = *(const float4*)(x + idx + 4);
        uint32_t r[4];
        r[0] = pack2h(a.x, a.y); r[1] = pack2h(a.z, a.w);
        r[2] = pack2h(b.x, b.y); r[3] = pack2h(b.z, b.w);
        *(uint4*)(g_x + idx) = *(uint4*)r;
    }
}

// =====================================================================
// Fused QKV GEMM, 768 linear blocks:
//   bid 0..511  : qk = x @ (Wqk_hi+Wqk_lo)^T  (2-term, scatter q/k)
//   bid 512..767: v  = x @ Wv^T               (1-term, scatter v transposed)
// BK=32, 3-stage ring, 24KB stages, 2 CTA/SM.
// =====================================================================
constexpr uint32_t G_STAGE = 3u * 128u * 64u;    // 24576 bytes
constexpr int GEMM_SMEM = 3 * (int)G_STAGE;      // 73728

__global__ __launch_bounds__(256, 2) void gemm_qkv()
{
    extern __shared__ __align__(16) char dynsm[];
    const uint32_t sbase = (uint32_t)__cvta_generic_to_shared(dynsm);

    const int bid = blockIdx.x;
    const bool qkpart = (bid < 512);

    const int tid = threadIdx.x, w = tid >> 5, lane = tid & 31;
    const int gid = lane >> 2, tig = lane & 3;
    const int wm = (w & 1) * 64, wn = (w >> 1) * 32;
    const int a_r = lane & 15, a_k8 = lane >> 4;
    const int b_r = (lane & 7) + ((lane >> 4) & 1) * 8, b_k8 = (lane >> 3) & 1;

    if (qkpart) {
        const int m0 = (bid >> 4) * 128, n0 = (bid & 15) * 128;
        const __half* planes[3] = { g_x      + (size_t)m0 * 1024,
                                    g_wqk_hi + (size_t)n0 * 1024,
                                    g_wqk_lo + (size_t)n0 * 1024 };
        auto issue_stage = [&](int s) {
            const uint32_t sbuf = sbase + (uint32_t)(s % 3) * G_STAGE;
            #pragma unroll
            for (int i = 0; i < 6; i++) {
                const int u = tid + 256 * i;
                const int plane = u >> 9, rem = u & 511;
                const int row = rem >> 2, cell = rem & 3;
                const uint32_t csw = (uint32_t)(cell ^ ((row >> 1) & 3));
                cp_async16(sbuf + (uint32_t)plane * 8192u + (uint32_t)row * 64u + csw * 16u,
                           planes[plane] + (size_t)row * 1024 + s * 32 + cell * 8);
            }
            cp_commit();
        };

        issue_stage(0);
        issue_stage(1);

        float acc[4][4][4] = {};
        for (int s = 0; s < 32; s++) {
            cp_wait<1>();
            __syncthreads();
            if (s + 2 < 32) issue_stage(s + 2);
            else cp_commit();
            const uint32_t bo = sbase + (uint32_t)(s % 3) * G_STAGE;
            #pragma unroll
            for (int hk = 0; hk < 2; hk++) {
                uint32_t bf[2][2][4];
                #pragma unroll
                for (int g = 0; g < 2; g++) {
                    const int row = wn + g * 16 + b_r;
                    const uint32_t csw = (uint32_t)((hk * 2 + b_k8) ^ ((row >> 1) & 3));
                    const uint32_t ad = bo + 8192u + (uint32_t)row * 64u + csw * 16u;
                    ldsm4(ad,         bf[0][g][0], bf[0][g][1], bf[0][g][2], bf[0][g][3]);
                    ldsm4(ad + 8192u, bf[1][g][0], bf[1][g][1], bf[1][g][2], bf[1][g][3]);
                }
                uint32_t ah[2][4];
                auto lda = [&](int i, int b) {
                    const int row = wm + i * 16 + a_r;
                    const uint32_t csw = (uint32_t)((hk * 2 + a_k8) ^ ((row >> 1) & 3));
                    ldsm4(bo + (uint32_t)row * 64u + csw * 16u,
                          ah[b][0], ah[b][1], ah[b][2], ah[b][3]);
                };
                lda(0, 0);
                #pragma unroll
                for (int i = 0; i < 4; i++) {
                    if (i < 3) lda(i + 1, (i + 1) & 1);
                    const int cb = i & 1;
                    #pragma unroll
                    for (int jn = 0; jn < 4; jn++) {
                        const int g = jn >> 1, h2 = (jn & 1) * 2;
                        mma16816(acc[i][jn], ah[cb], bf[0][g][h2], bf[0][g][h2+1]);
                    }
                    #pragma unroll
                    for (int jn = 0; jn < 4; jn++) {
                        const int g = jn >> 1, h2 = (jn & 1) * 2;
                        mma16816(acc[i][jn], ah[cb], bf[1][g][h2], bf[1][g][h2+1]);
                    }
                }
            }
        }

        #pragma unroll
        for (int i = 0; i < 4; i++) {
            const int row0 = m0 + wm + i*16 + gid;
            #pragma unroll
            for (int jn = 0; jn < 4; jn++) {
                const int col = n0 + wn + jn*8 + tig*2;
                #pragma unroll
                for (int r = 0; r < 4; r++) {
                    const int rr = row0 + ((r >= 2) ? 8 : 0), cc = col + (r & 1);
                    float v = acc[i][jn][r];
                    const int bb = rr >> 11, nn = rr & 2047;
                    if (cc < 1024) {
                        const int h = cc >> 6, d = cc & 63;
                        g_q[((size_t)(bb*16 + h)*2048 + nn)*64 + d] = __float2half_rn(v * 0.125f);
                    } else {
                        const int c2 = cc - 1024, h = c2 >> 6, d = c2 & 63;
                        g_k[((size_t)(bb*16 + h)*2048 + nn)*64 + d] = __float2half_rn(v);
                    }
                }
            }
        }
    } else {
        const int b2 = bid - 512;
        const int m0 = (b2 >> 3) * 128, n0 = (b2 & 7) * 128;
        const __half* planes[2] = { g_x  + (size_t)m0 * 1024,
                                    g_wv + (size_t)n0 * 1024 };
        auto issue_stage = [&](int s) {
            const uint32_t sbuf = sbase + (uint32_t)(s % 3) * G_STAGE;
            #pragma unroll
            for (int i = 0; i < 4; i++) {
                const int u = tid + 256 * i;
                const int plane = u >> 9, rem = u & 511;
                const int row = rem >> 2, cell = rem & 3;
                const uint32_t csw = (uint32_t)(cell ^ ((row >> 1) & 3));
                cp_async16(sbuf + (uint32_t)plane * 8192u + (uint32_t)row * 64u + csw * 16u,
                           planes[plane] + (size_t)row * 1024 + s * 32 + cell * 8);
            }
            cp_commit();
        };

        issue_stage(0);
        issue_stage(1);

        float acc[4][4][4] = {};
        for (int s = 0; s < 32; s++) {
            cp_wait<1>();
            __syncthreads();
            if (s + 2 < 32) issue_stage(s + 2);
            else cp_commit();
            const uint32_t bo = sbase + (uint32_t)(s % 3) * G_STAGE;
            #pragma unroll
            for (int hk = 0; hk < 2; hk++) {
                uint32_t bf[2][4];
                #pragma unroll
                for (int g = 0; g < 2; g++) {
                    const int row = wn + g * 16 + b_r;
                    const uint32_t csw = (uint32_t)((hk * 2 + b_k8) ^ ((row >> 1) & 3));
                    ldsm4(bo + 8192u + (uint32_t)row * 64u + csw * 16u,
                          bf[g][0], bf[g][1], bf[g][2], bf[g][3]);
                }
                uint32_t ah[2][4];
                auto lda = [&](int i, int b) {
                    const int row = wm + i * 16 + a_r;
                    const uint32_t csw = (uint32_t)((hk * 2 + a_k8) ^ ((row >> 1) & 3));
                    ldsm4(bo + (uint32_t)row * 64u + csw * 16u,
                          ah[b][0], ah[b][1], ah[b][2], ah[b][3]);
                };
                lda(0, 0);
                #pragma unroll
                for (int i = 0; i < 4; i++) {
                    if (i < 3) lda(i + 1, (i + 1) & 1);
                    const int cb = i & 1;
                    #pragma unroll
                    for (int jn = 0; jn < 4; jn++) {
                        const int g = jn >> 1, h2 = (jn & 1) * 2;
                        mma16816(acc[i][jn], ah[cb], bf[g][h2], bf[g][h2+1]);
                    }
                }
            }
        }

        #pragma unroll
        for (int i = 0; i < 4; i++) {
            const int row0 = m0 + wm + i*16 + gid;
            #pragma unroll
            for (int jn = 0; jn < 4; jn++) {
                const int col = n0 + wn + jn*8 + tig*2;
                #pragma unroll
                for (int r = 0; r < 4; r++) {
                    const int rr = row0 + ((r >= 2) ? 8 : 0), cc = col + (r & 1);
                    const int bb = rr >> 11, nn = rr & 2047;
                    const int h = cc >> 6, d = cc & 63;
                    g_v[((size_t)(bb*16 + h)*64 + d)*2048 + nn] = __float2half_rn(acc[i][jn][r]);
                }
            }
        }
    }
}

// =====================================================================
// Proj GEMM: out = att @ Wp^T (1-term, fp32 out). 2-plane stages.
// =====================================================================
constexpr uint32_t G1_STAGE = 2u * 128u * 64u;   // 16384 bytes
constexpr int G1_SMEM = 3 * (int)G1_STAGE;       // 49152

__global__ __launch_bounds__(256, 2) void gemm_proj(float* __restrict__ Cout)
{
    extern __shared__ __align__(16) char dynsm[];
    const uint32_t sbase = (uint32_t)__cvta_generic_to_shared(dynsm);

    const int m0 = blockIdx.y * 128, n0 = blockIdx.x * 128;
    const int tid = threadIdx.x, w = tid >> 5, lane = tid & 31;
    const int gid = lane >> 2, tig = lane & 3;
    const int wm = (w & 1) * 64, wn = (w >> 1) * 32;

    const __half* planes[2] = { g_att + (size_t)m0 * 1024, g_wp + (size_t)n0 * 1024 };

    auto issue_stage = [&](int s) {
        const uint32_t sbuf = sbase + (uint32_t)(s % 3) * G1_STAGE;
        #pragma unroll
        for (int i = 0; i < 4; i++) {
            const int u = tid + 256 * i;
            const int plane = u >> 9, rem = u & 511;
            const int row = rem >> 2, cell = rem & 3;
            const uint32_t csw = (uint32_t)(cell ^ ((row >> 1) & 3));
            cp_async16(sbuf + (uint32_t)plane * 8192u + (uint32_t)row * 64u + csw * 16u,
                       planes[plane] + (size_t)row * 1024 + s * 32 + cell * 8);
        }
        cp_commit();
    };

    const int a_r = lane & 15, a_k8 = lane >> 4;
    const int b_r = (lane & 7) + ((lane >> 4) & 1) * 8, b_k8 = (lane >> 3) & 1;

    issue_stage(0);
    issue_stage(1);

    float acc[4][4][4] = {};

    for (int s = 0; s < 32; s++) {
        cp_wait<1>();
        __syncthreads();
        if (s + 2 < 32) issue_stage(s + 2);
        else cp_commit();

        const uint32_t bo = sbase + (uint32_t)(s % 3) * G1_STAGE;

        #pragma unroll
        for (int hk = 0; hk < 2; hk++) {
            uint32_t bf[2][4];
            #pragma unroll
            for (int g = 0; g < 2; g++) {
                const int row = wn + g * 16 + b_r;
                const uint32_t csw = (uint32_t)((hk * 2 + b_k8) ^ ((row >> 1) & 3));
                ldsm4(bo + 8192u + (uint32_t)row * 64u + csw * 16u,
                      bf[g][0], bf[g][1], bf[g][2], bf[g][3]);
            }
            uint32_t ah[2][4];
            auto lda = [&](int i, int b) {
                const int row = wm + i * 16 + a_r;
                const uint32_t csw = (uint32_t)((hk * 2 + a_k8) ^ ((row >> 1) & 3));
                ldsm4(bo + (uint32_t)row * 64u + csw * 16u,
                      ah[b][0], ah[b][1], ah[b][2], ah[b][3]);
            };
            lda(0, 0);
            #pragma unroll
            for (int i = 0; i < 4; i++) {
                if (i < 3) lda(i + 1, (i + 1) & 1);
                const int cb = i & 1;
                #pragma unroll
                for (int jn = 0; jn < 4; jn++) {
                    const int g = jn >> 1, h2 = (jn & 1) * 2;
                    mma16816(acc[i][jn], ah[cb], bf[g][h2], bf[g][h2+1]);
                }
            }
        }
    }

    #pragma unroll
    for (int i = 0; i < 4; i++) {
        const int row0 = m0 + wm + i*16 + gid;
        #pragma unroll
        for (int jn = 0; jn < 4; jn++) {
            const int col = n0 + wn + jn*8 + tig*2;
            *(float2*)&Cout[(size_t)row0*1024 + col]     = make_float2(acc[i][jn][0], acc[i][jn][1]);
            *(float2*)&Cout[(size_t)(row0+8)*1024 + col] = make_float2(acc[i][jn][2], acc[i][jn][3]);
        }
    }
}

// =====================================================================
// fp16 causal flash attention (unchanged from R13): single-fp16 Q,K,V,P.
// Paired k-tiles per cp.async stage; one barrier per 2 k-tiles.
// smem: Q 16KB + 2 stages x 32KB = 80KB.
// =====================================================================
constexpr int ATTN_SMEM = 81920;

__global__ __launch_bounds__(256, 2) void attn_mma()
{
    extern __shared__ __align__(16) __half dsm[];

    const int qt = (int)gridDim.x - 1 - (int)blockIdx.x;
    const int bh = blockIdx.y, bb = bh >> 4, hh = bh & 15;
    const size_t base = (size_t)bh * (2048*64);
    const int tid = threadIdx.x, w = tid >> 5, lane = tid & 31;
    const int gid = lane >> 2, tig = lane & 3;
    const uint32_t sbase = (uint32_t)__cvta_generic_to_shared(dsm);
    const int a_r = lane & 15, a_k8 = lane >> 4;
    const int b_r = (lane & 7) + ((lane >> 4) & 1) * 8, b_k8 = (lane >> 3) & 1;

    auto issue_kv = [&](int st) {
        const uint32_t sbuf = sbase + 16384u + (uint32_t)(st & 1) * 32768u;
        #pragma unroll
        for (int i = 0; i < 8; i++) {
            const int u = tid + 256 * i;
            if ((u >> 10) == 0) {
                const int rem = u & 1023;
                const int row = rem >> 3, c16 = rem & 7;
                cp_async16(sbuf + (uint32_t)row * 128u + (uint32_t)((c16 ^ (row & 7)) * 16),
                           g_k + base + (size_t)(st * 128 + row) * 64 + c16 * 8);
            } else {
                const int rem = u & 1023;
                const int sub = rem >> 9, rem2 = rem & 511;
                const int row = rem2 >> 3, c16 = rem2 & 7;
                cp_async16(sbuf + 16384u + (uint32_t)sub * 8192u
                               + (uint32_t)row * 128u + (uint32_t)((c16 ^ (row & 7)) * 16),
                           g_v + base + (size_t)row * 2048 + (size_t)(st * 128 + sub * 64) + c16 * 8);
            }
        }
        cp_commit();
    };

    #pragma unroll
    for (int it = 0; it < 4; it++) {
        const int u = tid + 256*it, r = u >> 3, c16 = u & 7;
        const int so = r*64 + ((c16 ^ (r & 7))*8);
        *(uint4*)&dsm[so] = *(const uint4*)(g_q + base + (size_t)(qt*128 + r)*64 + c16*8);
    }

    float s[8][4], o[8][4] = {};
    float mr0 = -1e30f, mr1 = -1e30f, lr0 = 0.f, lr1 = 0.f;
    const int row0g = qt*128 + w*16 + gid, row1g = row0g + 8;
    const int nstages = qt + 1;

    issue_kv(0);

    for (int st = 0; st < nstages; st++) {
        cp_wait<0>();
        __syncthreads();
        if (st + 1 < nstages) issue_kv(st + 1);

        const int kbase_e = 8192 + (st & 1) * 16384;

        #pragma unroll
        for (int sub = 0; sub < 2; sub++) {
            const int kt = st * 2 + sub;
            const int koff = kbase_e + sub * 4096;
            const int voff = kbase_e + 8192 + sub * 4096;

            #pragma unroll
            for (int j = 0; j < 8; j++)
                #pragma unroll
                for (int r = 0; r < 4; r++) s[j][r] = 0.f;
            #pragma unroll
            for (int kk = 0; kk < 4; kk++) {
                uint32_t aq[4];
                {
                    const int r = w*16 + a_r, c16 = kk*2 + a_k8;
                    const int so = r*64 + ((c16 ^ (r & 7))*8);
                    ldsm4(sbase + (uint32_t)so*2, aq[0], aq[1], aq[2], aq[3]);
                }
                uint32_t bk[4][4];
                #pragma unroll
                for (int g = 0; g < 4; g++) {
                    const int r = g*16 + b_r, c16 = kk*2 + b_k8;
                    const int so = r*64 + ((c16 ^ (r & 7))*8);
                    ldsm4(sbase + (uint32_t)(koff + so)*2, bk[g][0], bk[g][1], bk[g][2], bk[g][3]);
                }
                #pragma unroll
                for (int j8 = 0; j8 < 8; j8++) {
                    const int g = j8 >> 1, h = (j8 & 1)*2;
                    mma16816(s[j8], aq, bk[g][h], bk[g][h+1]);
                }
            }

            if (kt >= 2*qt) {
                #pragma unroll
                for (int j8 = 0; j8 < 8; j8++) {
                    const int c = kt*64 + j8*8 + tig*2;
                    if (c > row0g)   s[j8][0] = -1e30f;
                    if (c+1 > row0g) s[j8][1] = -1e30f;
                    if (c > row1g)   s[j8][2] = -1e30f;
                    if (c+1 > row1g) s[j8][3] = -1e30f;
                }
            }

            float mx0 = -1e30f, mx1 = -1e30f;
            #pragma unroll
            for (int j8 = 0; j8 < 8; j8++) {
                mx0 = fmaxf(mx0, fmaxf(s[j8][0], s[j8][1]));
                mx1 = fmaxf(mx1, fmaxf(s[j8][2], s[j8][3]));
            }
            mx0 = fmaxf(mx0, __shfl_xor_sync(~0u, mx0, 1)); mx0 = fmaxf(mx0, __shfl_xor_sync(~0u, mx0, 2));
            mx1 = fmaxf(mx1, __shfl_xor_sync(~0u, mx1, 1)); mx1 = fmaxf(mx1, __shfl_xor_sync(~0u, mx1, 2));
            const float mn0 = fmaxf(mr0, mx0), mn1 = fmaxf(mr1, mx1);
            const float f0 = __expf(mr0 - mn0), f1 = __expf(mr1 - mn1);
            mr0 = mn0; mr1 = mn1;
            float s0 = 0.f, s1 = 0.f;
            #pragma unroll
            for (int j8 = 0; j8 < 8; j8++) {
                s[j8][0] = __expf(s[j8][0] - mn0); s[j8][1] = __expf(s[j8][1] - mn0);
                s[j8][2] = __expf(s[j8][2] - mn1); s[j8][3] = __expf(s[j8][3] - mn1);
                s0 += s[j8][0] + s[j8][1]; s1 += s[j8][2] + s[j8][3];
            }
            s0 += __shfl_xor_sync(~0u, s0, 1); s0 += __shfl_xor_sync(~0u, s0, 2);
            s1 += __shfl_xor_sync(~0u, s1, 1); s1 += __shfl_xor_sync(~0u, s1, 2);
            lr0 = lr0*f0 + s0; lr1 = lr1*f1 + s1;
            #pragma unroll
            for (int j8 = 0; j8 < 8; j8++) {
                o[j8][0] *= f0; o[j8][1] *= f0; o[j8][2] *= f1; o[j8][3] *= f1;
            }

            #pragma unroll
            for (int kk = 0; kk < 4; kk++) {
                uint32_t ap[4];
                ap[0] = pack2h(s[2*kk][0],   s[2*kk][1]);
                ap[1] = pack2h(s[2*kk][2],   s[2*kk][3]);
                ap[2] = pack2h(s[2*kk+1][0], s[2*kk+1][1]);
                ap[3] = pack2h(s[2*kk+1][2], s[2*kk+1][3]);
                uint32_t bv[4][4];
                #pragma unroll
                for (int g = 0; g < 4; g++) {
                    const int r = g*16 + b_r, c16 = kk*2 + b_k8;
                    const int so = r*64 + ((c16 ^ (r & 7))*8);
                    ldsm4(sbase + (uint32_t)(voff + so)*2, bv[g][0], bv[g][1], bv[g][2], bv[g][3]);
                }
                #pragma unroll
                for (int j8 = 0; j8 < 8; j8++) {
                    const int g = j8 >> 1, h = (j8 & 1)*2;
                    mma16816(o[j8], ap, bv[g][h], bv[g][h+1]);
                }
            }
        }
    }

    const float i0 = 1.f / lr0, i1 = 1.f / lr1;
    #pragma unroll
    for (int j8 = 0; j8 < 8; j8++) {
        const int col = hh*64 + j8*8 + tig*2;
        size_t ob = ((size_t)bb*2048 + row0g) * DM + col;
        *(uint32_t*)&g_att[ob] = pack2h(o[j8][0]*i0, o[j8][1]*i0);
        ob = ((size_t)bb*2048 + row1g) * DM + col;
        *(uint32_t*)&g_att[ob] = pack2h(o[j8][2]*i1, o[j8][3]*i1);
    }
}

extern "C" void kernel_launch(void* const* d_in, const int* in_sizes, int n_in,
                              void* d_out, int out_size)
{
    (void)in_sizes; (void)n_in; (void)out_size;
    const float* x      = (const float*)d_in[0];
    const float* w_qkv  = (const float*)d_in[1];
    const float* w_proj = (const float*)d_in[2];
    float* out = (float*)d_out;

    static bool attr_done = false;
    if (!attr_done) {
        cudaFuncSetAttribute(attn_mma,  cudaFuncAttributeMaxDynamicSharedMemorySize, ATTN_SMEM);
        cudaFuncSetAttribute(gemm_qkv,  cudaFuncAttributeMaxDynamicSharedMemorySize, GEMM_SMEM);
        cudaFuncSetAttribute(gemm_proj, cudaFuncAttributeMaxDynamicSharedMemorySize, G1_SMEM);
        attr_done = true;
    }

    prep_kernel<<<6144, 256>>>(x, w_qkv, w_proj);
    gemm_qkv<<<768, 256, GEMM_SMEM>>>();
    attn_mma<<<dim3(16, 32), 256, ATTN_SMEM>>>();
    gemm_proj<<<dim3(8, 32), 256, G1_SMEM>>>(out);
}

// round 15
// speedup vs baseline: 2.4998x; 1.0953x over previous
#include <cuda_runtime.h>
#include <cuda_fp16.h>
#include <cstdint>

constexpr int BATCH = 2, NSEQ = 2048, DM = 1024, NH = 16, DH = 64;
constexpr int MROWS = BATCH * NSEQ;

__device__ __align__(16) __half g_x[MROWS*DM];
__device__ __align__(16) __half g_wqk_hi[2*DM*DM], g_wqk_lo[2*DM*DM];  // [2048][1024]: 0..1023 Wq, 1024..2047 Wk
__device__ __align__(16) __half g_wv[DM*DM];                            // [1024][1024] single
__device__ __align__(16) __half g_wp[DM*DM];                            // [1024][1024] single
__device__ __align__(16) __half g_q[MROWS*NH*DH];                       // [bh][n][d] (pre-scaled, single)
__device__ __align__(16) __half g_k[MROWS*NH*DH];                       // [bh][n][d]
__device__ __align__(16) __half g_v[MROWS*NH*DH];                       // [bh][d][n] (transposed)
__device__ __align__(16) __half g_att[MROWS*DM];                        // [4096][1024]

// ---------------- helpers ----------------
__device__ __forceinline__ void ldsm4(uint32_t a, uint32_t& r0, uint32_t& r1, uint32_t& r2, uint32_t& r3) {
    asm volatile("ldmatrix.sync.aligned.m8n8.x4.shared.b16 {%0,%1,%2,%3}, [%4];\n"
                 : "=r"(r0), "=r"(r1), "=r"(r2), "=r"(r3) : "r"(a));
}
__device__ __forceinline__ void mma16816(float* c, const uint32_t* a, uint32_t b0, uint32_t b1) {
    asm volatile("mma.sync.aligned.m16n8k16.row.col.f32.f16.f16.f32 "
                 "{%0,%1,%2,%3}, {%4,%5,%6,%7}, {%8,%9}, {%0,%1,%2,%3};\n"
                 : "+f"(c[0]), "+f"(c[1]), "+f"(c[2]), "+f"(c[3])
                 : "r"(a[0]), "r"(a[1]), "r"(a[2]), "r"(a[3]), "r"(b0), "r"(b1));
}
__device__ __forceinline__ uint32_t pack2h(float a, float b) {
    __half2 h2 = __halves2half2(__float2half_rn(a), __float2half_rn(b));
    return *(uint32_t*)&h2;
}
__device__ __forceinline__ void cp_async16(uint32_t dst, const void* src) {
    asm volatile("cp.async.cg.shared.global [%0], [%1], 16;\n" :: "r"(dst), "l"(src) : "memory");
}
__device__ __forceinline__ void cp_commit() { asm volatile("cp.async.commit_group;\n" ::: "memory"); }
template<int N> __device__ __forceinline__ void cp_wait() {
    asm volatile("cp.async.wait_group %0;\n" :: "n"(N) : "memory");
}

// =====================================================================
// Fused prep: blocks 0..3071 split w_qkv, 3072..4095 round w_proj,
// 4096..6143 round x (8 floats/thread, vectorized).
// =====================================================================
__global__ void prep_kernel(const float* __restrict__ x,
                            const float* __restrict__ wqkv,
                            const float* __restrict__ wp)
{
    __shared__ float t[32][33];
    const int bid = blockIdx.x;
    const int tx = threadIdx.x & 31, ty0 = threadIdx.x >> 5;

    if (bid < 3072) {
        const int n0 = (bid % 96) * 32, k0 = (bid / 96) * 32;
        for (int ty = ty0; ty < 32; ty += 8) t[ty][tx] = wqkv[(size_t)(k0+ty)*3072 + n0 + tx];
        __syncthreads();
        for (int ty = ty0; ty < 32; ty += 8) {
            const int n = n0 + ty, k = k0 + tx;
            const float v = t[tx][ty];
            const int which = n % 3, hd = n / 3;
            if (which == 2) {
                g_wv[(size_t)hd * 1024 + k] = __float2half_rn(v);
            } else {
                const int row = which * 1024 + hd;
                __half h = __float2half_rn(v);
                const size_t o = (size_t)row * 1024 + k;
                g_wqk_hi[o] = h;
                g_wqk_lo[o] = __float2half_rn(v - __half2float(h));
            }
        }
    } else if (bid < 4096) {
        const int b2 = bid - 3072;
        const int n0 = (b2 & 31) * 32, k0 = (b2 >> 5) * 32;
        for (int ty = ty0; ty < 32; ty += 8) t[ty][tx] = wp[(size_t)(k0+ty)*1024 + n0 + tx];
        __syncthreads();
        for (int ty = ty0; ty < 32; ty += 8)
            g_wp[(size_t)(n0+ty)*1024 + k0 + tx] = __float2half_rn(t[tx][ty]);
    } else {
        const size_t idx = ((size_t)(bid - 4096) * 256 + threadIdx.x) * 8;
        const float4 a = *(const float4*)(x + idx);
        const float4 b = *(const float4*)(x + idx + 4);
        uint32_t r[4];
        r[0] = pack2h(a.x, a.y); r[1] = pack2h(a.z, a.w);
        r[2] = pack2h(b.x, b.y); r[3] = pack2h(b.z, b.w);
        *(uint4*)(g_x + idx) = *(uint4*)r;
    }
}

// =====================================================================
// Fused QKV GEMM, 768 linear blocks:
//   bid 0..511  : qk = x @ (Wqk_hi+Wqk_lo)^T  (2-term, scatter q/k)
//   bid 512..767: v  = x @ Wv^T               (1-term, scatter v transposed)
// =====================================================================
constexpr uint32_t G_STAGE = 3u * 128u * 64u;    // 24576 bytes
constexpr int GEMM_SMEM = 3 * (int)G_STAGE;      // 73728

__global__ __launch_bounds__(256, 2) void gemm_qkv()
{
    extern __shared__ __align__(16) char dynsm[];
    const uint32_t sbase = (uint32_t)__cvta_generic_to_shared(dynsm);

    const int bid = blockIdx.x;
    const bool qkpart = (bid < 512);

    const int tid = threadIdx.x, w = tid >> 5, lane = tid & 31;
    const int gid = lane >> 2, tig = lane & 3;
    const int wm = (w & 1) * 64, wn = (w >> 1) * 32;
    const int a_r = lane & 15, a_k8 = lane >> 4;
    const int b_r = (lane & 7) + ((lane >> 4) & 1) * 8, b_k8 = (lane >> 3) & 1;

    if (qkpart) {
        const int m0 = (bid >> 4) * 128, n0 = (bid & 15) * 128;
        const __half* planes[3] = { g_x      + (size_t)m0 * 1024,
                                    g_wqk_hi + (size_t)n0 * 1024,
                                    g_wqk_lo + (size_t)n0 * 1024 };
        auto issue_stage = [&](int s) {
            const uint32_t sbuf = sbase + (uint32_t)(s % 3) * G_STAGE;
            #pragma unroll
            for (int i = 0; i < 6; i++) {
                const int u = tid + 256 * i;
                const int plane = u >> 9, rem = u & 511;
                const int row = rem >> 2, cell = rem & 3;
                const uint32_t csw = (uint32_t)(cell ^ ((row >> 1) & 3));
                cp_async16(sbuf + (uint32_t)plane * 8192u + (uint32_t)row * 64u + csw * 16u,
                           planes[plane] + (size_t)row * 1024 + s * 32 + cell * 8);
            }
            cp_commit();
        };

        issue_stage(0);
        issue_stage(1);

        float acc[4][4][4] = {};
        for (int s = 0; s < 32; s++) {
            cp_wait<1>();
            __syncthreads();
            if (s + 2 < 32) issue_stage(s + 2);
            else cp_commit();
            const uint32_t bo = sbase + (uint32_t)(s % 3) * G_STAGE;
            #pragma unroll
            for (int hk = 0; hk < 2; hk++) {
                uint32_t bf[2][2][4];
                #pragma unroll
                for (int g = 0; g < 2; g++) {
                    const int row = wn + g * 16 + b_r;
                    const uint32_t csw = (uint32_t)((hk * 2 + b_k8) ^ ((row >> 1) & 3));
                    const uint32_t ad = bo + 8192u + (uint32_t)row * 64u + csw * 16u;
                    ldsm4(ad,         bf[0][g][0], bf[0][g][1], bf[0][g][2], bf[0][g][3]);
                    ldsm4(ad + 8192u, bf[1][g][0], bf[1][g][1], bf[1][g][2], bf[1][g][3]);
                }
                uint32_t ah[2][4];
                auto lda = [&](int i, int b) {
                    const int row = wm + i * 16 + a_r;
                    const uint32_t csw = (uint32_t)((hk * 2 + a_k8) ^ ((row >> 1) & 3));
                    ldsm4(bo + (uint32_t)row * 64u + csw * 16u,
                          ah[b][0], ah[b][1], ah[b][2], ah[b][3]);
                };
                lda(0, 0);
                #pragma unroll
                for (int i = 0; i < 4; i++) {
                    if (i < 3) lda(i + 1, (i + 1) & 1);
                    const int cb = i & 1;
                    #pragma unroll
                    for (int jn = 0; jn < 4; jn++) {
                        const int g = jn >> 1, h2 = (jn & 1) * 2;
                        mma16816(acc[i][jn], ah[cb], bf[0][g][h2], bf[0][g][h2+1]);
                    }
                    #pragma unroll
                    for (int jn = 0; jn < 4; jn++) {
                        const int g = jn >> 1, h2 = (jn & 1) * 2;
                        mma16816(acc[i][jn], ah[cb], bf[1][g][h2], bf[1][g][h2+1]);
                    }
                }
            }
        }

        #pragma unroll
        for (int i = 0; i < 4; i++) {
            const int row0 = m0 + wm + i*16 + gid;
            #pragma unroll
            for (int jn = 0; jn < 4; jn++) {
                const int col = n0 + wn + jn*8 + tig*2;
                #pragma unroll
                for (int r = 0; r < 4; r++) {
                    const int rr = row0 + ((r >= 2) ? 8 : 0), cc = col + (r & 1);
                    float v = acc[i][jn][r];
                    const int bb = rr >> 11, nn = rr & 2047;
                    if (cc < 1024) {
                        const int h = cc >> 6, d = cc & 63;
                        g_q[((size_t)(bb*16 + h)*2048 + nn)*64 + d] = __float2half_rn(v * 0.125f);
                    } else {
                        const int c2 = cc - 1024, h = c2 >> 6, d = c2 & 63;
                        g_k[((size_t)(bb*16 + h)*2048 + nn)*64 + d] = __float2half_rn(v);
                    }
                }
            }
        }
    } else {
        const int b2 = bid - 512;
        const int m0 = (b2 >> 3) * 128, n0 = (b2 & 7) * 128;
        const __half* planes[2] = { g_x  + (size_t)m0 * 1024,
                                    g_wv + (size_t)n0 * 1024 };
        auto issue_stage = [&](int s) {
            const uint32_t sbuf = sbase + (uint32_t)(s % 3) * G_STAGE;
            #pragma unroll
            for (int i = 0; i < 4; i++) {
                const int u = tid + 256 * i;
                const int plane = u >> 9, rem = u & 511;
                const int row = rem >> 2, cell = rem & 3;
                const uint32_t csw = (uint32_t)(cell ^ ((row >> 1) & 3));
                cp_async16(sbuf + (uint32_t)plane * 8192u + (uint32_t)row * 64u + csw * 16u,
                           planes[plane] + (size_t)row * 1024 + s * 32 + cell * 8);
            }
            cp_commit();
        };

        issue_stage(0);
        issue_stage(1);

        float acc[4][4][4] = {};
        for (int s = 0; s < 32; s++) {
            cp_wait<1>();
            __syncthreads();
            if (s + 2 < 32) issue_stage(s + 2);
            else cp_commit();
            const uint32_t bo = sbase + (uint32_t)(s % 3) * G_STAGE;
            #pragma unroll
            for (int hk = 0; hk < 2; hk++) {
                uint32_t bf[2][4];
                #pragma unroll
                for (int g = 0; g < 2; g++) {
                    const int row = wn + g * 16 + b_r;
                    const uint32_t csw = (uint32_t)((hk * 2 + b_k8) ^ ((row >> 1) & 3));
                    ldsm4(bo + 8192u + (uint32_t)row * 64u + csw * 16u,
                          bf[g][0], bf[g][1], bf[g][2], bf[g][3]);
                }
                uint32_t ah[2][4];
                auto lda = [&](int i, int b) {
                    const int row = wm + i * 16 + a_r;
                    const uint32_t csw = (uint32_t)((hk * 2 + a_k8) ^ ((row >> 1) & 3));
                    ldsm4(bo + (uint32_t)row * 64u + csw * 16u,
                          ah[b][0], ah[b][1], ah[b][2], ah[b][3]);
                };
                lda(0, 0);
                #pragma unroll
                for (int i = 0; i < 4; i++) {
                    if (i < 3) lda(i + 1, (i + 1) & 1);
                    const int cb = i & 1;
                    #pragma unroll
                    for (int jn = 0; jn < 4; jn++) {
                        const int g = jn >> 1, h2 = (jn & 1) * 2;
                        mma16816(acc[i][jn], ah[cb], bf[g][h2], bf[g][h2+1]);
                    }
                }
            }
        }

        #pragma unroll
        for (int i = 0; i < 4; i++) {
            const int row0 = m0 + wm + i*16 + gid;
            #pragma unroll
            for (int jn = 0; jn < 4; jn++) {
                const int col = n0 + wn + jn*8 + tig*2;
                #pragma unroll
                for (int r = 0; r < 4; r++) {
                    const int rr = row0 + ((r >= 2) ? 8 : 0), cc = col + (r & 1);
                    const int bb = rr >> 11, nn = rr & 2047;
                    const int h = cc >> 6, d = cc & 63;
                    g_v[((size_t)(bb*16 + h)*64 + d)*2048 + nn] = __float2half_rn(acc[i][jn][r]);
                }
            }
        }
    }
}

// =====================================================================
// Proj GEMM: out = att @ Wp^T (1-term, fp32 out). 2-plane stages.
// =====================================================================
constexpr uint32_t G1_STAGE = 2u * 128u * 64u;   // 16384 bytes
constexpr int G1_SMEM = 3 * (int)G1_STAGE;       // 49152

__global__ __launch_bounds__(256, 2) void gemm_proj(float* __restrict__ Cout)
{
    extern __shared__ __align__(16) char dynsm[];
    const uint32_t sbase = (uint32_t)__cvta_generic_to_shared(dynsm);

    const int m0 = blockIdx.y * 128, n0 = blockIdx.x * 128;
    const int tid = threadIdx.x, w = tid >> 5, lane = tid & 31;
    const int gid = lane >> 2, tig = lane & 3;
    const int wm = (w & 1) * 64, wn = (w >> 1) * 32;

    const __half* planes[2] = { g_att + (size_t)m0 * 1024, g_wp + (size_t)n0 * 1024 };

    auto issue_stage = [&](int s) {
        const uint32_t sbuf = sbase + (uint32_t)(s % 3) * G1_STAGE;
        #pragma unroll
        for (int i = 0; i < 4; i++) {
            const int u = tid + 256 * i;
            const int plane = u >> 9, rem = u & 511;
            const int row = rem >> 2, cell = rem & 3;
            const uint32_t csw = (uint32_t)(cell ^ ((row >> 1) & 3));
            cp_async16(sbuf + (uint32_t)plane * 8192u + (uint32_t)row * 64u + csw * 16u,
                       planes[plane] + (size_t)row * 1024 + s * 32 + cell * 8);
        }
        cp_commit();
    };

    const int a_r = lane & 15, a_k8 = lane >> 4;
    const int b_r = (lane & 7) + ((lane >> 4) & 1) * 8, b_k8 = (lane >> 3) & 1;

    issue_stage(0);
    issue_stage(1);

    float acc[4][4][4] = {};

    for (int s = 0; s < 32; s++) {
        cp_wait<1>();
        __syncthreads();
        if (s + 2 < 32) issue_stage(s + 2);
        else cp_commit();

        const uint32_t bo = sbase + (uint32_t)(s % 3) * G1_STAGE;

        #pragma unroll
        for (int hk = 0; hk < 2; hk++) {
            uint32_t bf[2][4];
            #pragma unroll
            for (int g = 0; g < 2; g++) {
                const int row = wn + g * 16 + b_r;
                const uint32_t csw = (uint32_t)((hk * 2 + b_k8) ^ ((row >> 1) & 3));
                ldsm4(bo + 8192u + (uint32_t)row * 64u + csw * 16u,
                      bf[g][0], bf[g][1], bf[g][2], bf[g][3]);
            }
            uint32_t ah[2][4];
            auto lda = [&](int i, int b) {
                const int row = wm + i * 16 + a_r;
                const uint32_t csw = (uint32_t)((hk * 2 + a_k8) ^ ((row >> 1) & 3));
                ldsm4(bo + (uint32_t)row * 64u + csw * 16u,
                      ah[b][0], ah[b][1], ah[b][2], ah[b][3]);
            };
            lda(0, 0);
            #pragma unroll
            for (int i = 0; i < 4; i++) {
                if (i < 3) lda(i + 1, (i + 1) & 1);
                const int cb = i & 1;
                #pragma unroll
                for (int jn = 0; jn < 4; jn++) {
                    const int g = jn >> 1, h2 = (jn & 1) * 2;
                    mma16816(acc[i][jn], ah[cb], bf[g][h2], bf[g][h2+1]);
                }
            }
        }
    }

    #pragma unroll
    for (int i = 0; i < 4; i++) {
        const int row0 = m0 + wm + i*16 + gid;
        #pragma unroll
        for (int jn = 0; jn < 4; jn++) {
            const int col = n0 + wn + jn*8 + tig*2;
            *(float2*)&Cout[(size_t)row0*1024 + col]     = make_float2(acc[i][jn][0], acc[i][jn][1]);
            *(float2*)&Cout[(size_t)(row0+8)*1024 + col] = make_float2(acc[i][jn][2], acc[i][jn][3]);
        }
    }
}

// =====================================================================
// fp16 causal flash attention: single-fp16 Q,K,V,P.
// LINEAR 512-block grid, GLOBAL big-first order:
//   qt = 15 - (bid >> 5)  (all 32 heaviest blocks dispatch first)
//   bh = bid & 31
// =====================================================================
constexpr int ATTN_SMEM = 81920;

__global__ __launch_bounds__(256, 2) void attn_mma()
{
    extern __shared__ __align__(16) __half dsm[];

    const int bid = blockIdx.x;
    const int qt = 15 - (bid >> 5);          // big q-tiles first, globally
    const int bh = bid & 31;
    const int bb = bh >> 4, hh = bh & 15;
    const size_t base = (size_t)bh * (2048*64);
    const int tid = threadIdx.x, w = tid >> 5, lane = tid & 31;
    const int gid = lane >> 2, tig = lane & 3;
    const uint32_t sbase = (uint32_t)__cvta_generic_to_shared(dsm);
    const int a_r = lane & 15, a_k8 = lane >> 4;
    const int b_r = (lane & 7) + ((lane >> 4) & 1) * 8, b_k8 = (lane >> 3) & 1;

    auto issue_kv = [&](int st) {
        const uint32_t sbuf = sbase + 16384u + (uint32_t)(st & 1) * 32768u;
        #pragma unroll
        for (int i = 0; i < 8; i++) {
            const int u = tid + 256 * i;
            if ((u >> 10) == 0) {
                const int rem = u & 1023;
                const int row = rem >> 3, c16 = rem & 7;
                cp_async16(sbuf + (uint32_t)row * 128u + (uint32_t)((c16 ^ (row & 7)) * 16),
                           g_k + base + (size_t)(st * 128 + row) * 64 + c16 * 8);
            } else {
                const int rem = u & 1023;
                const int sub = rem >> 9, rem2 = rem & 511;
                const int row = rem2 >> 3, c16 = rem2 & 7;
                cp_async16(sbuf + 16384u + (uint32_t)sub * 8192u
                               + (uint32_t)row * 128u + (uint32_t)((c16 ^ (row & 7)) * 16),
                           g_v + base + (size_t)row * 2048 + (size_t)(st * 128 + sub * 64) + c16 * 8);
            }
        }
        cp_commit();
    };

    #pragma unroll
    for (int it = 0; it < 4; it++) {
        const int u = tid + 256*it, r = u >> 3, c16 = u & 7;
        const int so = r*64 + ((c16 ^ (r & 7))*8);
        *(uint4*)&dsm[so] = *(const uint4*)(g_q + base + (size_t)(qt*128 + r)*64 + c16*8);
    }

    float s[8][4], o[8][4] = {};
    float mr0 = -1e30f, mr1 = -1e30f, lr0 = 0.f, lr1 = 0.f;
    const int row0g = qt*128 + w*16 + gid, row1g = row0g + 8;
    const int nstages = qt + 1;

    issue_kv(0);

    for (int st = 0; st < nstages; st++) {
        cp_wait<0>();
        __syncthreads();
        if (st + 1 < nstages) issue_kv(st + 1);

        const int kbase_e = 8192 + (st & 1) * 16384;

        #pragma unroll
        for (int sub = 0; sub < 2; sub++) {
            const int kt = st * 2 + sub;
            const int koff = kbase_e + sub * 4096;
            const int voff = kbase_e + 8192 + sub * 4096;

            #pragma unroll
            for (int j = 0; j < 8; j++)
                #pragma unroll
                for (int r = 0; r < 4; r++) s[j][r] = 0.f;
            #pragma unroll
            for (int kk = 0; kk < 4; kk++) {
                uint32_t aq[4];
                {
                    const int r = w*16 + a_r, c16 = kk*2 + a_k8;
                    const int so = r*64 + ((c16 ^ (r & 7))*8);
                    ldsm4(sbase + (uint32_t)so*2, aq[0], aq[1], aq[2], aq[3]);
                }
                uint32_t bk[4][4];
                #pragma unroll
                for (int g = 0; g < 4; g++) {
                    const int r = g*16 + b_r, c16 = kk*2 + b_k8;
                    const int so = r*64 + ((c16 ^ (r & 7))*8);
                    ldsm4(sbase + (uint32_t)(koff + so)*2, bk[g][0], bk[g][1], bk[g][2], bk[g][3]);
                }
                #pragma unroll
                for (int j8 = 0; j8 < 8; j8++) {
                    const int g = j8 >> 1, h = (j8 & 1)*2;
                    mma16816(s[j8], aq, bk[g][h], bk[g][h+1]);
                }
            }

            if (kt >= 2*qt) {
                #pragma unroll
                for (int j8 = 0; j8 < 8; j8++) {
                    const int c = kt*64 + j8*8 + tig*2;
                    if (c > row0g)   s[j8][0] = -1e30f;
                    if (c+1 > row0g) s[j8][1] = -1e30f;
                    if (c > row1g)   s[j8][2] = -1e30f;
                    if (c+1 > row1g) s[j8][3] = -1e30f;
                }
            }

            float mx0 = -1e30f, mx1 = -1e30f;
            #pragma unroll
            for (int j8 = 0; j8 < 8; j8++) {
                mx0 = fmaxf(mx0, fmaxf(s[j8][0], s[j8][1]));
                mx1 = fmaxf(mx1, fmaxf(s[j8][2], s[j8][3]));
            }
            mx0 = fmaxf(mx0, __shfl_xor_sync(~0u, mx0, 1)); mx0 = fmaxf(mx0, __shfl_xor_sync(~0u, mx0, 2));
            mx1 = fmaxf(mx1, __shfl_xor_sync(~0u, mx1, 1)); mx1 = fmaxf(mx1, __shfl_xor_sync(~0u, mx1, 2));
            const float mn0 = fmaxf(mr0, mx0), mn1 = fmaxf(mr1, mx1);
            const float f0 = __expf(mr0 - mn0), f1 = __expf(mr1 - mn1);
            mr0 = mn0; mr1 = mn1;
            float s0 = 0.f, s1 = 0.f;
            #pragma unroll
            for (int j8 = 0; j8 < 8; j8++) {
                s[j8][0] = __expf(s[j8][0] - mn0); s[j8][1] = __expf(s[j8][1] - mn0);
                s[j8][2] = __expf(s[j8][2] - mn1); s[j8][3] = __expf(s[j8][3] - mn1);
                s0 += s[j8][0] + s[j8][1]; s1 += s[j8][2] + s[j8][3];
            }
            s0 += __shfl_xor_sync(~0u, s0, 1); s0 += __shfl_xor_sync(~0u, s0, 2);
            s1 += __shfl_xor_sync(~0u, s1, 1); s1 += __shfl_xor_sync(~0u, s1, 2);
            lr0 = lr0*f0 + s0; lr1 = lr1*f1 + s1;
            #pragma unroll
            for (int j8 = 0; j8 < 8; j8++) {
                o[j8][0] *= f0; o[j8][1] *= f0; o[j8][2] *= f1; o[j8][3] *= f1;
            }

            #pragma unroll
            for (int kk = 0; kk < 4; kk++) {
                uint32_t ap[4];
                ap[0] = pack2h(s[2*kk][0],   s[2*kk][1]);
                ap[1] = pack2h(s[2*kk][2],   s[2*kk][3]);
                ap[2] = pack2h(s[2*kk+1][0], s[2*kk+1][1]);
                ap[3] = pack2h(s[2*kk+1][2], s[2*kk+1][3]);
                uint32_t bv[4][4];
                #pragma unroll
                for (int g = 0; g < 4; g++) {
                    const int r = g*16 + b_r, c16 = kk*2 + b_k8;
                    const int so = r*64 + ((c16 ^ (r & 7))*8);
                    ldsm4(sbase + (uint32_t)(voff + so)*2, bv[g][0], bv[g][1], bv[g][2], bv[g][3]);
                }
                #pragma unroll
                for (int j8 = 0; j8 < 8; j8++) {
                    const int g = j8 >> 1, h = (j8 & 1)*2;
                    mma16816(o[j8], ap, bv[g][h], bv[g][h+1]);
                }
            }
        }
    }

    const float i0 = 1.f / lr0, i1 = 1.f / lr1;
    #pragma unroll
    for (int j8 = 0; j8 < 8; j8++) {
        const int col = hh*64 + j8*8 + tig*2;
        size_t ob = ((size_t)bb*2048 + row0g) * DM + col;
        *(uint32_t*)&g_att[ob] = pack2h(o[j8][0]*i0, o[j8][1]*i0);
        ob = ((size_t)bb*2048 + row1g) * DM + col;
        *(uint32_t*)&g_att[ob] = pack2h(o[j8][2]*i1, o[j8][3]*i1);
    }
}

extern "C" void kernel_launch(void* const* d_in, const int* in_sizes, int n_in,
                              void* d_out, int out_size)
{
    (void)in_sizes; (void)n_in; (void)out_size;
    const float* x      = (const float*)d_in[0];
    const float* w_qkv  = (const float*)d_in[1];
    const float* w_proj = (const float*)d_in[2];
    float* out = (float*)d_out;

    static bool attr_done = false;
    if (!attr_done) {
        cudaFuncSetAttribute(attn_mma,  cudaFuncAttributeMaxDynamicSharedMemorySize, ATTN_SMEM);
        cudaFuncSetAttribute(gemm_qkv,  cudaFuncAttributeMaxDynamicSharedMemorySize, GEMM_SMEM);
        cudaFuncSetAttribute(gemm_proj, cudaFuncAttributeMaxDynamicSharedMemorySize, G1_SMEM);
        attr_done = true;
    }

    prep_kernel<<<6144, 256>>>(x, w_qkv, w_proj);
    gemm_qkv<<<768, 256, GEMM_SMEM>>>();
    attn_mma<<<512, 256, ATTN_SMEM>>>();
    gemm_proj<<<dim3(8, 32), 256, G1_SMEM>>>(out);
}

// round 16
// speedup vs baseline: 2.8760x; 1.1505x over previous
#include <cuda_runtime.h>
#include <cuda_fp16.h>
#include <cstdint>

constexpr int BATCH = 2, NSEQ = 2048, DM = 1024, NH = 16, DH = 64;
constexpr int MROWS = BATCH * NSEQ;

__device__ __align__(16) __half g_x[MROWS*DM];
__device__ __align__(16) __half g_wqkv[3*DM*DM];   // [3072][1024]: 0..1023 Wq, 1024..2047 Wk, 2048..3071 Wv
__device__ __align__(16) __half g_wp[DM*DM];       // [1024][1024] single
__device__ __align__(16) __half g_q[MROWS*NH*DH];  // [bh][n][d] (pre-scaled, single)
__device__ __align__(16) __half g_k[MROWS*NH*DH];  // [bh][n][d]
__device__ __align__(16) __half g_v[MROWS*NH*DH];  // [bh][d][n] (transposed)
__device__ __align__(16) __half g_att[MROWS*DM];   // [4096][1024]

// ---------------- helpers ----------------
__device__ __forceinline__ void ldsm4(uint32_t a, uint32_t& r0, uint32_t& r1, uint32_t& r2, uint32_t& r3) {
    asm volatile("ldmatrix.sync.aligned.m8n8.x4.shared.b16 {%0,%1,%2,%3}, [%4];\n"
                 : "=r"(r0), "=r"(r1), "=r"(r2), "=r"(r3) : "r"(a));
}
__device__ __forceinline__ void mma16816(float* c, const uint32_t* a, uint32_t b0, uint32_t b1) {
    asm volatile("mma.sync.aligned.m16n8k16.row.col.f32.f16.f16.f32 "
                 "{%0,%1,%2,%3}, {%4,%5,%6,%7}, {%8,%9}, {%0,%1,%2,%3};\n"
                 : "+f"(c[0]), "+f"(c[1]), "+f"(c[2]), "+f"(c[3])
                 : "r"(a[0]), "r"(a[1]), "r"(a[2]), "r"(a[3]), "r"(b0), "r"(b1));
}
__device__ __forceinline__ uint32_t pack2h(float a, float b) {
    __half2 h2 = __halves2half2(__float2half_rn(a), __float2half_rn(b));
    return *(uint32_t*)&h2;
}
__device__ __forceinline__ void cp_async16(uint32_t dst, const void* src) {
    asm volatile("cp.async.cg.shared.global [%0], [%1], 16;\n" :: "r"(dst), "l"(src) : "memory");
}
__device__ __forceinline__ void cp_commit() { asm volatile("cp.async.commit_group;\n" ::: "memory"); }
template<int N> __device__ __forceinline__ void cp_wait() {
    asm volatile("cp.async.wait_group %0;\n" :: "n"(N) : "memory");
}

// =====================================================================
// Fused prep: blocks 0..3071 de-interleave+transpose w_qkv (single fp16),
// 3072..4095 transpose w_proj, 4096..6143 round x (8 floats/thread).
// =====================================================================
__global__ void prep_kernel(const float* __restrict__ x,
                            const float* __restrict__ wqkv,
                            const float* __restrict__ wp)
{
    __shared__ float t[32][33];
    const int bid = blockIdx.x;
    const int tx = threadIdx.x & 31, ty0 = threadIdx.x >> 5;

    if (bid < 3072) {
        const int n0 = (bid % 96) * 32, k0 = (bid / 96) * 32;
        for (int ty = ty0; ty < 32; ty += 8) t[ty][tx] = wqkv[(size_t)(k0+ty)*3072 + n0 + tx];
        __syncthreads();
        for (int ty = ty0; ty < 32; ty += 8) {
            const int n = n0 + ty, k = k0 + tx;
            const int which = n % 3, hd = n / 3;
            g_wqkv[(size_t)(which * 1024 + hd) * 1024 + k] = __float2half_rn(t[tx][ty]);
        }
    } else if (bid < 4096) {
        const int b2 = bid - 3072;
        const int n0 = (b2 & 31) * 32, k0 = (b2 >> 5) * 32;
        for (int ty = ty0; ty < 32; ty += 8) t[ty][tx] = wp[(size_t)(k0+ty)*1024 + n0 + tx];
        __syncthreads();
        for (int ty = ty0; ty < 32; ty += 8)
            g_wp[(size_t)(n0+ty)*1024 + k0 + tx] = __float2half_rn(t[tx][ty]);
    } else {
        const size_t idx = ((size_t)(bid - 4096) * 256 + threadIdx.x) * 8;
        const float4 a = *(const float4*)(x + idx);
        const float4 b = *(const float4*)(x + idx + 4);
        uint32_t r[4];
        r[0] = pack2h(a.x, a.y); r[1] = pack2h(a.z, a.w);
        r[2] = pack2h(b.x, b.y); r[3] = pack2h(b.z, b.w);
        *(uint4*)(g_x + idx) = *(uint4*)r;
    }
}

// =====================================================================
// QKV GEMM (1-term, uniform): qkv = x @ Wqkv^T, 768 blocks
// (m = bid/24, n = bid%24). 2-plane stages, BK=32, 3-stage ring.
// Epilogue scatters q (pre-scaled) / k / v (transposed).
// =====================================================================
constexpr uint32_t G1_STAGE = 2u * 128u * 64u;   // 16384 bytes
constexpr int G1_SMEM = 3 * (int)G1_STAGE;       // 49152

__global__ __launch_bounds__(256, 2) void gemm_qkv()
{
    extern __shared__ __align__(16) char dynsm[];
    const uint32_t sbase = (uint32_t)__cvta_generic_to_shared(dynsm);

    const int bid = blockIdx.x;
    const int m0 = (bid / 24) * 128, n0 = (bid % 24) * 128;
    const int tid = threadIdx.x, w = tid >> 5, lane = tid & 31;
    const int gid = lane >> 2, tig = lane & 3;
    const int wm = (w & 1) * 64, wn = (w >> 1) * 32;
    const int a_r = lane & 15, a_k8 = lane >> 4;
    const int b_r = (lane & 7) + ((lane >> 4) & 1) * 8, b_k8 = (lane >> 3) & 1;

    const __half* planes[2] = { g_x    + (size_t)m0 * 1024,
                                g_wqkv + (size_t)n0 * 1024 };

    auto issue_stage = [&](int s) {
        const uint32_t sbuf = sbase + (uint32_t)(s % 3) * G1_STAGE;
        #pragma unroll
        for (int i = 0; i < 4; i++) {
            const int u = tid + 256 * i;
            const int plane = u >> 9, rem = u & 511;
            const int row = rem >> 2, cell = rem & 3;
            const uint32_t csw = (uint32_t)(cell ^ ((row >> 1) & 3));
            cp_async16(sbuf + (uint32_t)plane * 8192u + (uint32_t)row * 64u + csw * 16u,
                       planes[plane] + (size_t)row * 1024 + s * 32 + cell * 8);
        }
        cp_commit();
    };

    issue_stage(0);
    issue_stage(1);

    float acc[4][4][4] = {};

    for (int s = 0; s < 32; s++) {
        cp_wait<1>();
        __syncthreads();
        if (s + 2 < 32) issue_stage(s + 2);
        else cp_commit();

        const uint32_t bo = sbase + (uint32_t)(s % 3) * G1_STAGE;

        #pragma unroll
        for (int hk = 0; hk < 2; hk++) {
            uint32_t bf[2][4];
            #pragma unroll
            for (int g = 0; g < 2; g++) {
                const int row = wn + g * 16 + b_r;
                const uint32_t csw = (uint32_t)((hk * 2 + b_k8) ^ ((row >> 1) & 3));
                ldsm4(bo + 8192u + (uint32_t)row * 64u + csw * 16u,
                      bf[g][0], bf[g][1], bf[g][2], bf[g][3]);
            }
            uint32_t ah[2][4];
            auto lda = [&](int i, int b) {
                const int row = wm + i * 16 + a_r;
                const uint32_t csw = (uint32_t)((hk * 2 + a_k8) ^ ((row >> 1) & 3));
                ldsm4(bo + (uint32_t)row * 64u + csw * 16u,
                      ah[b][0], ah[b][1], ah[b][2], ah[b][3]);
            };
            lda(0, 0);
            #pragma unroll
            for (int i = 0; i < 4; i++) {
                if (i < 3) lda(i + 1, (i + 1) & 1);
                const int cb = i & 1;
                #pragma unroll
                for (int jn = 0; jn < 4; jn++) {
                    const int g = jn >> 1, h2 = (jn & 1) * 2;
                    mma16816(acc[i][jn], ah[cb], bf[g][h2], bf[g][h2+1]);
                }
            }
        }
    }

    #pragma unroll
    for (int i = 0; i < 4; i++) {
        const int row0 = m0 + wm + i*16 + gid;
        #pragma unroll
        for (int jn = 0; jn < 4; jn++) {
            const int col = n0 + wn + jn*8 + tig*2;
            #pragma unroll
            for (int r = 0; r < 4; r++) {
                const int rr = row0 + ((r >= 2) ? 8 : 0), cc = col + (r & 1);
                float v = acc[i][jn][r];
                const int bb = rr >> 11, nn = rr & 2047;
                const int which = cc >> 10, c2 = cc & 1023;
                const int h = c2 >> 6, d = c2 & 63;
                if (which == 0) {
                    g_q[((size_t)(bb*16 + h)*2048 + nn)*64 + d] = __float2half_rn(v * 0.125f);
                } else if (which == 1) {
                    g_k[((size_t)(bb*16 + h)*2048 + nn)*64 + d] = __float2half_rn(v);
                } else {
                    g_v[((size_t)(bb*16 + h)*64 + d)*2048 + nn] = __float2half_rn(v);
                }
            }
        }
    }
}

// =====================================================================
// Proj GEMM: out = att @ Wp^T (1-term, fp32 out). 2-plane stages.
// =====================================================================
__global__ __launch_bounds__(256, 2) void gemm_proj(float* __restrict__ Cout)
{
    extern __shared__ __align__(16) char dynsm[];
    const uint32_t sbase = (uint32_t)__cvta_generic_to_shared(dynsm);

    const int m0 = blockIdx.y * 128, n0 = blockIdx.x * 128;
    const int tid = threadIdx.x, w = tid >> 5, lane = tid & 31;
    const int gid = lane >> 2, tig = lane & 3;
    const int wm = (w & 1) * 64, wn = (w >> 1) * 32;

    const __half* planes[2] = { g_att + (size_t)m0 * 1024, g_wp + (size_t)n0 * 1024 };

    auto issue_stage = [&](int s) {
        const uint32_t sbuf = sbase + (uint32_t)(s % 3) * G1_STAGE;
        #pragma unroll
        for (int i = 0; i < 4; i++) {
            const int u = tid + 256 * i;
            const int plane = u >> 9, rem = u & 511;
            const int row = rem >> 2, cell = rem & 3;
            const uint32_t csw = (uint32_t)(cell ^ ((row >> 1) & 3));
            cp_async16(sbuf + (uint32_t)plane * 8192u + (uint32_t)row * 64u + csw * 16u,
                       planes[plane] + (size_t)row * 1024 + s * 32 + cell * 8);
        }
        cp_commit();
    };

    const int a_r = lane & 15, a_k8 = lane >> 4;
    const int b_r = (lane & 7) + ((lane >> 4) & 1) * 8, b_k8 = (lane >> 3) & 1;

    issue_stage(0);
    issue_stage(1);

    float acc[4][4][4] = {};

    for (int s = 0; s < 32; s++) {
        cp_wait<1>();
        __syncthreads();
        if (s + 2 < 32) issue_stage(s + 2);
        else cp_commit();

        const uint32_t bo = sbase + (uint32_t)(s % 3) * G1_STAGE;

        #pragma unroll
        for (int hk = 0; hk < 2; hk++) {
            uint32_t bf[2][4];
            #pragma unroll
            for (int g = 0; g < 2; g++) {
                const int row = wn + g * 16 + b_r;
                const uint32_t csw = (uint32_t)((hk * 2 + b_k8) ^ ((row >> 1) & 3));
                ldsm4(bo + 8192u + (uint32_t)row * 64u + csw * 16u,
                      bf[g][0], bf[g][1], bf[g][2], bf[g][3]);
            }
            uint32_t ah[2][4];
            auto lda = [&](int i, int b) {
                const int row = wm + i * 16 + a_r;
                const uint32_t csw = (uint32_t)((hk * 2 + a_k8) ^ ((row >> 1) & 3));
                ldsm4(bo + (uint32_t)row * 64u + csw * 16u,
                      ah[b][0], ah[b][1], ah[b][2], ah[b][3]);
            };
            lda(0, 0);
            #pragma unroll
            for (int i = 0; i < 4; i++) {
                if (i < 3) lda(i + 1, (i + 1) & 1);
                const int cb = i & 1;
                #pragma unroll
                for (int jn = 0; jn < 4; jn++) {
                    const int g = jn >> 1, h2 = (jn & 1) * 2;
                    mma16816(acc[i][jn], ah[cb], bf[g][h2], bf[g][h2+1]);
                }
            }
        }
    }

    #pragma unroll
    for (int i = 0; i < 4; i++) {
        const int row0 = m0 + wm + i*16 + gid;
        #pragma unroll
        for (int jn = 0; jn < 4; jn++) {
            const int col = n0 + wn + jn*8 + tig*2;
            *(float2*)&Cout[(size_t)row0*1024 + col]     = make_float2(acc[i][jn][0], acc[i][jn][1]);
            *(float2*)&Cout[(size_t)(row0+8)*1024 + col] = make_float2(acc[i][jn][2], acc[i][jn][3]);
        }
    }
}

// =====================================================================
// fp16 causal flash attention: single-fp16 Q,K,V,P.
// Linear 512-block grid, global big-first: qt = 15-(bid>>5), bh = bid&31.
// =====================================================================
constexpr int ATTN_SMEM = 81920;

__global__ __launch_bounds__(256, 2) void attn_mma()
{
    extern __shared__ __align__(16) __half dsm[];

    const int bid = blockIdx.x;
    const int qt = 15 - (bid >> 5);
    const int bh = bid & 31;
    const int bb = bh >> 4, hh = bh & 15;
    const size_t base = (size_t)bh * (2048*64);
    const int tid = threadIdx.x, w = tid >> 5, lane = tid & 31;
    const int gid = lane >> 2, tig = lane & 3;
    const uint32_t sbase = (uint32_t)__cvta_generic_to_shared(dsm);
    const int a_r = lane & 15, a_k8 = lane >> 4;
    const int b_r = (lane & 7) + ((lane >> 4) & 1) * 8, b_k8 = (lane >> 3) & 1;

    auto issue_kv = [&](int st) {
        const uint32_t sbuf = sbase + 16384u + (uint32_t)(st & 1) * 32768u;
        #pragma unroll
        for (int i = 0; i < 8; i++) {
            const int u = tid + 256 * i;
            if ((u >> 10) == 0) {
                const int rem = u & 1023;
                const int row = rem >> 3, c16 = rem & 7;
                cp_async16(sbuf + (uint32_t)row * 128u + (uint32_t)((c16 ^ (row & 7)) * 16),
                           g_k + base + (size_t)(st * 128 + row) * 64 + c16 * 8);
            } else {
                const int rem = u & 1023;
                const int sub = rem >> 9, rem2 = rem & 511;
                const int row = rem2 >> 3, c16 = rem2 & 7;
                cp_async16(sbuf + 16384u + (uint32_t)sub * 8192u
                               + (uint32_t)row * 128u + (uint32_t)((c16 ^ (row & 7)) * 16),
                           g_v + base + (size_t)row * 2048 + (size_t)(st * 128 + sub * 64) + c16 * 8);
            }
        }
        cp_commit();
    };

    #pragma unroll
    for (int it = 0; it < 4; it++) {
        const int u = tid + 256*it, r = u >> 3, c16 = u & 7;
        const int so = r*64 + ((c16 ^ (r & 7))*8);
        *(uint4*)&dsm[so] = *(const uint4*)(g_q + base + (size_t)(qt*128 + r)*64 + c16*8);
    }

    float s[8][4], o[8][4] = {};
    float mr0 = -1e30f, mr1 = -1e30f, lr0 = 0.f, lr1 = 0.f;
    const int row0g = qt*128 + w*16 + gid, row1g = row0g + 8;
    const int nstages = qt + 1;

    issue_kv(0);

    for (int st = 0; st < nstages; st++) {
        cp_wait<0>();
        __syncthreads();
        if (st + 1 < nstages) issue_kv(st + 1);

        const int kbase_e = 8192 + (st & 1) * 16384;

        #pragma unroll
        for (int sub = 0; sub < 2; sub++) {
            const int kt = st * 2 + sub;
            const int koff = kbase_e + sub * 4096;
            const int voff = kbase_e + 8192 + sub * 4096;

            #pragma unroll
            for (int j = 0; j < 8; j++)
                #pragma unroll
                for (int r = 0; r < 4; r++) s[j][r] = 0.f;
            #pragma unroll
            for (int kk = 0; kk < 4; kk++) {
                uint32_t aq[4];
                {
                    const int r = w*16 + a_r, c16 = kk*2 + a_k8;
                    const int so = r*64 + ((c16 ^ (r & 7))*8);
                    ldsm4(sbase + (uint32_t)so*2, aq[0], aq[1], aq[2], aq[3]);
                }
                uint32_t bk[4][4];
                #pragma unroll
                for (int g = 0; g < 4; g++) {
                    const int r = g*16 + b_r, c16 = kk*2 + b_k8;
                    const int so = r*64 + ((c16 ^ (r & 7))*8);
                    ldsm4(sbase + (uint32_t)(koff + so)*2, bk[g][0], bk[g][1], bk[g][2], bk[g][3]);
                }
                #pragma unroll
                for (int j8 = 0; j8 < 8; j8++) {
                    const int g = j8 >> 1, h = (j8 & 1)*2;
                    mma16816(s[j8], aq, bk[g][h], bk[g][h+1]);
                }
            }

            if (kt >= 2*qt) {
                #pragma unroll
                for (int j8 = 0; j8 < 8; j8++) {
                    const int c = kt*64 + j8*8 + tig*2;
                    if (c > row0g)   s[j8][0] = -1e30f;
                    if (c+1 > row0g) s[j8][1] = -1e30f;
                    if (c > row1g)   s[j8][2] = -1e30f;
                    if (c+1 > row1g) s[j8][3] = -1e30f;
                }
            }

            float mx0 = -1e30f, mx1 = -1e30f;
            #pragma unroll
            for (int j8 = 0; j8 < 8; j8++) {
                mx0 = fmaxf(mx0, fmaxf(s[j8][0], s[j8][1]));
                mx1 = fmaxf(mx1, fmaxf(s[j8][2], s[j8][3]));
            }
            mx0 = fmaxf(mx0, __shfl_xor_sync(~0u, mx0, 1)); mx0 = fmaxf(mx0, __shfl_xor_sync(~0u, mx0, 2));
            mx1 = fmaxf(mx1, __shfl_xor_sync(~0u, mx1, 1)); mx1 = fmaxf(mx1, __shfl_xor_sync(~0u, mx1, 2));
            const float mn0 = fmaxf(mr0, mx0), mn1 = fmaxf(mr1, mx1);
            const float f0 = __expf(mr0 - mn0), f1 = __expf(mr1 - mn1);
            mr0 = mn0; mr1 = mn1;
            float s0 = 0.f, s1 = 0.f;
            #pragma unroll
            for (int j8 = 0; j8 < 8; j8++) {
                s[j8][0] = __expf(s[j8][0] - mn0); s[j8][1] = __expf(s[j8][1] - mn0);
                s[j8][2] = __expf(s[j8][2] - mn1); s[j8][3] = __expf(s[j8][3] - mn1);
                s0 += s[j8][0] + s[j8][1]; s1 += s[j8][2] + s[j8][3];
            }
            s0 += __shfl_xor_sync(~0u, s0, 1); s0 += __shfl_xor_sync(~0u, s0, 2);
            s1 += __shfl_xor_sync(~0u, s1, 1); s1 += __shfl_xor_sync(~0u, s1, 2);
            lr0 = lr0*f0 + s0; lr1 = lr1*f1 + s1;
            #pragma unroll
            for (int j8 = 0; j8 < 8; j8++) {
                o[j8][0] *= f0; o[j8][1] *= f0; o[j8][2] *= f1; o[j8][3] *= f1;
            }

            #pragma unroll
            for (int kk = 0; kk < 4; kk++) {
                uint32_t ap[4];
                ap[0] = pack2h(s[2*kk][0],   s[2*kk][1]);
                ap[1] = pack2h(s[2*kk][2],   s[2*kk][3]);
                ap[2] = pack2h(s[2*kk+1][0], s[2*kk+1][1]);
                ap[3] = pack2h(s[2*kk+1][2], s[2*kk+1][3]);
                uint32_t bv[4][4];
                #pragma unroll
                for (int g = 0; g < 4; g++) {
                    const int r = g*16 + b_r, c16 = kk*2 + b_k8;
                    const int so = r*64 + ((c16 ^ (r & 7))*8);
                    ldsm4(sbase + (uint32_t)(voff + so)*2, bv[g][0], bv[g][1], bv[g][2], bv[g][3]);
                }
                #pragma unroll
                for (int j8 = 0; j8 < 8; j8++) {
                    const int g = j8 >> 1, h = (j8 & 1)*2;
                    mma16816(o[j8], ap, bv[g][h], bv[g][h+1]);
                }
            }
        }
    }

    const float i0 = 1.f / lr0, i1 = 1.f / lr1;
    #pragma unroll
    for (int j8 = 0; j8 < 8; j8++) {
        const int col = hh*64 + j8*8 + tig*2;
        size_t ob = ((size_t)bb*2048 + row0g) * DM + col;
        *(uint32_t*)&g_att[ob] = pack2h(o[j8][0]*i0, o[j8][1]*i0);
        ob = ((size_t)bb*2048 + row1g) * DM + col;
        *(uint32_t*)&g_att[ob] = pack2h(o[j8][2]*i1, o[j8][3]*i1);
    }
}

extern "C" void kernel_launch(void* const* d_in, const int* in_sizes, int n_in,
                              void* d_out, int out_size)
{
    (void)in_sizes; (void)n_in; (void)out_size;
    const float* x      = (const float*)d_in[0];
    const float* w_qkv  = (const float*)d_in[1];
    const float* w_proj = (const float*)d_in[2];
    float* out = (float*)d_out;

    static bool attr_done = false;
    if (!attr_done) {
        cudaFuncSetAttribute(attn_mma,  cudaFuncAttributeMaxDynamicSharedMemorySize, ATTN_SMEM);
        cudaFuncSetAttribute(gemm_qkv,  cudaFuncAttributeMaxDynamicSharedMemorySize, G1_SMEM);
        cudaFuncSetAttribute(gemm_proj, cudaFuncAttributeMaxDynamicSharedMemorySize, G1_SMEM);
        attr_done = true;
    }

    prep_kernel<<<6144, 256>>>(x, w_qkv, w_proj);
    gemm_qkv<<<768, 256, G1_SMEM>>>();
    attn_mma<<<512, 256, ATTN_SMEM>>>();
    gemm_proj<<<dim3(8, 32), 256, G1_SMEM>>>(out);
}

// round 17
// speedup vs baseline: 3.0734x; 1.0686x over previous
#include <cuda_runtime.h>
#include <cuda_fp16.h>
#include <cstdint>

constexpr int BATCH = 2, NSEQ = 2048, DM = 1024, NH = 16, DH = 64;
constexpr int MROWS = BATCH * NSEQ;

__device__ __align__(16) __half g_x[MROWS*DM];
__device__ __align__(16) __half g_wqkv[3*DM*DM];   // [3072][1024]: 0..1023 Wq, 1024..2047 Wk, 2048..3071 Wv
__device__ __align__(16) __half g_wp[DM*DM];       // [1024][1024]
__device__ __align__(16) __half g_q[MROWS*NH*DH];  // [bh][n][d] (pre-scaled)
__device__ __align__(16) __half g_k[MROWS*NH*DH];  // [bh][n][d]
__device__ __align__(16) __half g_v[MROWS*NH*DH];  // [bh][d][n] (transposed)
__device__ __align__(16) __half g_att[MROWS*DM];   // [4096][1024]

// ---------------- helpers ----------------
__device__ __forceinline__ void ldsm4(uint32_t a, uint32_t& r0, uint32_t& r1, uint32_t& r2, uint32_t& r3) {
    asm volatile("ldmatrix.sync.aligned.m8n8.x4.shared.b16 {%0,%1,%2,%3}, [%4];\n"
                 : "=r"(r0), "=r"(r1), "=r"(r2), "=r"(r3) : "r"(a));
}
__device__ __forceinline__ void mma16816(float* c, const uint32_t* a, uint32_t b0, uint32_t b1) {
    asm volatile("mma.sync.aligned.m16n8k16.row.col.f32.f16.f16.f32 "
                 "{%0,%1,%2,%3}, {%4,%5,%6,%7}, {%8,%9}, {%0,%1,%2,%3};\n"
                 : "+f"(c[0]), "+f"(c[1]), "+f"(c[2]), "+f"(c[3])
                 : "r"(a[0]), "r"(a[1]), "r"(a[2]), "r"(a[3]), "r"(b0), "r"(b1));
}
__device__ __forceinline__ uint32_t pack2h(float a, float b) {
    __half2 h2 = __halves2half2(__float2half_rn(a), __float2half_rn(b));
    return *(uint32_t*)&h2;
}
__device__ __forceinline__ void cp_async16(uint32_t dst, const void* src) {
    asm volatile("cp.async.cg.shared.global [%0], [%1], 16;\n" :: "r"(dst), "l"(src) : "memory");
}
__device__ __forceinline__ void cp_commit() { asm volatile("cp.async.commit_group;\n" ::: "memory"); }
template<int N> __device__ __forceinline__ void cp_wait() {
    asm volatile("cp.async.wait_group %0;\n" :: "n"(N) : "memory");
}

// =====================================================================
// Fused prep (unchanged): w_qkv de-interleave+transpose, w_proj transpose,
// x rounding (vectorized).
// =====================================================================
__global__ void prep_kernel(const float* __restrict__ x,
                            const float* __restrict__ wqkv,
                            const float* __restrict__ wp)
{
    __shared__ float t[32][33];
    const int bid = blockIdx.x;
    const int tx = threadIdx.x & 31, ty0 = threadIdx.x >> 5;

    if (bid < 3072) {
        const int n0 = (bid % 96) * 32, k0 = (bid / 96) * 32;
        for (int ty = ty0; ty < 32; ty += 8) t[ty][tx] = wqkv[(size_t)(k0+ty)*3072 + n0 + tx];
        __syncthreads();
        for (int ty = ty0; ty < 32; ty += 8) {
            const int n = n0 + ty, k = k0 + tx;
            const int which = n % 3, hd = n / 3;
            g_wqkv[(size_t)(which * 1024 + hd) * 1024 + k] = __float2half_rn(t[tx][ty]);
        }
    } else if (bid < 4096) {
        const int b2 = bid - 3072;
        const int n0 = (b2 & 31) * 32, k0 = (b2 >> 5) * 32;
        for (int ty = ty0; ty < 32; ty += 8) t[ty][tx] = wp[(size_t)(k0+ty)*1024 + n0 + tx];
        __syncthreads();
        for (int ty = ty0; ty < 32; ty += 8)
            g_wp[(size_t)(n0+ty)*1024 + k0 + tx] = __float2half_rn(t[tx][ty]);
    } else {
        const size_t idx = ((size_t)(bid - 4096) * 256 + threadIdx.x) * 8;
        const float4 a = *(const float4*)(x + idx);
        const float4 b = *(const float4*)(x + idx + 4);
        uint32_t r[4];
        r[0] = pack2h(a.x, a.y); r[1] = pack2h(a.z, a.w);
        r[2] = pack2h(b.x, b.y); r[3] = pack2h(b.z, b.w);
        *(uint4*)(g_x + idx) = *(uint4*)r;
    }
}

// =====================================================================
// 1-term GEMM core, BK=64 stages (32KB: 2 planes x 128 rows x 128B),
// 3-stage ring (96KB), 16 barriers per block. Rows use c16^(row&7) swizzle.
// =====================================================================
constexpr uint32_t GB_STAGE = 2u * 128u * 128u;   // 32768 bytes
constexpr int GB_SMEM = 3 * (int)GB_STAGE;        // 98304

// QKV: 768 blocks (m = bid/24, n = bid%24); epilogue scatters q/k/v.
__global__ __launch_bounds__(256, 2) void gemm_qkv()
{
    extern __shared__ __align__(16) char dynsm[];
    const uint32_t sbase = (uint32_t)__cvta_generic_to_shared(dynsm);

    const int bid = blockIdx.x;
    const int m0 = (bid / 24) * 128, n0 = (bid % 24) * 128;
    const int tid = threadIdx.x, w = tid >> 5, lane = tid & 31;
    const int gid = lane >> 2, tig = lane & 3;
    const int wm = (w & 1) * 64, wn = (w >> 1) * 32;
    const int a_r = lane & 15, a_k8 = lane >> 4;
    const int b_r = (lane & 7) + ((lane >> 4) & 1) * 8, b_k8 = (lane >> 3) & 1;

    const __half* planes[2] = { g_x    + (size_t)m0 * 1024,
                                g_wqkv + (size_t)n0 * 1024 };

    // per stage: 2 planes x 128 rows x 8 cells(16B) = 2048 chunks, 8/thread
    auto issue_stage = [&](int s) {
        const uint32_t sbuf = sbase + (uint32_t)(s % 3) * GB_STAGE;
        #pragma unroll
        for (int i = 0; i < 8; i++) {
            const int u = tid + 256 * i;
            const int plane = u >> 10, rem = u & 1023;
            const int row = rem >> 3, c16 = rem & 7;
            cp_async16(sbuf + (uint32_t)plane * 16384u + (uint32_t)row * 128u
                           + (uint32_t)((c16 ^ (row & 7)) * 16),
                       planes[plane] + (size_t)row * 1024 + s * 64 + c16 * 8);
        }
        cp_commit();
    };

    issue_stage(0);
    issue_stage(1);

    float acc[4][4][4] = {};

    for (int s = 0; s < 16; s++) {
        cp_wait<1>();
        __syncthreads();
        if (s + 2 < 16) issue_stage(s + 2);
        else cp_commit();

        const uint32_t bo = sbase + (uint32_t)(s % 3) * GB_STAGE;

        #pragma unroll
        for (int hk = 0; hk < 4; hk++) {
            uint32_t bf[2][4];
            #pragma unroll
            for (int g = 0; g < 2; g++) {
                const int row = wn + g * 16 + b_r;
                const int c16 = hk * 2 + b_k8;
                ldsm4(bo + 16384u + (uint32_t)row * 128u + (uint32_t)((c16 ^ (row & 7)) * 16),
                      bf[g][0], bf[g][1], bf[g][2], bf[g][3]);
            }
            uint32_t ah[2][4];
            auto lda = [&](int i, int b) {
                const int row = wm + i * 16 + a_r;
                const int c16 = hk * 2 + a_k8;
                ldsm4(bo + (uint32_t)row * 128u + (uint32_t)((c16 ^ (row & 7)) * 16),
                      ah[b][0], ah[b][1], ah[b][2], ah[b][3]);
            };
            lda(0, 0);
            #pragma unroll
            for (int i = 0; i < 4; i++) {
                if (i < 3) lda(i + 1, (i + 1) & 1);
                const int cb = i & 1;
                #pragma unroll
                for (int jn = 0; jn < 4; jn++) {
                    const int g = jn >> 1, h2 = (jn & 1) * 2;
                    mma16816(acc[i][jn], ah[cb], bf[g][h2], bf[g][h2+1]);
                }
            }
        }
    }

    #pragma unroll
    for (int i = 0; i < 4; i++) {
        const int row0 = m0 + wm + i*16 + gid;
        #pragma unroll
        for (int jn = 0; jn < 4; jn++) {
            const int col = n0 + wn + jn*8 + tig*2;
            #pragma unroll
            for (int r = 0; r < 4; r++) {
                const int rr = row0 + ((r >= 2) ? 8 : 0), cc = col + (r & 1);
                float v = acc[i][jn][r];
                const int bb = rr >> 11, nn = rr & 2047;
                const int which = cc >> 10, c2 = cc & 1023;
                const int h = c2 >> 6, d = c2 & 63;
                if (which == 0) {
                    g_q[((size_t)(bb*16 + h)*2048 + nn)*64 + d] = __float2half_rn(v * 0.125f);
                } else if (which == 1) {
                    g_k[((size_t)(bb*16 + h)*2048 + nn)*64 + d] = __float2half_rn(v);
                } else {
                    g_v[((size_t)(bb*16 + h)*64 + d)*2048 + nn] = __float2half_rn(v);
                }
            }
        }
    }
}

// Proj: out = att @ Wp^T (fp32 out), same BK=64 core.
__global__ __launch_bounds__(256, 2) void gemm_proj(float* __restrict__ Cout)
{
    extern __shared__ __align__(16) char dynsm[];
    const uint32_t sbase = (uint32_t)__cvta_generic_to_shared(dynsm);

    const int m0 = blockIdx.y * 128, n0 = blockIdx.x * 128;
    const int tid = threadIdx.x, w = tid >> 5, lane = tid & 31;
    const int gid = lane >> 2, tig = lane & 3;
    const int wm = (w & 1) * 64, wn = (w >> 1) * 32;
    const int a_r = lane & 15, a_k8 = lane >> 4;
    const int b_r = (lane & 7) + ((lane >> 4) & 1) * 8, b_k8 = (lane >> 3) & 1;

    const __half* planes[2] = { g_att + (size_t)m0 * 1024, g_wp + (size_t)n0 * 1024 };

    auto issue_stage = [&](int s) {
        const uint32_t sbuf = sbase + (uint32_t)(s % 3) * GB_STAGE;
        #pragma unroll
        for (int i = 0; i < 8; i++) {
            const int u = tid + 256 * i;
            const int plane = u >> 10, rem = u & 1023;
            const int row = rem >> 3, c16 = rem & 7;
            cp_async16(sbuf + (uint32_t)plane * 16384u + (uint32_t)row * 128u
                           + (uint32_t)((c16 ^ (row & 7)) * 16),
                       planes[plane] + (size_t)row * 1024 + s * 64 + c16 * 8);
        }
        cp_commit();
    };

    issue_stage(0);
    issue_stage(1);

    float acc[4][4][4] = {};

    for (int s = 0; s < 16; s++) {
        cp_wait<1>();
        __syncthreads();
        if (s + 2 < 16) issue_stage(s + 2);
        else cp_commit();

        const uint32_t bo = sbase + (uint32_t)(s % 3) * GB_STAGE;

        #pragma unroll
        for (int hk = 0; hk < 4; hk++) {
            uint32_t bf[2][4];
            #pragma unroll
            for (int g = 0; g < 2; g++) {
                const int row = wn + g * 16 + b_r;
                const int c16 = hk * 2 + b_k8;
                ldsm4(bo + 16384u + (uint32_t)row * 128u + (uint32_t)((c16 ^ (row & 7)) * 16),
                      bf[g][0], bf[g][1], bf[g][2], bf[g][3]);
            }
            uint32_t ah[2][4];
            auto lda = [&](int i, int b) {
                const int row = wm + i * 16 + a_r;
                const int c16 = hk * 2 + a_k8;
                ldsm4(bo + (uint32_t)row * 128u + (uint32_t)((c16 ^ (row & 7)) * 16),
                      ah[b][0], ah[b][1], ah[b][2], ah[b][3]);
            };
            lda(0, 0);
            #pragma unroll
            for (int i = 0; i < 4; i++) {
                if (i < 3) lda(i + 1, (i + 1) & 1);
                const int cb = i & 1;
                #pragma unroll
                for (int jn = 0; jn < 4; jn++) {
                    const int g = jn >> 1, h2 = (jn & 1) * 2;
                    mma16816(acc[i][jn], ah[cb], bf[g][h2], bf[g][h2+1]);
                }
            }
        }
    }

    #pragma unroll
    for (int i = 0; i < 4; i++) {
        const int row0 = m0 + wm + i*16 + gid;
        #pragma unroll
        for (int jn = 0; jn < 4; jn++) {
            const int col = n0 + wn + jn*8 + tig*2;
            *(float2*)&Cout[(size_t)row0*1024 + col]     = make_float2(acc[i][jn][0], acc[i][jn][1]);
            *(float2*)&Cout[(size_t)(row0+8)*1024 + col] = make_float2(acc[i][jn][2], acc[i][jn][3]);
        }
    }
}

// =====================================================================
// fp16 causal flash attention (unchanged): single-fp16 Q,K,V,P.
// Linear 512-block grid, global big-first: qt = 15-(bid>>5), bh = bid&31.
// =====================================================================
constexpr int ATTN_SMEM = 81920;

__global__ __launch_bounds__(256, 2) void attn_mma()
{
    extern __shared__ __align__(16) __half dsm[];

    const int bid = blockIdx.x;
    const int qt = 15 - (bid >> 5);
    const int bh = bid & 31;
    const int bb = bh >> 4, hh = bh & 15;
    const size_t base = (size_t)bh * (2048*64);
    const int tid = threadIdx.x, w = tid >> 5, lane = tid & 31;
    const int gid = lane >> 2, tig = lane & 3;
    const uint32_t sbase = (uint32_t)__cvta_generic_to_shared(dsm);
    const int a_r = lane & 15, a_k8 = lane >> 4;
    const int b_r = (lane & 7) + ((lane >> 4) & 1) * 8, b_k8 = (lane >> 3) & 1;

    auto issue_kv = [&](int st) {
        const uint32_t sbuf = sbase + 16384u + (uint32_t)(st & 1) * 32768u;
        #pragma unroll
        for (int i = 0; i < 8; i++) {
            const int u = tid + 256 * i;
            if ((u >> 10) == 0) {
                const int rem = u & 1023;
                const int row = rem >> 3, c16 = rem & 7;
                cp_async16(sbuf + (uint32_t)row * 128u + (uint32_t)((c16 ^ (row & 7)) * 16),
                           g_k + base + (size_t)(st * 128 + row) * 64 + c16 * 8);
            } else {
                const int rem = u & 1023;
                const int sub = rem >> 9, rem2 = rem & 511;
                const int row = rem2 >> 3, c16 = rem2 & 7;
                cp_async16(sbuf + 16384u + (uint32_t)sub * 8192u
                               + (uint32_t)row * 128u + (uint32_t)((c16 ^ (row & 7)) * 16),
                           g_v + base + (size_t)row * 2048 + (size_t)(st * 128 + sub * 64) + c16 * 8);
            }
        }
        cp_commit();
    };

    #pragma unroll
    for (int it = 0; it < 4; it++) {
        const int u = tid + 256*it, r = u >> 3, c16 = u & 7;
        const int so = r*64 + ((c16 ^ (r & 7))*8);
        *(uint4*)&dsm[so] = *(const uint4*)(g_q + base + (size_t)(qt*128 + r)*64 + c16*8);
    }

    float s[8][4], o[8][4] = {};
    float mr0 = -1e30f, mr1 = -1e30f, lr0 = 0.f, lr1 = 0.f;
    const int row0g = qt*128 + w*16 + gid, row1g = row0g + 8;
    const int nstages = qt + 1;

    issue_kv(0);

    for (int st = 0; st < nstages; st++) {
        cp_wait<0>();
        __syncthreads();
        if (st + 1 < nstages) issue_kv(st + 1);

        const int kbase_e = 8192 + (st & 1) * 16384;

        #pragma unroll
        for (int sub = 0; sub < 2; sub++) {
            const int kt = st * 2 + sub;
            const int koff = kbase_e + sub * 4096;
            const int voff = kbase_e + 8192 + sub * 4096;

            #pragma unroll
            for (int j = 0; j < 8; j++)
                #pragma unroll
                for (int r = 0; r < 4; r++) s[j][r] = 0.f;
            #pragma unroll
            for (int kk = 0; kk < 4; kk++) {
                uint32_t aq[4];
                {
                    const int r = w*16 + a_r, c16 = kk*2 + a_k8;
                    const int so = r*64 + ((c16 ^ (r & 7))*8);
                    ldsm4(sbase + (uint32_t)so*2, aq[0], aq[1], aq[2], aq[3]);
                }
                uint32_t bk[4][4];
                #pragma unroll
                for (int g = 0; g < 4; g++) {
                    const int r = g*16 + b_r, c16 = kk*2 + b_k8;
                    const int so = r*64 + ((c16 ^ (r & 7))*8);
                    ldsm4(sbase + (uint32_t)(koff + so)*2, bk[g][0], bk[g][1], bk[g][2], bk[g][3]);
                }
                #pragma unroll
                for (int j8 = 0; j8 < 8; j8++) {
                    const int g = j8 >> 1, h = (j8 & 1)*2;
                    mma16816(s[j8], aq, bk[g][h], bk[g][h+1]);
                }
            }

            if (kt >= 2*qt) {
                #pragma unroll
                for (int j8 = 0; j8 < 8; j8++) {
                    const int c = kt*64 + j8*8 + tig*2;
                    if (c > row0g)   s[j8][0] = -1e30f;
                    if (c+1 > row0g) s[j8][1] = -1e30f;
                    if (c > row1g)   s[j8][2] = -1e30f;
                    if (c+1 > row1g) s[j8][3] = -1e30f;
                }
            }

            float mx0 = -1e30f, mx1 = -1e30f;
            #pragma unroll
            for (int j8 = 0; j8 < 8; j8++) {
                mx0 = fmaxf(mx0, fmaxf(s[j8][0], s[j8][1]));
                mx1 = fmaxf(mx1, fmaxf(s[j8][2], s[j8][3]));
            }
            mx0 = fmaxf(mx0, __shfl_xor_sync(~0u, mx0, 1)); mx0 = fmaxf(mx0, __shfl_xor_sync(~0u, mx0, 2));
            mx1 = fmaxf(mx1, __shfl_xor_sync(~0u, mx1, 1)); mx1 = fmaxf(mx1, __shfl_xor_sync(~0u, mx1, 2));
            const float mn0 = fmaxf(mr0, mx0), mn1 = fmaxf(mr1, mx1);
            const float f0 = __expf(mr0 - mn0), f1 = __expf(mr1 - mn1);
            mr0 = mn0; mr1 = mn1;
            float s0 = 0.f, s1 = 0.f;
            #pragma unroll
            for (int j8 = 0; j8 < 8; j8++) {
                s[j8][0] = __expf(s[j8][0] - mn0); s[j8][1] = __expf(s[j8][1] - mn0);
                s[j8][2] = __expf(s[j8][2] - mn1); s[j8][3] = __expf(s[j8][3] - mn1);
                s0 += s[j8][0] + s[j8][1]; s1 += s[j8][2] + s[j8][3];
            }
            s0 += __shfl_xor_sync(~0u, s0, 1); s0 += __shfl_xor_sync(~0u, s0, 2);
            s1 += __shfl_xor_sync(~0u, s1, 1); s1 += __shfl_xor_sync(~0u, s1, 2);
            lr0 = lr0*f0 + s0; lr1 = lr1*f1 + s1;
            #pragma unroll
            for (int j8 = 0; j8 < 8; j8++) {
                o[j8][0] *= f0; o[j8][1] *= f0; o[j8][2] *= f1; o[j8][3] *= f1;
            }

            #pragma unroll
            for (int kk = 0; kk < 4; kk++) {
                uint32_t ap[4];
                ap[0] = pack2h(s[2*kk][0],   s[2*kk][1]);
                ap[1] = pack2h(s[2*kk][2],   s[2*kk][3]);
                ap[2] = pack2h(s[2*kk+1][0], s[2*kk+1][1]);
                ap[3] = pack2h(s[2*kk+1][2], s[2*kk+1][3]);
                uint32_t bv[4][4];
                #pragma unroll
                for (int g = 0; g < 4; g++) {
                    const int r = g*16 + b_r, c16 = kk*2 + b_k8;
                    const int so = r*64 + ((c16 ^ (r & 7))*8);
                    ldsm4(sbase + (uint32_t)(voff + so)*2, bv[g][0], bv[g][1], bv[g][2], bv[g][3]);
                }
                #pragma unroll
                for (int j8 = 0; j8 < 8; j8++) {
                    const int g = j8 >> 1, h = (j8 & 1)*2;
                    mma16816(o[j8], ap, bv[g][h], bv[g][h+1]);
                }
            }
        }
    }

    const float i0 = 1.f / lr0, i1 = 1.f / lr1;
    #pragma unroll
    for (int j8 = 0; j8 < 8; j8++) {
        const int col = hh*64 + j8*8 + tig*2;
        size_t ob = ((size_t)bb*2048 + row0g) * DM + col;
        *(uint32_t*)&g_att[ob] = pack2h(o[j8][0]*i0, o[j8][1]*i0);
        ob = ((size_t)bb*2048 + row1g) * DM + col;
        *(uint32_t*)&g_att[ob] = pack2h(o[j8][2]*i1, o[j8][3]*i1);
    }
}

extern "C" void kernel_launch(void* const* d_in, const int* in_sizes, int n_in,
                              void* d_out, int out_size)
{
    (void)in_sizes; (void)n_in; (void)out_size;
    const float* x      = (const float*)d_in[0];
    const float* w_qkv  = (const float*)d_in[1];
    const float* w_proj = (const float*)d_in[2];
    float* out = (float*)d_out;

    static bool attr_done = false;
    if (!attr_done) {
        cudaFuncSetAttribute(attn_mma,  cudaFuncAttributeMaxDynamicSharedMemorySize, ATTN_SMEM);
        cudaFuncSetAttribute(gemm_qkv,  cudaFuncAttributeMaxDynamicSharedMemorySize, GB_SMEM);
        cudaFuncSetAttribute(gemm_proj, cudaFuncAttributeMaxDynamicSharedMemorySize, GB_SMEM);
        attr_done = true;
    }

    prep_kernel<<<6144, 256>>>(x, w_qkv, w_proj);
    gemm_qkv<<<768, 256, GB_SMEM>>>();
    attn_mma<<<512, 256, ATTN_SMEM>>>();
    gemm_proj<<<dim3(8, 32), 256, GB_SMEM>>>(out);
}